// round 1
// baseline (speedup 1.0000x reference)
#include <cuda_runtime.h>
#include <math.h>

#define Bn   4096
#define Dd   112
#define NTd  200
#define Hh   512
#define Kmix 10
#define HIDd 512
#define CN   536      /* 3*D + NT */
#define G3   1536     /* 3*H */
#define TOTR (Dd*Bn)  /* 458752 */

// ---------------- device scratch (static globals; no runtime alloc) ----------
__device__ float g_const[(size_t)Bn * CN];        //  8.8 MB
__device__ float g_gic  [(size_t)Bn * G3];        // 25.2 MB
__device__ float g_mlpc [(size_t)Bn * HIDd];      //  8.4 MB
__device__ float g_gh   [(size_t)Bn * G3];        // 25.2 MB
__device__ float g_H    [(size_t)(Dd+1) * Bn * Hh]; // 948 MB (h0 + 112 states)
__device__ float g_A1   [(size_t)TOTR * HIDd];    // 940 MB
__device__ float g_A2   [(size_t)TOTR * HIDd];    // 940 MB
__device__ float g_ll   [(size_t)Bn * Dd];        //  1.8 MB

// ---------------- small helpers ---------------------------------------------
__global__ void build_const_kernel(const float* __restrict__ c,
                                   const float* __restrict__ bb,
                                   const float* __restrict__ m)
{
    size_t idx = (size_t)blockIdx.x * blockDim.x + threadIdx.x;
    if (idx >= (size_t)Bn * CN) return;
    int b = (int)(idx / CN);
    int i = (int)(idx % CN);
    float v;
    if (i < Dd + NTd)            v = c [(size_t)b * (Dd + NTd) + i];
    else if (i < Dd + NTd + Dd)  v = bb[(size_t)b * Dd + (i - (Dd + NTd))];
    else                         v = m [(size_t)b * Dd + (i - (Dd + NTd + Dd))];
    g_const[idx] = v;
}

__global__ void zero_h0_kernel()
{
    size_t idx = (size_t)blockIdx.x * blockDim.x + threadIdx.x;
    if (idx < (size_t)Bn * Hh) g_H[idx] = 0.f;
}

// ---------------- fp32 SGEMM: C = act(A@B + bias), row-major ----------------
// MODE 0: C = A@B + bias[col]
// MODE 1: C = tanh(A@B + bias[col])
// MODE 2: C = tanh(A@B + bias[(row & 4095)*512 + col])   (mlp_const row-bcast)
template<int MODE>
__global__ __launch_bounds__(256)
void sgemm_kernel(const float* __restrict__ A, const float* __restrict__ B,
                  const float* __restrict__ bias, float* __restrict__ C,
                  int M, int N, int K, int ldb)
{
    const int BM = 128, BN = 64, BK = 16;
    __shared__ float As[BK][BM];
    __shared__ float Bs[BK][BN];

    int tx = threadIdx.x, ty = threadIdx.y;
    int tid  = ty * 16 + tx;
    int row0 = blockIdx.y * BM;
    int col0 = blockIdx.x * BN;

    float acc[8][4];
#pragma unroll
    for (int i = 0; i < 8; i++)
#pragma unroll
        for (int j = 0; j < 4; j++) acc[i][j] = 0.f;

    int k0 = 0;
    for (; k0 + BK <= K; k0 += BK) {
#pragma unroll
        for (int i = 0; i < 2; i++) {
            int f4 = tid + i * 256;
            int ar = f4 >> 2;
            int ak = (f4 & 3) * 4;
            float4 v = *(const float4*)(A + (size_t)(row0 + ar) * K + k0 + ak);
            As[ak + 0][ar] = v.x; As[ak + 1][ar] = v.y;
            As[ak + 2][ar] = v.z; As[ak + 3][ar] = v.w;
        }
        {
            int br = tid >> 4;
            int bc = (tid & 15) * 4;
            float4 v = *(const float4*)(B + (size_t)(k0 + br) * ldb + col0 + bc);
            *(float4*)&Bs[br][bc] = v;
        }
        __syncthreads();
#pragma unroll
        for (int kk = 0; kk < BK; kk++) {
            float a[8], bv[4];
#pragma unroll
            for (int i = 0; i < 8; i++) a[i] = As[kk][ty * 8 + i];
#pragma unroll
            for (int j = 0; j < 4; j++) bv[j] = Bs[kk][tx * 4 + j];
#pragma unroll
            for (int i = 0; i < 8; i++)
#pragma unroll
                for (int j = 0; j < 4; j++) acc[i][j] = fmaf(a[i], bv[j], acc[i][j]);
        }
        __syncthreads();
    }
    if (k0 < K) {                     // K tail (K=536 case): zero-pad, full compute
        int rem = K - k0;
#pragma unroll
        for (int i = 0; i < 2; i++) {
            int f4 = tid + i * 256;
            int ar = f4 >> 2;
            int ak = (f4 & 3) * 4;
            float4 v = make_float4(0.f, 0.f, 0.f, 0.f);
            const float* ap = A + (size_t)(row0 + ar) * K + k0;
            if (ak + 3 < rem) v = *(const float4*)(ap + ak);
            else {
                if (ak + 0 < rem) v.x = ap[ak + 0];
                if (ak + 1 < rem) v.y = ap[ak + 1];
                if (ak + 2 < rem) v.z = ap[ak + 2];
                if (ak + 3 < rem) v.w = ap[ak + 3];
            }
            As[ak + 0][ar] = v.x; As[ak + 1][ar] = v.y;
            As[ak + 2][ar] = v.z; As[ak + 3][ar] = v.w;
        }
        {
            int br = tid >> 4;
            int bc = (tid & 15) * 4;
            float4 v = make_float4(0.f, 0.f, 0.f, 0.f);
            if (br < rem) v = *(const float4*)(B + (size_t)(k0 + br) * ldb + col0 + bc);
            *(float4*)&Bs[br][bc] = v;
        }
        __syncthreads();
#pragma unroll
        for (int kk = 0; kk < BK; kk++) {
            float a[8], bv[4];
#pragma unroll
            for (int i = 0; i < 8; i++) a[i] = As[kk][ty * 8 + i];
#pragma unroll
            for (int j = 0; j < 4; j++) bv[j] = Bs[kk][tx * 4 + j];
#pragma unroll
            for (int i = 0; i < 8; i++)
#pragma unroll
                for (int j = 0; j < 4; j++) acc[i][j] = fmaf(a[i], bv[j], acc[i][j]);
        }
        __syncthreads();
    }

#pragma unroll
    for (int i = 0; i < 8; i++) {
        int row = row0 + ty * 8 + i;
#pragma unroll
        for (int j = 0; j < 4; j++) {
            int col = col0 + tx * 4 + j;
            float v = acc[i][j];
            if (MODE == 0)      v = v + bias[col];
            else if (MODE == 1) v = tanhf(v + bias[col]);
            else                v = tanhf(v + bias[(size_t)(row & (Bn - 1)) * HIDd + col]);
            C[(size_t)row * N + col] = v;
        }
    }
}

// ---------------- GRU elementwise step --------------------------------------
__global__ __launch_bounds__(256)
void gru_step_kernel(const float* __restrict__ z, const float* __restrict__ Wih, int t)
{
    size_t idx = (size_t)blockIdx.x * blockDim.x + threadIdx.x; // < Bn*Hh
    int b = (int)(idx >> 9);
    int j = (int)(idx & 511);

    float zt = (t == 0) ? -1.0f : z[(size_t)b * Dd + (t - 1)];

    size_t gb = (size_t)b * G3;
    float ir  = fmaf(zt, Wih[j],        g_gic[gb + j]);
    float iz  = fmaf(zt, Wih[j + 512],  g_gic[gb + j + 512]);
    float inn = fmaf(zt, Wih[j + 1024], g_gic[gb + j + 1024]);
    float hr  = g_gh[gb + j];
    float hz  = g_gh[gb + j + 512];
    float hn  = g_gh[gb + j + 1024];

    float r = 1.f / (1.f + expf(-(ir + hr)));
    float u = 1.f / (1.f + expf(-(iz + hz)));
    float n = tanhf(inn + r * hn);

    float h = g_H[(size_t)t * Bn * Hh + idx];
    g_H[(size_t)(t + 1) * Bn * Hh + idx] = (1.f - u) * n + u * h;
}

// ---------------- head GEMM (N=30) fused with mixture log-likelihood --------
__global__ __launch_bounds__(128)
void head_kernel(const float* __restrict__ W2, const float* __restrict__ b2,
                 const float* __restrict__ z)
{
    __shared__ float a2s[4][512];
    __shared__ float ps[4][32];
    int w = threadIdx.x >> 5, lane = threadIdx.x & 31;
    size_t r = (size_t)blockIdx.x * 4 + w;   // r = t*4096 + b

    const float4* src = (const float4*)(g_A2 + r * HIDd);
#pragma unroll
    for (int i = 0; i < 4; i++) {
        float4 v = src[lane + 32 * i];
        *(float4*)&a2s[w][(lane + 32 * i) * 4] = v;
    }
    __syncwarp();

    if (lane < 30) {
        float acc = b2[lane];
#pragma unroll 8
        for (int k = 0; k < 512; k++)
            acc = fmaf(a2s[w][k], W2[k * 30 + lane], acc);
        ps[w][lane] = acc;
    }
    __syncwarp();

    if (lane == 0) {
        int t = (int)(r >> 12);
        int b = (int)(r & 4095);
        float zv = z[(size_t)b * Dd + t];
        float* p = ps[w];
        float m1 = -1e30f, m2 = -1e30f;
        float term[10];
#pragma unroll
        for (int k = 0; k < 10; k++) {
            float l = p[k], mu = p[10 + k], ls = p[20 + k];
            float d = (zv - mu) * expf(-ls);
            float tv = l - ls - 0.91893853320467274f - 0.5f * d * d;
            term[k] = tv;
            m1 = fmaxf(m1, tv);
            m2 = fmaxf(m2, l);
        }
        float s1 = 0.f, s2 = 0.f;
#pragma unroll
        for (int k = 0; k < 10; k++) {
            s1 += expf(term[k] - m1);
            s2 += expf(p[k] - m2);
        }
        g_ll[(size_t)b * Dd + t] = (m1 + logf(s1)) - (m2 + logf(s2));
    }
}

// ---------------- final: sort query desc (bitonic) + masked dot -------------
__global__ __launch_bounds__(128)
void final_kernel(const float* __restrict__ bb, const float* __restrict__ m,
                  float* __restrict__ out)
{
    __shared__ float s[128];
    __shared__ float red[128];
    int b = blockIdx.x, t = threadIdx.x;

    float q = -1.0f;                                   // pad < any real query (>=0)
    if (t < Dd) {
        float bv = bb[(size_t)b * Dd + t];
        q = m[(size_t)b * Dd + t] * (1.0f - bv);
    }
    s[t] = q;
    __syncthreads();

    // ascending bitonic sort of 128 elems
    for (int k = 2; k <= 128; k <<= 1) {
        for (int j = k >> 1; j > 0; j >>= 1) {
            int ixj = t ^ j;
            if (ixj > t) {
                float a = s[t], c = s[ixj];
                bool up = ((t & k) == 0);
                if (up ? (a > c) : (a < c)) { s[t] = c; s[ixj] = a; }
            }
            __syncthreads();
        }
    }

    float prod = 0.f;
    if (t < Dd) prod = g_ll[(size_t)b * Dd + t] * s[127 - t]; // mask[t] = t-th largest
    red[t] = prod;
    __syncthreads();
    for (int st = 64; st > 0; st >>= 1) {
        if (t < st) red[t] += red[t + st];
        __syncthreads();
    }
    if (t == 0) out[b] = red[0];
}

// ---------------- launch ----------------------------------------------------
extern "C" void kernel_launch(void* const* d_in, const int* in_sizes, int n_in,
                              void* d_out, int out_size)
{
    const float* z   = (const float*)d_in[0];
    const float* c   = (const float*)d_in[1];
    const float* bb  = (const float*)d_in[2];
    const float* m   = (const float*)d_in[3];
    const float* Wih = (const float*)d_in[4];
    const float* Whh = (const float*)d_in[5];
    const float* bih = (const float*)d_in[6];
    const float* bhh = (const float*)d_in[7];
    const float* W0  = (const float*)d_in[8];
    const float* b0  = (const float*)d_in[9];
    const float* W1  = (const float*)d_in[10];
    const float* b1  = (const float*)d_in[11];
    const float* W2  = (const float*)d_in[12];
    const float* b2  = (const float*)d_in[13];
    float* out = (float*)d_out;

    float *pConst, *pGic, *pMlpc, *pGh, *pH, *pA1, *pA2;
    cudaGetSymbolAddress((void**)&pConst, g_const);
    cudaGetSymbolAddress((void**)&pGic,   g_gic);
    cudaGetSymbolAddress((void**)&pMlpc,  g_mlpc);
    cudaGetSymbolAddress((void**)&pGh,    g_gh);
    cudaGetSymbolAddress((void**)&pH,     g_H);
    cudaGetSymbolAddress((void**)&pA1,    g_A1);
    cudaGetSymbolAddress((void**)&pA2,    g_A2);

    dim3 thr(16, 16);

    build_const_kernel<<<(Bn * CN) / 256, 256>>>(c, bb, m);
    zero_h0_kernel<<<(Bn * Hh) / 256, 256>>>();

    // gi_const = const @ Wih[1:] + bih          (4096 x 1536, K=536)
    sgemm_kernel<0><<<dim3(G3 / 64, Bn / 128), thr>>>(pConst, Wih + G3, bih, pGic,
                                                      Bn, G3, CN, G3);
    // mlp_const = const @ W0[H:] + b0           (4096 x 512, K=536)
    sgemm_kernel<0><<<dim3(HIDd / 64, Bn / 128), thr>>>(pConst, W0 + (size_t)Hh * HIDd,
                                                        b0, pMlpc, Bn, HIDd, CN, HIDd);
    // recurrence
    for (int t = 0; t < Dd; t++) {
        sgemm_kernel<0><<<dim3(G3 / 64, Bn / 128), thr>>>(pH + (size_t)t * Bn * Hh, Whh,
                                                          bhh, pGh, Bn, G3, Hh, G3);
        gru_step_kernel<<<(Bn * Hh) / 256, 256>>>(z, Wih, t);
    }
    // batched MLP over all (t,b) rows
    sgemm_kernel<2><<<dim3(HIDd / 64, TOTR / 128), thr>>>(pH + (size_t)Bn * Hh, W0,
                                                          pMlpc, pA1, TOTR, HIDd, Hh, HIDd);
    sgemm_kernel<1><<<dim3(HIDd / 64, TOTR / 128), thr>>>(pA1, W1, b1, pA2,
                                                          TOTR, HIDd, HIDd, HIDd);
    head_kernel<<<TOTR / 4, 128>>>(W2, b2, z);
    final_kernel<<<Bn, 128>>>(bb, m, out);
}

// round 2
// speedup vs baseline: 2.3771x; 2.3771x over previous
#include <cuda_runtime.h>
#include <math.h>
#include <stdint.h>

#define Bn   4096
#define Dd   112
#define NTd  200
#define Hh   512
#define Kmix 10
#define HIDd 512
#define CN   536      /* 3*D + NT */
#define G3   1536     /* 3*H */
#define TOTR (Dd*Bn)  /* 458752 */

// ---------------- device scratch (static globals; no runtime alloc) ----------
__device__ float g_const[(size_t)Bn * CN];
__device__ float g_gic  [(size_t)Bn * G3];
__device__ float g_mlpc [(size_t)Bn * HIDd];
__device__ float g_gh   [(size_t)Bn * G3];
__device__ float g_H    [(size_t)(Dd+1) * Bn * Hh];
__device__ float g_A1   [(size_t)TOTR * HIDd];
__device__ float g_A2   [(size_t)TOTR * HIDd];
__device__ float g_ll   [(size_t)Bn * Dd];

// ---------------- helpers ----------------------------------------------------
__global__ void build_const_kernel(const float* __restrict__ c,
                                   const float* __restrict__ bb,
                                   const float* __restrict__ m)
{
    size_t idx = (size_t)blockIdx.x * blockDim.x + threadIdx.x;
    if (idx >= (size_t)Bn * CN) return;
    int b = (int)(idx / CN);
    int i = (int)(idx % CN);
    float v;
    if (i < Dd + NTd)            v = c [(size_t)b * (Dd + NTd) + i];
    else if (i < Dd + NTd + Dd)  v = bb[(size_t)b * Dd + (i - (Dd + NTd))];
    else                         v = m [(size_t)b * Dd + (i - (Dd + NTd + Dd))];
    g_const[idx] = v;
}

__global__ void zero_h0_kernel()
{
    size_t idx = (size_t)blockIdx.x * blockDim.x + threadIdx.x;
    if (idx < (size_t)Bn * Hh) g_H[idx] = 0.f;
}

__device__ __forceinline__ uint32_t f2tf32(float x)
{
    uint32_t u;
    asm("cvt.rna.tf32.f32 %0, %1;" : "=r"(u) : "f"(x));
    return u;
}

__device__ __forceinline__ void mma_tf32(float* d, const uint32_t* a, const uint32_t* b)
{
    asm volatile(
        "mma.sync.aligned.m16n8k8.row.col.f32.tf32.tf32.f32 "
        "{%0,%1,%2,%3}, {%4,%5,%6,%7}, {%8,%9}, {%0,%1,%2,%3};\n"
        : "+f"(d[0]), "+f"(d[1]), "+f"(d[2]), "+f"(d[3])
        : "r"(a[0]), "r"(a[1]), "r"(a[2]), "r"(a[3]),
          "r"(b[0]), "r"(b[1]));
}

// ---------------- TF32 tensor-core GEMM: C = act(A@B + bias) ----------------
// A row-major [M,K], B row-major [K,N] (ldb = N), C row-major [M,N].
// MODE 0: C = A@B + bias[col]
// MODE 1: C = tanh(A@B + bias[col])
// MODE 2: C = tanh(A@B + bias[(row & 4095)*512 + col])
// Requires: M % 128 == 0, N % 128 == 0, K % 8 == 0.
template<int MODE>
__global__ __launch_bounds__(256)
void tgemm_kernel(const float* __restrict__ A, const float* __restrict__ B,
                  const float* __restrict__ bias, float* __restrict__ C,
                  int M, int N, int K)
{
    __shared__ uint32_t As[128][12];   // [row][k], pad 12 -> conflict-free frag loads
    __shared__ uint32_t Bs[8][136];    // [k][col], pad 136 -> conflict-free frag loads

    const int tid  = threadIdx.x;
    const int wid  = tid >> 5;
    const int lane = tid & 31;
    const int gid  = lane >> 2;        // 0..7
    const int tig  = lane & 3;         // 0..3
    const int wm   = wid >> 2;         // 0..1  (64-row slice)
    const int wn   = wid & 3;          // 0..3  (32-col slice)

    const int row0 = blockIdx.y * 128;
    const int col0 = blockIdx.x * 128;

    float acc[4][4][4];
#pragma unroll
    for (int mt = 0; mt < 4; mt++)
#pragma unroll
        for (int nt = 0; nt < 4; nt++)
#pragma unroll
            for (int r = 0; r < 4; r++) acc[mt][nt][r] = 0.f;

    // global-load assignments
    const int ar = tid >> 1;           // 0..127
    const int ak = (tid & 1) * 4;      // 0 or 4
    const int bk = tid >> 5;           // 0..7
    const int bn = (tid & 31) * 4;     // 0..124

    const int niter = K >> 3;

    const float* Ag = A + (size_t)(row0 + ar) * K + ak;
    const float* Bg = B + (size_t)bk * N + col0 + bn;

    float4 pa = *(const float4*)Ag;
    float4 pb = *(const float4*)Bg;

    for (int it = 0; it < niter; ++it) {
        // store prefetched tile (convert to tf32)
        As[ar][ak + 0] = f2tf32(pa.x);
        As[ar][ak + 1] = f2tf32(pa.y);
        As[ar][ak + 2] = f2tf32(pa.z);
        As[ar][ak + 3] = f2tf32(pa.w);
        Bs[bk][bn + 0] = f2tf32(pb.x);
        Bs[bk][bn + 1] = f2tf32(pb.y);
        Bs[bk][bn + 2] = f2tf32(pb.z);
        Bs[bk][bn + 3] = f2tf32(pb.w);
        __syncthreads();

        if (it + 1 < niter) {
            pa = *(const float4*)(Ag + (size_t)(it + 1) * 8);
            pb = *(const float4*)(Bg + (size_t)(it + 1) * 8 * N);
        }

        // fragments
        uint32_t af[4][4];
#pragma unroll
        for (int mt = 0; mt < 4; mt++) {
            int rbase = wm * 64 + mt * 16 + gid;
            af[mt][0] = As[rbase    ][tig    ];
            af[mt][1] = As[rbase + 8][tig    ];
            af[mt][2] = As[rbase    ][tig + 4];
            af[mt][3] = As[rbase + 8][tig + 4];
        }
        uint32_t bf[4][2];
#pragma unroll
        for (int nt = 0; nt < 4; nt++) {
            int cb = wn * 32 + nt * 8 + gid;
            bf[nt][0] = Bs[tig    ][cb];
            bf[nt][1] = Bs[tig + 4][cb];
        }
#pragma unroll
        for (int mt = 0; mt < 4; mt++)
#pragma unroll
            for (int nt = 0; nt < 4; nt++)
                mma_tf32(acc[mt][nt], af[mt], bf[nt]);

        __syncthreads();
    }

    // epilogue
#pragma unroll
    for (int mt = 0; mt < 4; mt++) {
        int row_lo = row0 + wm * 64 + mt * 16 + gid;
        int row_hi = row_lo + 8;
#pragma unroll
        for (int nt = 0; nt < 4; nt++) {
            int col = col0 + wn * 32 + nt * 8 + tig * 2;
            float v0 = acc[mt][nt][0], v1 = acc[mt][nt][1];
            float v2 = acc[mt][nt][2], v3 = acc[mt][nt][3];
            if (MODE == 0) {
                float b0 = bias[col], b1 = bias[col + 1];
                v0 += b0; v1 += b1; v2 += b0; v3 += b1;
            } else if (MODE == 1) {
                float b0 = bias[col], b1 = bias[col + 1];
                v0 = tanhf(v0 + b0); v1 = tanhf(v1 + b1);
                v2 = tanhf(v2 + b0); v3 = tanhf(v3 + b1);
            } else {
                const float* blo = bias + (size_t)(row_lo & (Bn - 1)) * HIDd + col;
                const float* bhi = bias + (size_t)(row_hi & (Bn - 1)) * HIDd + col;
                v0 = tanhf(v0 + blo[0]); v1 = tanhf(v1 + blo[1]);
                v2 = tanhf(v2 + bhi[0]); v3 = tanhf(v3 + bhi[1]);
            }
            *(float2*)(C + (size_t)row_lo * N + col) = make_float2(v0, v1);
            *(float2*)(C + (size_t)row_hi * N + col) = make_float2(v2, v3);
        }
    }
}

// ---------------- GRU elementwise step --------------------------------------
__global__ __launch_bounds__(256)
void gru_step_kernel(const float* __restrict__ z, const float* __restrict__ Wih, int t)
{
    size_t idx = (size_t)blockIdx.x * blockDim.x + threadIdx.x; // < Bn*Hh
    int b = (int)(idx >> 9);
    int j = (int)(idx & 511);

    float zt = (t == 0) ? -1.0f : z[(size_t)b * Dd + (t - 1)];

    size_t gb = (size_t)b * G3;
    float ir  = fmaf(zt, Wih[j],        g_gic[gb + j]);
    float iz  = fmaf(zt, Wih[j + 512],  g_gic[gb + j + 512]);
    float inn = fmaf(zt, Wih[j + 1024], g_gic[gb + j + 1024]);
    float hr  = g_gh[gb + j];
    float hz  = g_gh[gb + j + 512];
    float hn  = g_gh[gb + j + 1024];

    float r = 1.f / (1.f + expf(-(ir + hr)));
    float u = 1.f / (1.f + expf(-(iz + hz)));
    float n = tanhf(inn + r * hn);

    float h = g_H[(size_t)t * Bn * Hh + idx];
    g_H[(size_t)(t + 1) * Bn * Hh + idx] = (1.f - u) * n + u * h;
}

// ---------------- head GEMM (N=30) fused with mixture log-likelihood --------
__global__ __launch_bounds__(128)
void head_kernel(const float* __restrict__ W2, const float* __restrict__ b2,
                 const float* __restrict__ z)
{
    __shared__ float a2s[4][512];
    __shared__ float ps[4][32];
    int w = threadIdx.x >> 5, lane = threadIdx.x & 31;
    size_t r = (size_t)blockIdx.x * 4 + w;   // r = t*4096 + b

    const float4* src = (const float4*)(g_A2 + r * HIDd);
#pragma unroll
    for (int i = 0; i < 4; i++) {
        float4 v = src[lane + 32 * i];
        *(float4*)&a2s[w][(lane + 32 * i) * 4] = v;
    }
    __syncwarp();

    if (lane < 30) {
        float acc = b2[lane];
#pragma unroll 8
        for (int k = 0; k < 512; k++)
            acc = fmaf(a2s[w][k], W2[k * 30 + lane], acc);
        ps[w][lane] = acc;
    }
    __syncwarp();

    if (lane == 0) {
        int t = (int)(r >> 12);
        int b = (int)(r & 4095);
        float zv = z[(size_t)b * Dd + t];
        float* p = ps[w];
        float m1 = -1e30f, m2 = -1e30f;
        float term[10];
#pragma unroll
        for (int k = 0; k < 10; k++) {
            float l = p[k], mu = p[10 + k], ls = p[20 + k];
            float d = (zv - mu) * expf(-ls);
            float tv = l - ls - 0.91893853320467274f - 0.5f * d * d;
            term[k] = tv;
            m1 = fmaxf(m1, tv);
            m2 = fmaxf(m2, l);
        }
        float s1 = 0.f, s2 = 0.f;
#pragma unroll
        for (int k = 0; k < 10; k++) {
            s1 += expf(term[k] - m1);
            s2 += expf(p[k] - m2);
        }
        g_ll[(size_t)b * Dd + t] = (m1 + logf(s1)) - (m2 + logf(s2));
    }
}

// ---------------- final: sort query desc (bitonic) + masked dot -------------
__global__ __launch_bounds__(128)
void final_kernel(const float* __restrict__ bb, const float* __restrict__ m,
                  float* __restrict__ out)
{
    __shared__ float s[128];
    __shared__ float red[128];
    int b = blockIdx.x, t = threadIdx.x;

    float q = -1.0f;
    if (t < Dd) {
        float bv = bb[(size_t)b * Dd + t];
        q = m[(size_t)b * Dd + t] * (1.0f - bv);
    }
    s[t] = q;
    __syncthreads();

    for (int k = 2; k <= 128; k <<= 1) {
        for (int j = k >> 1; j > 0; j >>= 1) {
            int ixj = t ^ j;
            if (ixj > t) {
                float a = s[t], c = s[ixj];
                bool up = ((t & k) == 0);
                if (up ? (a > c) : (a < c)) { s[t] = c; s[ixj] = a; }
            }
            __syncthreads();
        }
    }

    float prod = 0.f;
    if (t < Dd) prod = g_ll[(size_t)b * Dd + t] * s[127 - t];
    red[t] = prod;
    __syncthreads();
    for (int st = 64; st > 0; st >>= 1) {
        if (t < st) red[t] += red[t + st];
        __syncthreads();
    }
    if (t == 0) out[b] = red[0];
}

// ---------------- launch ----------------------------------------------------
extern "C" void kernel_launch(void* const* d_in, const int* in_sizes, int n_in,
                              void* d_out, int out_size)
{
    const float* z   = (const float*)d_in[0];
    const float* c   = (const float*)d_in[1];
    const float* bb  = (const float*)d_in[2];
    const float* m   = (const float*)d_in[3];
    const float* Wih = (const float*)d_in[4];
    const float* Whh = (const float*)d_in[5];
    const float* bih = (const float*)d_in[6];
    const float* bhh = (const float*)d_in[7];
    const float* W0  = (const float*)d_in[8];
    const float* b0  = (const float*)d_in[9];
    const float* W1  = (const float*)d_in[10];
    const float* b1  = (const float*)d_in[11];
    const float* W2  = (const float*)d_in[12];
    const float* b2  = (const float*)d_in[13];
    float* out = (float*)d_out;

    float *pConst, *pGic, *pMlpc, *pGh, *pH, *pA1, *pA2;
    cudaGetSymbolAddress((void**)&pConst, g_const);
    cudaGetSymbolAddress((void**)&pGic,   g_gic);
    cudaGetSymbolAddress((void**)&pMlpc,  g_mlpc);
    cudaGetSymbolAddress((void**)&pGh,    g_gh);
    cudaGetSymbolAddress((void**)&pH,     g_H);
    cudaGetSymbolAddress((void**)&pA1,    g_A1);
    cudaGetSymbolAddress((void**)&pA2,    g_A2);

    build_const_kernel<<<(Bn * CN + 255) / 256, 256>>>(c, bb, m);
    zero_h0_kernel<<<(Bn * Hh) / 256, 256>>>();

    // gi_const = const @ Wih[1:] + bih          (4096 x 1536, K=536)
    tgemm_kernel<0><<<dim3(G3 / 128, Bn / 128), 256>>>(pConst, Wih + G3, bih, pGic,
                                                       Bn, G3, CN);
    // mlp_const = const @ W0[H:] + b0           (4096 x 512, K=536)
    tgemm_kernel<0><<<dim3(HIDd / 128, Bn / 128), 256>>>(pConst, W0 + (size_t)Hh * HIDd,
                                                         b0, pMlpc, Bn, HIDd, CN);
    // recurrence
    for (int t = 0; t < Dd; t++) {
        tgemm_kernel<0><<<dim3(G3 / 128, Bn / 128), 256>>>(pH + (size_t)t * Bn * Hh, Whh,
                                                           bhh, pGh, Bn, G3, Hh);
        gru_step_kernel<<<(Bn * Hh) / 256, 256>>>(z, Wih, t);
    }
    // batched MLP over all (t,b) rows
    tgemm_kernel<2><<<dim3(HIDd / 128, TOTR / 128), 256>>>(pH + (size_t)Bn * Hh, W0,
                                                           pMlpc, pA1, TOTR, HIDd, Hh);
    tgemm_kernel<1><<<dim3(HIDd / 128, TOTR / 128), 256>>>(pA1, W1, b1, pA2,
                                                           TOTR, HIDd, HIDd);
    head_kernel<<<TOTR / 4, 128>>>(W2, b2, z);
    final_kernel<<<Bn, 128>>>(bb, m, out);
}

// round 3
// speedup vs baseline: 2.4236x; 1.0196x over previous
#include <cuda_runtime.h>
#include <math.h>
#include <stdint.h>

#define Bn   4096
#define Dd   112
#define NTd  200
#define Hh   512
#define Kmix 10
#define HIDd 512
#define CN   536      /* 3*D + NT */
#define G3   1536     /* 3*H */
#define TOTR (Dd*Bn)  /* 458752 */

// ---------------- device scratch ---------------------------------------------
__device__ float g_const[(size_t)Bn * CN];
__device__ float g_gic  [(size_t)Bn * G3];
__device__ float g_mlpc [(size_t)Bn * HIDd];
__device__ float g_H    [(size_t)(Dd+1) * Bn * Hh];
__device__ float g_A1   [(size_t)TOTR * HIDd];
__device__ float g_A2   [(size_t)TOTR * HIDd];
__device__ float g_ll   [(size_t)Bn * Dd];

// ---------------- helpers ----------------------------------------------------
__device__ __forceinline__ float fast_sig(float x)
{
    return 1.f / (1.f + __expf(-x));
}
__device__ __forceinline__ float fast_tanh(float x)
{
    return fmaf(2.f, 1.f / (1.f + __expf(-2.f * x)), -1.f);
}

__global__ void build_const_kernel(const float* __restrict__ c,
                                   const float* __restrict__ bb,
                                   const float* __restrict__ m)
{
    size_t idx = (size_t)blockIdx.x * blockDim.x + threadIdx.x;
    if (idx >= (size_t)Bn * CN) return;
    int b = (int)(idx / CN);
    int i = (int)(idx % CN);
    float v;
    if (i < Dd + NTd)            v = c [(size_t)b * (Dd + NTd) + i];
    else if (i < Dd + NTd + Dd)  v = bb[(size_t)b * Dd + (i - (Dd + NTd))];
    else                         v = m [(size_t)b * Dd + (i - (Dd + NTd + Dd))];
    g_const[idx] = v;
}

__global__ void zero_h0_kernel()
{
    size_t idx = (size_t)blockIdx.x * blockDim.x + threadIdx.x;
    if (idx < (size_t)Bn * Hh) g_H[idx] = 0.f;
}

__device__ __forceinline__ uint32_t f2tf32(float x)
{
    uint32_t u;
    asm("cvt.rna.tf32.f32 %0, %1;" : "=r"(u) : "f"(x));
    return u;
}

__device__ __forceinline__ void mma_tf32(float* d, const uint32_t* a, const uint32_t* b)
{
    asm volatile(
        "mma.sync.aligned.m16n8k8.row.col.f32.tf32.tf32.f32 "
        "{%0,%1,%2,%3}, {%4,%5,%6,%7}, {%8,%9}, {%0,%1,%2,%3};\n"
        : "+f"(d[0]), "+f"(d[1]), "+f"(d[2]), "+f"(d[3])
        : "r"(a[0]), "r"(a[1]), "r"(a[2]), "r"(a[3]),
          "r"(b[0]), "r"(b[1]));
}

__device__ __forceinline__ void cpa16(void* smem, const void* gmem)
{
    uint32_t s = (uint32_t)__cvta_generic_to_shared(smem);
    asm volatile("cp.async.cg.shared.global [%0], [%1], 16;\n" :: "r"(s), "l"(gmem));
}
__device__ __forceinline__ void cpa_commit()
{
    asm volatile("cp.async.commit_group;\n");
}
template<int N>
__device__ __forceinline__ void cpa_wait()
{
    asm volatile("cp.async.wait_group %0;\n" :: "n"(N));
}

// ============ legacy BK=8 TF32 GEMM (used only for K=536 precompute) =========
template<int MODE>
__global__ __launch_bounds__(256)
void tgemm_kernel(const float* __restrict__ A, const float* __restrict__ B,
                  const float* __restrict__ bias, float* __restrict__ C,
                  int M, int N, int K)
{
    __shared__ uint32_t As[128][12];
    __shared__ uint32_t Bs[8][136];

    const int tid  = threadIdx.x;
    const int wid  = tid >> 5;
    const int lane = tid & 31;
    const int gid  = lane >> 2;
    const int tig  = lane & 3;
    const int wm   = wid >> 2;
    const int wn   = wid & 3;

    const int row0 = blockIdx.y * 128;
    const int col0 = blockIdx.x * 128;

    float acc[4][4][4];
#pragma unroll
    for (int mt = 0; mt < 4; mt++)
#pragma unroll
        for (int nt = 0; nt < 4; nt++)
#pragma unroll
            for (int r = 0; r < 4; r++) acc[mt][nt][r] = 0.f;

    const int ar = tid >> 1;
    const int ak = (tid & 1) * 4;
    const int bk = tid >> 5;
    const int bn = (tid & 31) * 4;

    const int niter = K >> 3;

    const float* Ag = A + (size_t)(row0 + ar) * K + ak;
    const float* Bg = B + (size_t)bk * N + col0 + bn;

    float4 pa = *(const float4*)Ag;
    float4 pb = *(const float4*)Bg;

    for (int it = 0; it < niter; ++it) {
        As[ar][ak + 0] = f2tf32(pa.x);
        As[ar][ak + 1] = f2tf32(pa.y);
        As[ar][ak + 2] = f2tf32(pa.z);
        As[ar][ak + 3] = f2tf32(pa.w);
        Bs[bk][bn + 0] = f2tf32(pb.x);
        Bs[bk][bn + 1] = f2tf32(pb.y);
        Bs[bk][bn + 2] = f2tf32(pb.z);
        Bs[bk][bn + 3] = f2tf32(pb.w);
        __syncthreads();

        if (it + 1 < niter) {
            pa = *(const float4*)(Ag + (size_t)(it + 1) * 8);
            pb = *(const float4*)(Bg + (size_t)(it + 1) * 8 * N);
        }

        uint32_t af[4][4];
#pragma unroll
        for (int mt = 0; mt < 4; mt++) {
            int rbase = wm * 64 + mt * 16 + gid;
            af[mt][0] = As[rbase    ][tig    ];
            af[mt][1] = As[rbase + 8][tig    ];
            af[mt][2] = As[rbase    ][tig + 4];
            af[mt][3] = As[rbase + 8][tig + 4];
        }
        uint32_t bf[4][2];
#pragma unroll
        for (int nt = 0; nt < 4; nt++) {
            int cb = wn * 32 + nt * 8 + gid;
            bf[nt][0] = Bs[tig    ][cb];
            bf[nt][1] = Bs[tig + 4][cb];
        }
#pragma unroll
        for (int mt = 0; mt < 4; mt++)
#pragma unroll
            for (int nt = 0; nt < 4; nt++)
                mma_tf32(acc[mt][nt], af[mt], bf[nt]);

        __syncthreads();
    }

#pragma unroll
    for (int mt = 0; mt < 4; mt++) {
        int row_lo = row0 + wm * 64 + mt * 16 + gid;
        int row_hi = row_lo + 8;
#pragma unroll
        for (int nt = 0; nt < 4; nt++) {
            int col = col0 + wn * 32 + nt * 8 + tig * 2;
            float v0 = acc[mt][nt][0], v1 = acc[mt][nt][1];
            float v2 = acc[mt][nt][2], v3 = acc[mt][nt][3];
            float b0 = bias[col], b1 = bias[col + 1];
            v0 += b0; v1 += b1; v2 += b0; v3 += b1;
            *(float2*)(C + (size_t)row_lo * N + col) = make_float2(v0, v1);
            *(float2*)(C + (size_t)row_hi * N + col) = make_float2(v2, v3);
        }
    }
}

// ============ cp.async 2-stage pipelined TF32 GEMM (K % 16 == 0) =============
// MODE 1: C = tanh(A@B + bias[col])
// MODE 2: C = tanh(A@B + bias[(row & 4095)*512 + col])
template<int MODE>
__global__ __launch_bounds__(256)
void tgemm_pipe(const float* __restrict__ A, const float* __restrict__ B,
                const float* __restrict__ bias, float* __restrict__ C,
                int M, int N, int K)
{
    __shared__ uint32_t As[2][128][20];
    __shared__ uint32_t Bs[2][16][136];

    const int tid  = threadIdx.x;
    const int wid  = tid >> 5;
    const int lane = tid & 31;
    const int gid  = lane >> 2;
    const int tig  = lane & 3;
    const int wm   = wid >> 2;
    const int wn   = wid & 3;

    const int row0 = blockIdx.y * 128;
    const int col0 = blockIdx.x * 128;

    float acc[4][4][4];
#pragma unroll
    for (int mt = 0; mt < 4; mt++)
#pragma unroll
        for (int nt = 0; nt < 4; nt++)
#pragma unroll
            for (int r = 0; r < 4; r++) acc[mt][nt][r] = 0.f;

    const int nk = K >> 4;

    // loader assignments
    const int la_r  = tid >> 1;              // A: rows 0..127 (2 chunks/thread)
    const int la_k  = (tid & 1) * 8;         // 0 or 8 ... chunk covers k..k+3 twice
    const int lb_k  = tid >> 5;              // B: 2 chunks/thread over k 0..15
    const int lb_n  = (tid & 31) * 4;

#define LOAD_STAGE(s, kt)                                                          \
    do {                                                                           \
        cpa16(&As[s][la_r][la_k],                                                  \
              A + (size_t)(row0 + la_r) * K + (kt) * 16 + la_k);                   \
        cpa16(&As[s][la_r][la_k + 4],                                              \
              A + (size_t)(row0 + la_r) * K + (kt) * 16 + la_k + 4);               \
        cpa16(&Bs[s][lb_k][lb_n],                                                  \
              B + (size_t)((kt) * 16 + lb_k) * N + col0 + lb_n);                   \
        cpa16(&Bs[s][lb_k + 8][lb_n],                                              \
              B + (size_t)((kt) * 16 + lb_k + 8) * N + col0 + lb_n);               \
        cpa_commit();                                                              \
    } while (0)

    LOAD_STAGE(0, 0);
    LOAD_STAGE(1, 1);

    for (int kt = 0; kt < nk; ++kt) {
        const int s = kt & 1;
        cpa_wait<1>();
        __syncthreads();

#pragma unroll
        for (int ks = 0; ks < 16; ks += 8) {
            uint32_t af[4][4];
#pragma unroll
            for (int mt = 0; mt < 4; mt++) {
                int rbase = wm * 64 + mt * 16 + gid;
                af[mt][0] = As[s][rbase    ][ks + tig    ];
                af[mt][1] = As[s][rbase + 8][ks + tig    ];
                af[mt][2] = As[s][rbase    ][ks + tig + 4];
                af[mt][3] = As[s][rbase + 8][ks + tig + 4];
            }
            uint32_t bf[4][2];
#pragma unroll
            for (int nt = 0; nt < 4; nt++) {
                int cb = wn * 32 + nt * 8 + gid;
                bf[nt][0] = Bs[s][ks + tig    ][cb];
                bf[nt][1] = Bs[s][ks + tig + 4][cb];
            }
#pragma unroll
            for (int mt = 0; mt < 4; mt++)
#pragma unroll
                for (int nt = 0; nt < 4; nt++)
                    mma_tf32(acc[mt][nt], af[mt], bf[nt]);
        }
        __syncthreads();
        if (kt + 2 < nk) LOAD_STAGE(s, kt + 2);
    }
#undef LOAD_STAGE

#pragma unroll
    for (int mt = 0; mt < 4; mt++) {
        int row_lo = row0 + wm * 64 + mt * 16 + gid;
        int row_hi = row_lo + 8;
#pragma unroll
        for (int nt = 0; nt < 4; nt++) {
            int col = col0 + wn * 32 + nt * 8 + tig * 2;
            float v0 = acc[mt][nt][0], v1 = acc[mt][nt][1];
            float v2 = acc[mt][nt][2], v3 = acc[mt][nt][3];
            if (MODE == 1) {
                float b0 = bias[col], b1 = bias[col + 1];
                v0 = fast_tanh(v0 + b0); v1 = fast_tanh(v1 + b1);
                v2 = fast_tanh(v2 + b0); v3 = fast_tanh(v3 + b1);
            } else {
                const float* blo = bias + (size_t)(row_lo & (Bn - 1)) * HIDd + col;
                const float* bhi = bias + (size_t)(row_hi & (Bn - 1)) * HIDd + col;
                v0 = fast_tanh(v0 + blo[0]); v1 = fast_tanh(v1 + blo[1]);
                v2 = fast_tanh(v2 + bhi[0]); v3 = fast_tanh(v3 + bhi[1]);
            }
            *(float2*)(C + (size_t)row_lo * N + col) = make_float2(v0, v1);
            *(float2*)(C + (size_t)row_hi * N + col) = make_float2(v2, v3);
        }
    }
}

// ============ fused GRU step: 3-gate GEMM + gates + state update =============
// Block: 128 batch x 64 j.  Computes h_{t+1}[row0..+128][j0..+64].
__global__ __launch_bounds__(256)
void gru_fused_kernel(const float* __restrict__ Hprev,  // g_H + t*Bn*Hh
                      float* __restrict__ Hnext,        // g_H + (t+1)*Bn*Hh
                      const float* __restrict__ Whh,    // [512][1536]
                      const float* __restrict__ Wih,    // row 0 = w_z [1536]
                      const float* __restrict__ bhh,    // [1536]
                      const float* __restrict__ gic,    // [Bn][1536]
                      const float* __restrict__ z, int t)
{
    __shared__ uint32_t As[2][128][20];
    __shared__ uint32_t Bs[2][3][16][72];

    const int tid  = threadIdx.x;
    const int wid  = tid >> 5;
    const int lane = tid & 31;
    const int gid  = lane >> 2;
    const int tig  = lane & 3;
    const int wm   = wid >> 1;     // 0..3 : 32-row slice
    const int wn   = wid & 1;      // 0..1 : 32-col slice

    const int row0 = blockIdx.y * 128;
    const int j0   = blockIdx.x * 64;

    float acc[3][2][4][4];
#pragma unroll
    for (int g = 0; g < 3; g++)
#pragma unroll
        for (int mt = 0; mt < 2; mt++)
#pragma unroll
            for (int nt = 0; nt < 4; nt++)
#pragma unroll
                for (int r = 0; r < 4; r++) acc[g][mt][nt][r] = 0.f;

    // A loader: 512 chunks -> 2/thread
    const int la_r = tid >> 1;
    const int la_k = (tid & 1) * 8;

#define LOAD_STAGE(s, kt)                                                          \
    do {                                                                           \
        cpa16(&As[s][la_r][la_k],                                                  \
              Hprev + (size_t)(row0 + la_r) * 512 + (kt) * 16 + la_k);             \
        cpa16(&As[s][la_r][la_k + 4],                                              \
              Hprev + (size_t)(row0 + la_r) * 512 + (kt) * 16 + la_k + 4);         \
        _Pragma("unroll")                                                          \
        for (int i = 0; i < 3; i++) {                                              \
            int cc  = tid + i * 256;                                               \
            int gg  = cc >> 8;                                                     \
            int rem = cc & 255;                                                    \
            int bk  = rem >> 4;                                                    \
            int bn4 = (rem & 15) * 4;                                              \
            cpa16(&Bs[s][gg][bk][bn4],                                             \
                  Whh + (size_t)((kt) * 16 + bk) * G3 + gg * 512 + j0 + bn4);      \
        }                                                                          \
        cpa_commit();                                                              \
    } while (0)

    LOAD_STAGE(0, 0);
    LOAD_STAGE(1, 1);

    for (int kt = 0; kt < 32; ++kt) {
        const int s = kt & 1;
        cpa_wait<1>();
        __syncthreads();

#pragma unroll
        for (int ks = 0; ks < 16; ks += 8) {
            uint32_t af[2][4];
#pragma unroll
            for (int mt = 0; mt < 2; mt++) {
                int rbase = wm * 32 + mt * 16 + gid;
                af[mt][0] = As[s][rbase    ][ks + tig    ];
                af[mt][1] = As[s][rbase + 8][ks + tig    ];
                af[mt][2] = As[s][rbase    ][ks + tig + 4];
                af[mt][3] = As[s][rbase + 8][ks + tig + 4];
            }
#pragma unroll
            for (int g = 0; g < 3; g++) {
                uint32_t bf[4][2];
#pragma unroll
                for (int nt = 0; nt < 4; nt++) {
                    int cb = wn * 32 + nt * 8 + gid;
                    bf[nt][0] = Bs[s][g][ks + tig    ][cb];
                    bf[nt][1] = Bs[s][g][ks + tig + 4][cb];
                }
#pragma unroll
                for (int mt = 0; mt < 2; mt++)
#pragma unroll
                    for (int nt = 0; nt < 4; nt++)
                        mma_tf32(acc[g][mt][nt], af[mt], bf[nt]);
            }
        }
        __syncthreads();
        if (kt + 2 < 32) LOAD_STAGE(s, kt + 2);
    }
#undef LOAD_STAGE

    // ---- epilogue: GRU gates + state update --------------------------------
#pragma unroll
    for (int mt = 0; mt < 2; mt++) {
        int b_lo = row0 + wm * 32 + mt * 16 + gid;
        int b_hi = b_lo + 8;
        float zt_lo = (t == 0) ? -1.0f : z[(size_t)b_lo * Dd + (t - 1)];
        float zt_hi = (t == 0) ? -1.0f : z[(size_t)b_hi * Dd + (t - 1)];
        const float* gic_lo = gic + (size_t)b_lo * G3;
        const float* gic_hi = gic + (size_t)b_hi * G3;
        const float* hp_lo  = Hprev + (size_t)b_lo * 512;
        const float* hp_hi  = Hprev + (size_t)b_hi * 512;
        float* hn_lo = Hnext + (size_t)b_lo * 512;
        float* hn_hi = Hnext + (size_t)b_hi * 512;
#pragma unroll
        for (int nt = 0; nt < 4; nt++) {
            int jc = j0 + wn * 32 + nt * 8 + tig * 2;
#pragma unroll
            for (int cc = 0; cc < 2; cc++) {
                int j = jc + cc;
                float wzr = Wih[j], wzz = Wih[512 + j], wzn = Wih[1024 + j];
                float br  = bhh[j], bz  = bhh[512 + j], bn_ = bhh[1024 + j];
                // low row
                {
                    float hr = acc[0][mt][nt][cc] + br;
                    float hz = acc[1][mt][nt][cc] + bz;
                    float hn = acc[2][mt][nt][cc] + bn_;
                    float ir  = fmaf(zt_lo, wzr, gic_lo[j]);
                    float iz  = fmaf(zt_lo, wzz, gic_lo[512 + j]);
                    float inn = fmaf(zt_lo, wzn, gic_lo[1024 + j]);
                    float r = fast_sig(ir + hr);
                    float u = fast_sig(iz + hz);
                    float n = fast_tanh(fmaf(r, hn, inn));
                    float hp = hp_lo[j];
                    hn_lo[j] = fmaf(u, hp - n, n);
                }
                // high row
                {
                    float hr = acc[0][mt][nt][2 + cc] + br;
                    float hz = acc[1][mt][nt][2 + cc] + bz;
                    float hn = acc[2][mt][nt][2 + cc] + bn_;
                    float ir  = fmaf(zt_hi, wzr, gic_hi[j]);
                    float iz  = fmaf(zt_hi, wzz, gic_hi[512 + j]);
                    float inn = fmaf(zt_hi, wzn, gic_hi[1024 + j]);
                    float r = fast_sig(ir + hr);
                    float u = fast_sig(iz + hz);
                    float n = fast_tanh(fmaf(r, hn, inn));
                    float hp = hp_hi[j];
                    hn_hi[j] = fmaf(u, hp - n, n);
                }
            }
        }
    }
}

// ---------------- head GEMM (N=30) fused with mixture log-likelihood --------
__global__ __launch_bounds__(128)
void head_kernel(const float* __restrict__ W2, const float* __restrict__ b2,
                 const float* __restrict__ z)
{
    __shared__ float a2s[4][512];
    __shared__ float ps[4][32];
    int w = threadIdx.x >> 5, lane = threadIdx.x & 31;
    size_t r = (size_t)blockIdx.x * 4 + w;

    const float4* src = (const float4*)(g_A2 + r * HIDd);
#pragma unroll
    for (int i = 0; i < 4; i++) {
        float4 v = src[lane + 32 * i];
        *(float4*)&a2s[w][(lane + 32 * i) * 4] = v;
    }
    __syncwarp();

    if (lane < 30) {
        float acc = b2[lane];
#pragma unroll 8
        for (int k = 0; k < 512; k++)
            acc = fmaf(a2s[w][k], W2[k * 30 + lane], acc);
        ps[w][lane] = acc;
    }
    __syncwarp();

    if (lane == 0) {
        int t = (int)(r >> 12);
        int b = (int)(r & 4095);
        float zv = z[(size_t)b * Dd + t];
        float* p = ps[w];
        float m1 = -1e30f, m2 = -1e30f;
        float term[10];
#pragma unroll
        for (int k = 0; k < 10; k++) {
            float l = p[k], mu = p[10 + k], ls = p[20 + k];
            float d = (zv - mu) * expf(-ls);
            float tv = l - ls - 0.91893853320467274f - 0.5f * d * d;
            term[k] = tv;
            m1 = fmaxf(m1, tv);
            m2 = fmaxf(m2, l);
        }
        float s1 = 0.f, s2 = 0.f;
#pragma unroll
        for (int k = 0; k < 10; k++) {
            s1 += expf(term[k] - m1);
            s2 += expf(p[k] - m2);
        }
        g_ll[(size_t)b * Dd + t] = (m1 + logf(s1)) - (m2 + logf(s2));
    }
}

// ---------------- final: sort query desc (bitonic) + masked dot -------------
__global__ __launch_bounds__(128)
void final_kernel(const float* __restrict__ bb, const float* __restrict__ m,
                  float* __restrict__ out)
{
    __shared__ float s[128];
    __shared__ float red[128];
    int b = blockIdx.x, t = threadIdx.x;

    float q = -1.0f;
    if (t < Dd) {
        float bv = bb[(size_t)b * Dd + t];
        q = m[(size_t)b * Dd + t] * (1.0f - bv);
    }
    s[t] = q;
    __syncthreads();

    for (int k = 2; k <= 128; k <<= 1) {
        for (int j = k >> 1; j > 0; j >>= 1) {
            int ixj = t ^ j;
            if (ixj > t) {
                float a = s[t], c = s[ixj];
                bool up = ((t & k) == 0);
                if (up ? (a > c) : (a < c)) { s[t] = c; s[ixj] = a; }
            }
            __syncthreads();
        }
    }

    float prod = 0.f;
    if (t < Dd) prod = g_ll[(size_t)b * Dd + t] * s[127 - t];
    red[t] = prod;
    __syncthreads();
    for (int st = 64; st > 0; st >>= 1) {
        if (t < st) red[t] += red[t + st];
        __syncthreads();
    }
    if (t == 0) out[b] = red[0];
}

// ---------------- launch ----------------------------------------------------
extern "C" void kernel_launch(void* const* d_in, const int* in_sizes, int n_in,
                              void* d_out, int out_size)
{
    const float* z   = (const float*)d_in[0];
    const float* c   = (const float*)d_in[1];
    const float* bb  = (const float*)d_in[2];
    const float* m   = (const float*)d_in[3];
    const float* Wih = (const float*)d_in[4];
    const float* Whh = (const float*)d_in[5];
    const float* bih = (const float*)d_in[6];
    const float* bhh = (const float*)d_in[7];
    const float* W0  = (const float*)d_in[8];
    const float* b0  = (const float*)d_in[9];
    const float* W1  = (const float*)d_in[10];
    const float* b1  = (const float*)d_in[11];
    const float* W2  = (const float*)d_in[12];
    const float* b2  = (const float*)d_in[13];
    float* out = (float*)d_out;

    float *pGic, *pMlpc, *pH, *pA1, *pA2, *pConst;
    cudaGetSymbolAddress((void**)&pConst, g_const);
    cudaGetSymbolAddress((void**)&pGic,   g_gic);
    cudaGetSymbolAddress((void**)&pMlpc,  g_mlpc);
    cudaGetSymbolAddress((void**)&pH,     g_H);
    cudaGetSymbolAddress((void**)&pA1,    g_A1);
    cudaGetSymbolAddress((void**)&pA2,    g_A2);

    build_const_kernel<<<(Bn * CN + 255) / 256, 256>>>(c, bb, m);
    zero_h0_kernel<<<(Bn * Hh) / 256, 256>>>();

    // gi_const = const @ Wih[1:] + bih          (4096 x 1536, K=536)
    tgemm_kernel<0><<<dim3(G3 / 128, Bn / 128), 256>>>(pConst, Wih + G3, bih, pGic,
                                                       Bn, G3, CN);
    // mlp_const = const @ W0[H:] + b0           (4096 x 512, K=536)
    tgemm_kernel<0><<<dim3(HIDd / 128, Bn / 128), 256>>>(pConst, W0 + (size_t)Hh * HIDd,
                                                         b0, pMlpc, Bn, HIDd, CN);
    // recurrence: one fused kernel per step
    for (int t = 0; t < Dd; t++) {
        gru_fused_kernel<<<dim3(Hh / 64, Bn / 128), 256>>>(
            pH + (size_t)t * Bn * Hh, pH + (size_t)(t + 1) * Bn * Hh,
            Whh, Wih, bhh, pGic, z, t);
    }
    // batched MLP over all (t,b) rows
    tgemm_pipe<2><<<dim3(HIDd / 128, TOTR / 128), 256>>>(pH + (size_t)Bn * Hh, W0,
                                                         pMlpc, pA1, TOTR, HIDd, Hh);
    tgemm_pipe<1><<<dim3(HIDd / 128, TOTR / 128), 256>>>(pA1, W1, b1, pA2,
                                                         TOTR, HIDd, HIDd);
    head_kernel<<<TOTR / 4, 128>>>(W2, b2, z);
    final_kernel<<<Bn, 128>>>(bb, m, out);
}

// round 4
// speedup vs baseline: 2.7535x; 1.1361x over previous
#include <cuda_runtime.h>
#include <cuda_bf16.h>
#include <math.h>
#include <stdint.h>

#define Bn   4096
#define Dd   112
#define NTd  200
#define Hh   512
#define HIDd 512
#define CN   536      /* 3*D + NT */
#define G3   1536     /* 3*H */
#define TOTR (Dd*Bn)  /* 458752 */

// ---------------- device scratch ---------------------------------------------
__device__ float g_const[(size_t)Bn * CN];
__device__ float g_gic  [(size_t)Bn * G3];
__device__ float g_mlpc [(size_t)Bn * HIDd];
__device__ float g_Hf   [2 * (size_t)Bn * Hh];                 // fp32 ping-pong
__device__ __nv_bfloat16 g_Hbf [(size_t)(Dd+1) * Bn * Hh];     // bf16 history
__device__ __nv_bfloat16 g_WhhT[(size_t)G3 * Hh];              // [n=1536][k=512]
__device__ __nv_bfloat16 g_W0T [(size_t)HIDd * Hh];            // [n=512][k=512]
__device__ __nv_bfloat16 g_W1T [(size_t)HIDd * HIDd];
__device__ __nv_bfloat16 g_A1bf[(size_t)TOTR * HIDd];
__device__ float g_A2   [(size_t)TOTR * HIDd];
__device__ float g_ll   [(size_t)Bn * Dd];

// ---------------- helpers ----------------------------------------------------
__device__ __forceinline__ float fast_sig(float x)  { return 1.f / (1.f + __expf(-x)); }
__device__ __forceinline__ float fast_tanh(float x) { return fmaf(2.f, 1.f / (1.f + __expf(-2.f * x)), -1.f); }

__global__ void build_const_kernel(const float* __restrict__ c,
                                   const float* __restrict__ bb,
                                   const float* __restrict__ m)
{
    size_t idx = (size_t)blockIdx.x * blockDim.x + threadIdx.x;
    if (idx >= (size_t)Bn * CN) return;
    int b = (int)(idx / CN);
    int i = (int)(idx % CN);
    float v;
    if (i < Dd + NTd)            v = c [(size_t)b * (Dd + NTd) + i];
    else if (i < Dd + NTd + Dd)  v = bb[(size_t)b * Dd + (i - (Dd + NTd))];
    else                         v = m [(size_t)b * Dd + (i - (Dd + NTd + Dd))];
    g_const[idx] = v;
}

__global__ void zero_h0_kernel()
{
    size_t idx = (size_t)blockIdx.x * blockDim.x + threadIdx.x;
    if (idx < (size_t)Bn * Hh) {
        g_Hf[idx] = 0.f;
        g_Hbf[idx] = __float2bfloat16(0.f);
    }
}

// transpose+convert: out[n][Krows] (bf16) = in[k][Ncols] (f32)
__global__ void convT_kernel(const float* __restrict__ in, __nv_bfloat16* __restrict__ out,
                             int Krows, int Ncols)
{
    __shared__ float tile[32][33];
    int k0 = blockIdx.y * 32, n0 = blockIdx.x * 32;
    int tx = threadIdx.x, ty = threadIdx.y;
    for (int i = ty; i < 32; i += 8)
        tile[i][tx] = in[(size_t)(k0 + i) * Ncols + n0 + tx];
    __syncthreads();
    for (int i = ty; i < 32; i += 8)
        out[(size_t)(n0 + i) * Krows + k0 + tx] = __float2bfloat16(tile[tx][i]);
}

__device__ __forceinline__ uint32_t f2tf32(float x)
{
    uint32_t u;
    asm("cvt.rna.tf32.f32 %0, %1;" : "=r"(u) : "f"(x));
    return u;
}
__device__ __forceinline__ void mma_tf32(float* d, const uint32_t* a, const uint32_t* b)
{
    asm volatile(
        "mma.sync.aligned.m16n8k8.row.col.f32.tf32.tf32.f32 "
        "{%0,%1,%2,%3}, {%4,%5,%6,%7}, {%8,%9}, {%0,%1,%2,%3};\n"
        : "+f"(d[0]), "+f"(d[1]), "+f"(d[2]), "+f"(d[3])
        : "r"(a[0]), "r"(a[1]), "r"(a[2]), "r"(a[3]), "r"(b[0]), "r"(b[1]));
}
__device__ __forceinline__ void mma_bf16(float* d, const uint32_t* a, const uint32_t* b)
{
    asm volatile(
        "mma.sync.aligned.m16n8k16.row.col.f32.bf16.bf16.f32 "
        "{%0,%1,%2,%3}, {%4,%5,%6,%7}, {%8,%9}, {%0,%1,%2,%3};\n"
        : "+f"(d[0]), "+f"(d[1]), "+f"(d[2]), "+f"(d[3])
        : "r"(a[0]), "r"(a[1]), "r"(a[2]), "r"(a[3]), "r"(b[0]), "r"(b[1]));
}
__device__ __forceinline__ void cpa16(void* smem, const void* gmem)
{
    uint32_t s = (uint32_t)__cvta_generic_to_shared(smem);
    asm volatile("cp.async.cg.shared.global [%0], [%1], 16;\n" :: "r"(s), "l"(gmem));
}
__device__ __forceinline__ void cpa_commit() { asm volatile("cp.async.commit_group;\n"); }
template<int N>
__device__ __forceinline__ void cpa_wait()   { asm volatile("cp.async.wait_group %0;\n" :: "n"(N)); }

// ============ legacy tf32 GEMM for K=536 precompute (fp32 in/out) ============
__global__ __launch_bounds__(256)
void tgemm_kernel(const float* __restrict__ A, const float* __restrict__ B,
                  const float* __restrict__ bias, float* __restrict__ C,
                  int M, int N, int K)
{
    __shared__ uint32_t As[128][12];
    __shared__ uint32_t Bs[8][136];

    const int tid  = threadIdx.x;
    const int wid  = tid >> 5;
    const int lane = tid & 31;
    const int gid  = lane >> 2;
    const int tig  = lane & 3;
    const int wm   = wid >> 2;
    const int wn   = wid & 3;
    const int row0 = blockIdx.y * 128;
    const int col0 = blockIdx.x * 128;

    float acc[4][4][4];
#pragma unroll
    for (int mt = 0; mt < 4; mt++)
#pragma unroll
        for (int nt = 0; nt < 4; nt++)
#pragma unroll
            for (int r = 0; r < 4; r++) acc[mt][nt][r] = 0.f;

    const int ar = tid >> 1;
    const int ak = (tid & 1) * 4;
    const int bk = tid >> 5;
    const int bn = (tid & 31) * 4;
    const int niter = K >> 3;

    const float* Ag = A + (size_t)(row0 + ar) * K + ak;
    const float* Bg = B + (size_t)bk * N + col0 + bn;

    float4 pa = *(const float4*)Ag;
    float4 pb = *(const float4*)Bg;

    for (int it = 0; it < niter; ++it) {
        As[ar][ak + 0] = f2tf32(pa.x); As[ar][ak + 1] = f2tf32(pa.y);
        As[ar][ak + 2] = f2tf32(pa.z); As[ar][ak + 3] = f2tf32(pa.w);
        Bs[bk][bn + 0] = f2tf32(pb.x); Bs[bk][bn + 1] = f2tf32(pb.y);
        Bs[bk][bn + 2] = f2tf32(pb.z); Bs[bk][bn + 3] = f2tf32(pb.w);
        __syncthreads();
        if (it + 1 < niter) {
            pa = *(const float4*)(Ag + (size_t)(it + 1) * 8);
            pb = *(const float4*)(Bg + (size_t)(it + 1) * 8 * N);
        }
        uint32_t af[4][4];
#pragma unroll
        for (int mt = 0; mt < 4; mt++) {
            int rb = wm * 64 + mt * 16 + gid;
            af[mt][0] = As[rb][tig];     af[mt][1] = As[rb + 8][tig];
            af[mt][2] = As[rb][tig + 4]; af[mt][3] = As[rb + 8][tig + 4];
        }
        uint32_t bf[4][2];
#pragma unroll
        for (int nt = 0; nt < 4; nt++) {
            int cb = wn * 32 + nt * 8 + gid;
            bf[nt][0] = Bs[tig][cb]; bf[nt][1] = Bs[tig + 4][cb];
        }
#pragma unroll
        for (int mt = 0; mt < 4; mt++)
#pragma unroll
            for (int nt = 0; nt < 4; nt++)
                mma_tf32(acc[mt][nt], af[mt], bf[nt]);
        __syncthreads();
    }
#pragma unroll
    for (int mt = 0; mt < 4; mt++) {
        int row_lo = row0 + wm * 64 + mt * 16 + gid;
        int row_hi = row_lo + 8;
#pragma unroll
        for (int nt = 0; nt < 4; nt++) {
            int col = col0 + wn * 32 + nt * 8 + tig * 2;
            float b0 = bias[col], b1 = bias[col + 1];
            *(float2*)(C + (size_t)row_lo * N + col) =
                make_float2(acc[mt][nt][0] + b0, acc[mt][nt][1] + b1);
            *(float2*)(C + (size_t)row_hi * N + col) =
                make_float2(acc[mt][nt][2] + b0, acc[mt][nt][3] + b1);
        }
    }
}

// ============ bf16 MLP GEMM (A bf16 [M][512], BT bf16 [512][512]) ============
// MODE 0: bf16 out = tanh(v + mlpc[row&4095][col])
// MODE 1: f32  out = tanh(v + bias[col])
template<int MODE>
__global__ __launch_bounds__(256)
void bgemm_mlp(const __nv_bfloat16* __restrict__ A, const __nv_bfloat16* __restrict__ BT,
               const float* __restrict__ bias, void* __restrict__ Cout, int M)
{
    const int K = 512, N = 512;
    __shared__ uint32_t As[2][128][20];   // 128 rows x 32 bf16 (16 u32) + pad4
    __shared__ uint32_t Bs[2][128][20];   // 128 n    x 32 bf16

    const int tid  = threadIdx.x;
    const int wid  = tid >> 5;
    const int lane = tid & 31;
    const int g    = lane >> 2;
    const int t    = lane & 3;
    const int wm   = wid >> 2;           // 0..1 (64 rows)
    const int wn   = wid & 3;            // 0..3 (32 cols)

    const int row0 = blockIdx.y * 128;
    const int col0 = blockIdx.x * 128;

    float acc[4][4][4];
#pragma unroll
    for (int mt = 0; mt < 4; mt++)
#pragma unroll
        for (int nt = 0; nt < 4; nt++)
#pragma unroll
            for (int r = 0; r < 4; r++) acc[mt][nt][r] = 0.f;

    const int lr = tid >> 1;             // 0..127
    const int lc = (tid & 1) * 2;        // chunk 0/2 (+1)

#define LOAD_STAGE(s, kt)                                                        \
    do {                                                                         \
        cpa16(&As[s][lr][lc * 4],                                                \
              A  + (size_t)(row0 + lr) * K + (kt) * 32 + lc * 8);                \
        cpa16(&As[s][lr][(lc + 1) * 4],                                          \
              A  + (size_t)(row0 + lr) * K + (kt) * 32 + (lc + 1) * 8);          \
        cpa16(&Bs[s][lr][lc * 4],                                                \
              BT + (size_t)(col0 + lr) * K + (kt) * 32 + lc * 8);                \
        cpa16(&Bs[s][lr][(lc + 1) * 4],                                          \
              BT + (size_t)(col0 + lr) * K + (kt) * 32 + (lc + 1) * 8);          \
        cpa_commit();                                                            \
    } while (0)

    LOAD_STAGE(0, 0);
    LOAD_STAGE(1, 1);

    const int nk = K / 32;               // 16
    for (int kt = 0; kt < nk; ++kt) {
        const int s = kt & 1;
        cpa_wait<1>();
        __syncthreads();
#pragma unroll
        for (int kb = 0; kb < 16; kb += 8) {   // two k16 slabs
            uint32_t af[4][4];
#pragma unroll
            for (int mt = 0; mt < 4; mt++) {
                int r = wm * 64 + mt * 16 + g;
                af[mt][0] = As[s][r][kb + t];     af[mt][1] = As[s][r + 8][kb + t];
                af[mt][2] = As[s][r][kb + t + 4]; af[mt][3] = As[s][r + 8][kb + t + 4];
            }
#pragma unroll
            for (int nt = 0; nt < 4; nt++) {
                int n = wn * 32 + nt * 8 + g;
                uint32_t bf[2];
                bf[0] = Bs[s][n][kb + t];
                bf[1] = Bs[s][n][kb + t + 4];
#pragma unroll
                for (int mt = 0; mt < 4; mt++)
                    mma_bf16(acc[mt][nt], af[mt], bf);
            }
        }
        __syncthreads();
        if (kt + 2 < nk) LOAD_STAGE(s, kt + 2);
    }
#undef LOAD_STAGE

#pragma unroll
    for (int mt = 0; mt < 4; mt++) {
        int row_lo = row0 + wm * 64 + mt * 16 + g;
        int row_hi = row_lo + 8;
#pragma unroll
        for (int nt = 0; nt < 4; nt++) {
            int col = col0 + wn * 32 + nt * 8 + t * 2;
            float v0 = acc[mt][nt][0], v1 = acc[mt][nt][1];
            float v2 = acc[mt][nt][2], v3 = acc[mt][nt][3];
            if (MODE == 0) {
                const float* blo = bias + (size_t)(row_lo & (Bn - 1)) * HIDd + col;
                const float* bhi = bias + (size_t)(row_hi & (Bn - 1)) * HIDd + col;
                v0 = fast_tanh(v0 + blo[0]); v1 = fast_tanh(v1 + blo[1]);
                v2 = fast_tanh(v2 + bhi[0]); v3 = fast_tanh(v3 + bhi[1]);
                __nv_bfloat16* C = (__nv_bfloat16*)Cout;
                *(__nv_bfloat162*)(C + (size_t)row_lo * N + col) = __floats2bfloat162_rn(v0, v1);
                *(__nv_bfloat162*)(C + (size_t)row_hi * N + col) = __floats2bfloat162_rn(v2, v3);
            } else {
                float b0 = bias[col], b1 = bias[col + 1];
                v0 = fast_tanh(v0 + b0); v1 = fast_tanh(v1 + b1);
                v2 = fast_tanh(v2 + b0); v3 = fast_tanh(v3 + b1);
                float* C = (float*)Cout;
                *(float2*)(C + (size_t)row_lo * N + col) = make_float2(v0, v1);
                *(float2*)(C + (size_t)row_hi * N + col) = make_float2(v2, v3);
            }
        }
    }
}

// ============ fused GRU step (bf16 GEMM + gates), 128 batch x 64 j ==========
__global__ __launch_bounds__(256)
void gru_fused_bf16(const __nv_bfloat16* __restrict__ Hbf_prev,
                    __nv_bfloat16* __restrict__ Hbf_next,
                    const float* __restrict__ Hf_prev,
                    float* __restrict__ Hf_next,
                    const __nv_bfloat16* __restrict__ WhhT,   // [1536][512]
                    const float* __restrict__ Wih,            // row0 = w_z [1536]
                    const float* __restrict__ bhh,
                    const float* __restrict__ gic,
                    const float* __restrict__ z, int t)
{
    const int K = 512;
    __shared__ uint32_t As[2][128][20];        // 128 batch x 32 k (bf16)
    __shared__ uint32_t Bs[2][3][64][20];      // gate x 64 j x 32 k

    const int tid  = threadIdx.x;
    const int wid  = tid >> 5;
    const int lane = tid & 31;
    const int g    = lane >> 2;
    const int t4   = lane & 3;
    const int wm   = wid >> 1;                 // 0..3 (32 rows)
    const int wn   = wid & 1;                  // 0..1 (32 cols)

    const int row0 = blockIdx.y * 128;
    const int j0   = blockIdx.x * 64;

    float acc[3][2][4][4];
#pragma unroll
    for (int gg = 0; gg < 3; gg++)
#pragma unroll
        for (int mt = 0; mt < 2; mt++)
#pragma unroll
            for (int nt = 0; nt < 4; nt++)
#pragma unroll
                for (int r = 0; r < 4; r++) acc[gg][mt][nt][r] = 0.f;

    const int lr = tid >> 1;
    const int lc = (tid & 1) * 2;

#define LOAD_STAGE(s, kt)                                                        \
    do {                                                                         \
        cpa16(&As[s][lr][lc * 4],                                                \
              Hbf_prev + (size_t)(row0 + lr) * K + (kt) * 32 + lc * 8);          \
        cpa16(&As[s][lr][(lc + 1) * 4],                                          \
              Hbf_prev + (size_t)(row0 + lr) * K + (kt) * 32 + (lc + 1) * 8);    \
        _Pragma("unroll")                                                        \
        for (int i = 0; i < 3; i++) {                                            \
            int cc  = tid + i * 256;                                             \
            int gg  = cc >> 8;                                                   \
            int rem = cc & 255;                                                  \
            int n   = rem >> 2;                                                  \
            int ch  = rem & 3;                                                   \
            cpa16(&Bs[s][gg][n][ch * 4],                                         \
                  WhhT + (size_t)(gg * 512 + j0 + n) * K + (kt) * 32 + ch * 8);  \
        }                                                                        \
        cpa_commit();                                                            \
    } while (0)

    LOAD_STAGE(0, 0);
    LOAD_STAGE(1, 1);

    const int nk = K / 32;                     // 16
    for (int kt = 0; kt < nk; ++kt) {
        const int s = kt & 1;
        cpa_wait<1>();
        __syncthreads();
#pragma unroll
        for (int kb = 0; kb < 16; kb += 8) {
            uint32_t af[2][4];
#pragma unroll
            for (int mt = 0; mt < 2; mt++) {
                int r = wm * 32 + mt * 16 + g;
                af[mt][0] = As[s][r][kb + t4];     af[mt][1] = As[s][r + 8][kb + t4];
                af[mt][2] = As[s][r][kb + t4 + 4]; af[mt][3] = As[s][r + 8][kb + t4 + 4];
            }
#pragma unroll
            for (int gg = 0; gg < 3; gg++)
#pragma unroll
                for (int nt = 0; nt < 4; nt++) {
                    int n = wn * 32 + nt * 8 + g;
                    uint32_t bf[2];
                    bf[0] = Bs[s][gg][n][kb + t4];
                    bf[1] = Bs[s][gg][n][kb + t4 + 4];
#pragma unroll
                    for (int mt = 0; mt < 2; mt++)
                        mma_bf16(acc[gg][mt][nt], af[mt], bf);
                }
        }
        __syncthreads();
        if (kt + 2 < nk) LOAD_STAGE(s, kt + 2);
    }
#undef LOAD_STAGE

    // ---- epilogue: gates + state update ------------------------------------
#pragma unroll
    for (int mt = 0; mt < 2; mt++) {
        int b_lo = row0 + wm * 32 + mt * 16 + g;
        int b_hi = b_lo + 8;
        float zt_lo = (t == 0) ? -1.0f : z[(size_t)b_lo * Dd + (t - 1)];
        float zt_hi = (t == 0) ? -1.0f : z[(size_t)b_hi * Dd + (t - 1)];
        const float* gic_lo = gic + (size_t)b_lo * G3;
        const float* gic_hi = gic + (size_t)b_hi * G3;
        const float* hp_lo  = Hf_prev + (size_t)b_lo * Hh;
        const float* hp_hi  = Hf_prev + (size_t)b_hi * Hh;
#pragma unroll
        for (int nt = 0; nt < 4; nt++) {
            int jc = j0 + wn * 32 + nt * 8 + t4 * 2;
            float hlo[2], hhi[2];
#pragma unroll
            for (int cc = 0; cc < 2; cc++) {
                int j = jc + cc;
                float wzr = Wih[j], wzz = Wih[512 + j], wzn = Wih[1024 + j];
                float br  = bhh[j], bz  = bhh[512 + j], bn_ = bhh[1024 + j];
                {
                    float hr = acc[0][mt][nt][cc] + br;
                    float hz = acc[1][mt][nt][cc] + bz;
                    float hn = acc[2][mt][nt][cc] + bn_;
                    float r = fast_sig(fmaf(zt_lo, wzr, gic_lo[j]) + hr);
                    float u = fast_sig(fmaf(zt_lo, wzz, gic_lo[512 + j]) + hz);
                    float n = fast_tanh(fmaf(r, hn, fmaf(zt_lo, wzn, gic_lo[1024 + j])));
                    hlo[cc] = fmaf(u, hp_lo[j] - n, n);
                }
                {
                    float hr = acc[0][mt][nt][2 + cc] + br;
                    float hz = acc[1][mt][nt][2 + cc] + bz;
                    float hn = acc[2][mt][nt][2 + cc] + bn_;
                    float r = fast_sig(fmaf(zt_hi, wzr, gic_hi[j]) + hr);
                    float u = fast_sig(fmaf(zt_hi, wzz, gic_hi[512 + j]) + hz);
                    float n = fast_tanh(fmaf(r, hn, fmaf(zt_hi, wzn, gic_hi[1024 + j])));
                    hhi[cc] = fmaf(u, hp_hi[j] - n, n);
                }
            }
            *(float2*)(Hf_next + (size_t)b_lo * Hh + jc) = make_float2(hlo[0], hlo[1]);
            *(float2*)(Hf_next + (size_t)b_hi * Hh + jc) = make_float2(hhi[0], hhi[1]);
            *(__nv_bfloat162*)(Hbf_next + (size_t)b_lo * Hh + jc) = __floats2bfloat162_rn(hlo[0], hlo[1]);
            *(__nv_bfloat162*)(Hbf_next + (size_t)b_hi * Hh + jc) = __floats2bfloat162_rn(hhi[0], hhi[1]);
        }
    }
}

// ---------------- head GEMM (N=30) fused with mixture log-likelihood --------
__global__ __launch_bounds__(128)
void head_kernel(const float* __restrict__ W2, const float* __restrict__ b2,
                 const float* __restrict__ z)
{
    __shared__ float a2s[4][512];
    __shared__ float ps[4][32];
    int w = threadIdx.x >> 5, lane = threadIdx.x & 31;
    size_t r = (size_t)blockIdx.x * 4 + w;

    const float4* src = (const float4*)(g_A2 + r * HIDd);
#pragma unroll
    for (int i = 0; i < 4; i++) {
        float4 v = src[lane + 32 * i];
        *(float4*)&a2s[w][(lane + 32 * i) * 4] = v;
    }
    __syncwarp();

    if (lane < 30) {
        float acc = b2[lane];
#pragma unroll 8
        for (int k = 0; k < 512; k++)
            acc = fmaf(a2s[w][k], W2[k * 30 + lane], acc);
        ps[w][lane] = acc;
    }
    __syncwarp();

    if (lane == 0) {
        int t = (int)(r >> 12);
        int b = (int)(r & 4095);
        float zv = z[(size_t)b * Dd + t];
        float* p = ps[w];
        float m1 = -1e30f, m2 = -1e30f;
        float term[10];
#pragma unroll
        for (int k = 0; k < 10; k++) {
            float l = p[k], mu = p[10 + k], ls = p[20 + k];
            float d = (zv - mu) * expf(-ls);
            float tv = l - ls - 0.91893853320467274f - 0.5f * d * d;
            term[k] = tv;
            m1 = fmaxf(m1, tv);
            m2 = fmaxf(m2, l);
        }
        float s1 = 0.f, s2 = 0.f;
#pragma unroll
        for (int k = 0; k < 10; k++) {
            s1 += expf(term[k] - m1);
            s2 += expf(p[k] - m2);
        }
        g_ll[(size_t)b * Dd + t] = (m1 + logf(s1)) - (m2 + logf(s2));
    }
}

// ---------------- final: sort query desc (bitonic) + masked dot -------------
__global__ __launch_bounds__(128)
void final_kernel(const float* __restrict__ bb, const float* __restrict__ m,
                  float* __restrict__ out)
{
    __shared__ float s[128];
    __shared__ float red[128];
    int b = blockIdx.x, t = threadIdx.x;

    float q = -1.0f;
    if (t < Dd) {
        float bv = bb[(size_t)b * Dd + t];
        q = m[(size_t)b * Dd + t] * (1.0f - bv);
    }
    s[t] = q;
    __syncthreads();

    for (int k = 2; k <= 128; k <<= 1) {
        for (int j = k >> 1; j > 0; j >>= 1) {
            int ixj = t ^ j;
            if (ixj > t) {
                float a = s[t], c = s[ixj];
                bool up = ((t & k) == 0);
                if (up ? (a > c) : (a < c)) { s[t] = c; s[ixj] = a; }
            }
            __syncthreads();
        }
    }

    float prod = 0.f;
    if (t < Dd) prod = g_ll[(size_t)b * Dd + t] * s[127 - t];
    red[t] = prod;
    __syncthreads();
    for (int st = 64; st > 0; st >>= 1) {
        if (t < st) red[t] += red[t + st];
        __syncthreads();
    }
    if (t == 0) out[b] = red[0];
}

// ---------------- launch ----------------------------------------------------
extern "C" void kernel_launch(void* const* d_in, const int* in_sizes, int n_in,
                              void* d_out, int out_size)
{
    const float* z   = (const float*)d_in[0];
    const float* c   = (const float*)d_in[1];
    const float* bb  = (const float*)d_in[2];
    const float* m   = (const float*)d_in[3];
    const float* Wih = (const float*)d_in[4];
    const float* Whh = (const float*)d_in[5];
    const float* bih = (const float*)d_in[6];
    const float* bhh = (const float*)d_in[7];
    const float* W0  = (const float*)d_in[8];
    const float* b0  = (const float*)d_in[9];
    const float* W1  = (const float*)d_in[10];
    const float* b1  = (const float*)d_in[11];
    const float* W2  = (const float*)d_in[12];
    const float* b2  = (const float*)d_in[13];
    float* out = (float*)d_out;

    float *pConst, *pGic, *pMlpc, *pHf, *pA2;
    __nv_bfloat16 *pHbf, *pWhhT, *pW0T, *pW1T, *pA1bf;
    cudaGetSymbolAddress((void**)&pConst, g_const);
    cudaGetSymbolAddress((void**)&pGic,   g_gic);
    cudaGetSymbolAddress((void**)&pMlpc,  g_mlpc);
    cudaGetSymbolAddress((void**)&pHf,    g_Hf);
    cudaGetSymbolAddress((void**)&pHbf,   g_Hbf);
    cudaGetSymbolAddress((void**)&pWhhT,  g_WhhT);
    cudaGetSymbolAddress((void**)&pW0T,   g_W0T);
    cudaGetSymbolAddress((void**)&pW1T,   g_W1T);
    cudaGetSymbolAddress((void**)&pA1bf,  g_A1bf);
    cudaGetSymbolAddress((void**)&pA2,    g_A2);

    build_const_kernel<<<(Bn * CN + 255) / 256, 256>>>(c, bb, m);
    zero_h0_kernel<<<(Bn * Hh) / 256, 256>>>();

    dim3 cb(32, 8);
    convT_kernel<<<dim3(G3 / 32,  Hh / 32),  cb>>>(Whh, pWhhT, Hh, G3);
    convT_kernel<<<dim3(HIDd / 32, Hh / 32), cb>>>(W0,  pW0T,  Hh, HIDd);
    convT_kernel<<<dim3(HIDd / 32, HIDd / 32), cb>>>(W1, pW1T, HIDd, HIDd);

    // gi_const = const @ Wih[1:] + bih   (fp32/tf32 path)
    tgemm_kernel<<<dim3(G3 / 128, Bn / 128), 256>>>(pConst, Wih + G3, bih, pGic,
                                                    Bn, G3, CN);
    // mlp_const = const @ W0[H:] + b0
    tgemm_kernel<<<dim3(HIDd / 128, Bn / 128), 256>>>(pConst, W0 + (size_t)Hh * HIDd,
                                                      b0, pMlpc, Bn, HIDd, CN);
    // recurrence
    for (int t = 0; t < Dd; t++) {
        gru_fused_bf16<<<dim3(Hh / 64, Bn / 128), 256>>>(
            pHbf + (size_t)t * Bn * Hh, pHbf + (size_t)(t + 1) * Bn * Hh,
            pHf + (size_t)(t & 1) * Bn * Hh, pHf + (size_t)((t + 1) & 1) * Bn * Hh,
            pWhhT, Wih, bhh, pGic, z, t);
    }
    // batched MLP
    bgemm_mlp<0><<<dim3(HIDd / 128, TOTR / 128), 256>>>(pHbf + (size_t)Bn * Hh, pW0T,
                                                        pMlpc, pA1bf, TOTR);
    bgemm_mlp<1><<<dim3(HIDd / 128, TOTR / 128), 256>>>(pA1bf, pW1T, b1, pA2, TOTR);
    head_kernel<<<TOTR / 4, 128>>>(W2, b2, z);
    final_kernel<<<Bn, 128>>>(bb, m, out);
}

// round 7
// speedup vs baseline: 2.7948x; 1.0150x over previous
#include <cuda_runtime.h>
#include <cuda_bf16.h>
#include <math.h>
#include <stdint.h>

#define Bn   4096
#define Dd   112
#define NTd  200
#define Hh   512
#define HIDd 512
#define CN   536      /* 3*D + NT */
#define G3   1536     /* 3*H */
#define TOTR (Dd*Bn)  /* 458752 */
#define NCTA 128      /* persistent grid */

// ---------------- device scratch ---------------------------------------------
__device__ float g_const[(size_t)Bn * CN];
__device__ float g_gic  [(size_t)Bn * G3];
__device__ float g_mlpc [(size_t)Bn * HIDd];
__device__ float g_Hf   [2 * (size_t)Bn * Hh];                 // fp32 ping-pong
__device__ __nv_bfloat16 g_Hbf [(size_t)(Dd+1) * Bn * Hh];     // bf16 history
__device__ __nv_bfloat16 g_WhhT[(size_t)G3 * Hh];              // [n=1536][k=512]
__device__ __nv_bfloat16 g_W0T [(size_t)HIDd * Hh];
__device__ __nv_bfloat16 g_W1T [(size_t)HIDd * HIDd];
__device__ __nv_bfloat16 g_A1bf[(size_t)TOTR * HIDd];
__device__ float g_A2   [(size_t)TOTR * HIDd];
__device__ float g_ll   [(size_t)Bn * Dd];
__device__ unsigned g_bar_cnt;
__device__ unsigned g_bar_flag;

// ---------------- helpers ----------------------------------------------------
__device__ __forceinline__ float fast_sig(float x)  { return 1.f / (1.f + __expf(-x)); }
__device__ __forceinline__ float fast_tanh(float x) { return fmaf(2.f, 1.f / (1.f + __expf(-2.f * x)), -1.f); }

__device__ __forceinline__ uint32_t pack_bf16x2(float lo, float hi)
{
    uint32_t r;
    asm("cvt.rn.bf16x2.f32 %0, %1, %2;" : "=r"(r) : "f"(hi), "f"(lo));
    return r;
}
__device__ __forceinline__ uint32_t smem_u32(const void* p)
{
    uint32_t a;
    asm("{ .reg .u64 t; cvta.to.shared.u64 t, %1; cvt.u32.u64 %0, t; }" : "=r"(a) : "l"(p));
    return a;
}
__device__ __forceinline__ void cpa16_u(uint32_t dst, const void* src)
{
    asm volatile("cp.async.cg.shared.global [%0], [%1], 16;\n" :: "r"(dst), "l"(src));
}
__device__ __forceinline__ void cpa_commit() { asm volatile("cp.async.commit_group;\n"); }
template<int N>
__device__ __forceinline__ void cpa_wait()   { asm volatile("cp.async.wait_group %0;\n" :: "n"(N)); }

__device__ __forceinline__ uint32_t f2tf32(float x)
{
    uint32_t u;
    asm("cvt.rna.tf32.f32 %0, %1;" : "=r"(u) : "f"(x));
    return u;
}
__device__ __forceinline__ void mma_tf32(float* d, const uint32_t* a, const uint32_t* b)
{
    asm volatile(
        "mma.sync.aligned.m16n8k8.row.col.f32.tf32.tf32.f32 "
        "{%0,%1,%2,%3}, {%4,%5,%6,%7}, {%8,%9}, {%0,%1,%2,%3};\n"
        : "+f"(d[0]), "+f"(d[1]), "+f"(d[2]), "+f"(d[3])
        : "r"(a[0]), "r"(a[1]), "r"(a[2]), "r"(a[3]), "r"(b[0]), "r"(b[1]));
}
__device__ __forceinline__ void mma_bf16(float* d, const uint32_t* a, const uint32_t* b)
{
    asm volatile(
        "mma.sync.aligned.m16n8k16.row.col.f32.bf16.bf16.f32 "
        "{%0,%1,%2,%3}, {%4,%5,%6,%7}, {%8,%9}, {%0,%1,%2,%3};\n"
        : "+f"(d[0]), "+f"(d[1]), "+f"(d[2]), "+f"(d[3])
        : "r"(a[0]), "r"(a[1]), "r"(a[2]), "r"(a[3]), "r"(b[0]), "r"(b[1]));
}

// ---------------- small prep kernels -----------------------------------------
__global__ void build_const_kernel(const float* __restrict__ c,
                                   const float* __restrict__ bb,
                                   const float* __restrict__ m)
{
    size_t idx = (size_t)blockIdx.x * blockDim.x + threadIdx.x;
    if (idx >= (size_t)Bn * CN) return;
    int b = (int)(idx / CN);
    int i = (int)(idx % CN);
    float v;
    if (i < Dd + NTd)            v = c [(size_t)b * (Dd + NTd) + i];
    else if (i < Dd + NTd + Dd)  v = bb[(size_t)b * Dd + (i - (Dd + NTd))];
    else                         v = m [(size_t)b * Dd + (i - (Dd + NTd + Dd))];
    g_const[idx] = v;
}

__global__ void zero_h0_kernel()
{
    size_t idx = (size_t)blockIdx.x * blockDim.x + threadIdx.x;
    if (idx < (size_t)Bn * Hh) {
        g_Hf[idx] = 0.f;
        g_Hbf[idx] = __float2bfloat16(0.f);
    }
    if (idx == 0) { g_bar_cnt = 0; g_bar_flag = 0; }
}

__global__ void convT_kernel(const float* __restrict__ in, __nv_bfloat16* __restrict__ out,
                             int Krows, int Ncols)
{
    __shared__ float tile[32][33];
    int k0 = blockIdx.y * 32, n0 = blockIdx.x * 32;
    int tx = threadIdx.x, ty = threadIdx.y;
    for (int i = ty; i < 32; i += 8)
        tile[i][tx] = in[(size_t)(k0 + i) * Ncols + n0 + tx];
    __syncthreads();
    for (int i = ty; i < 32; i += 8)
        out[(size_t)(n0 + i) * Krows + k0 + tx] = __float2bfloat16(tile[tx][i]);
}

// ---------------- tf32 GEMM for K=536 precompute (fp32 in/out) ---------------
__global__ __launch_bounds__(256)
void tgemm_kernel(const float* __restrict__ A, const float* __restrict__ B,
                  const float* __restrict__ bias, float* __restrict__ C,
                  int M, int N, int K)
{
    __shared__ uint32_t As[128][12];
    __shared__ uint32_t Bs[8][136];

    const int tid  = threadIdx.x;
    const int wid  = tid >> 5;
    const int lane = tid & 31;
    const int gid  = lane >> 2;
    const int tig  = lane & 3;
    const int wm   = wid >> 2;
    const int wn   = wid & 3;
    const int row0 = blockIdx.y * 128;
    const int col0 = blockIdx.x * 128;

    float acc[4][4][4];
#pragma unroll
    for (int mt = 0; mt < 4; mt++)
#pragma unroll
        for (int nt = 0; nt < 4; nt++)
#pragma unroll
            for (int r = 0; r < 4; r++) acc[mt][nt][r] = 0.f;

    const int ar = tid >> 1;
    const int ak = (tid & 1) * 4;
    const int bk = tid >> 5;
    const int bn = (tid & 31) * 4;
    const int niter = K >> 3;

    const float* Ag = A + (size_t)(row0 + ar) * K + ak;
    const float* Bg = B + (size_t)bk * N + col0 + bn;

    float4 pa = *(const float4*)Ag;
    float4 pb = *(const float4*)Bg;

    for (int it = 0; it < niter; ++it) {
        As[ar][ak + 0] = f2tf32(pa.x); As[ar][ak + 1] = f2tf32(pa.y);
        As[ar][ak + 2] = f2tf32(pa.z); As[ar][ak + 3] = f2tf32(pa.w);
        Bs[bk][bn + 0] = f2tf32(pb.x); Bs[bk][bn + 1] = f2tf32(pb.y);
        Bs[bk][bn + 2] = f2tf32(pb.z); Bs[bk][bn + 3] = f2tf32(pb.w);
        __syncthreads();
        if (it + 1 < niter) {
            pa = *(const float4*)(Ag + (size_t)(it + 1) * 8);
            pb = *(const float4*)(Bg + (size_t)(it + 1) * 8 * N);
        }
        uint32_t af[4][4];
#pragma unroll
        for (int mt = 0; mt < 4; mt++) {
            int rb = wm * 64 + mt * 16 + gid;
            af[mt][0] = As[rb][tig];     af[mt][1] = As[rb + 8][tig];
            af[mt][2] = As[rb][tig + 4]; af[mt][3] = As[rb + 8][tig + 4];
        }
        uint32_t bf[4][2];
#pragma unroll
        for (int nt = 0; nt < 4; nt++) {
            int cb = wn * 32 + nt * 8 + gid;
            bf[nt][0] = Bs[tig][cb]; bf[nt][1] = Bs[tig + 4][cb];
        }
#pragma unroll
        for (int mt = 0; mt < 4; mt++)
#pragma unroll
            for (int nt = 0; nt < 4; nt++)
                mma_tf32(acc[mt][nt], af[mt], bf[nt]);
        __syncthreads();
    }
#pragma unroll
    for (int mt = 0; mt < 4; mt++) {
        int row_lo = row0 + wm * 64 + mt * 16 + gid;
        int row_hi = row_lo + 8;
#pragma unroll
        for (int nt = 0; nt < 4; nt++) {
            int col = col0 + wn * 32 + nt * 8 + tig * 2;
            float b0 = bias[col], b1 = bias[col + 1];
            *(float2*)(C + (size_t)row_lo * N + col) =
                make_float2(acc[mt][nt][0] + b0, acc[mt][nt][1] + b1);
            *(float2*)(C + (size_t)row_hi * N + col) =
                make_float2(acc[mt][nt][2] + b0, acc[mt][nt][3] + b1);
        }
    }
}

// ============ PERSISTENT weight-stationary GRU recurrence ====================
// 128 CTAs, 1/SM. CTA c: batch rows [ (c>>3)*256 , +256 ), j cols [ (c&7)*64, +64 ).
// smem: A double-buffer [2][128][20] u32 (20480 B) + resident WhhT slice
// [192 rows][260 u32] (199680 B) = 220160 B total.
__global__ __launch_bounds__(256, 1)
void gru_persist(const __nv_bfloat16* __restrict__ Hbf,
                 float* __restrict__ Hf,
                 const __nv_bfloat16* __restrict__ WhhT,
                 const float* __restrict__ Wih,
                 const float* __restrict__ bhh,
                 const float* __restrict__ gic,
                 const float* __restrict__ z)
{
    extern __shared__ uint32_t sm[];
    const int tid  = threadIdx.x;
    const int wid  = tid >> 5;
    const int lane = tid & 31;
    const int gid  = lane >> 2;
    const int t4   = lane & 3;
    const int wm   = wid >> 1;           // 0..3 : 32-row slice of 128
    const int wn   = wid & 1;            // 0..1 : 32-col slice of 64
    const int jb   = blockIdx.x & 7;
    const int mb   = blockIdx.x >> 3;
    uint32_t su = smem_u32(sm);
    const uint32_t BW = 5120;            // B region start (u32 words)

    // ---- load resident Whh slice: [3 gates][64 n][512 k] bf16, stride 260 u32
    for (int i = tid; i < 12288; i += 256) {
        int n_row = i >> 6;              // 0..191
        int k4    = (i & 63) << 2;       // u32 offset 0..252
        int g = n_row >> 6, n = n_row & 63;
        cpa16_u(su + (BW + (uint32_t)n_row * 260u + (uint32_t)k4) * 4u,
                WhhT + ((size_t)(g * 512 + jb * 64 + n)) * 512 + k4 * 2);
    }
    cpa_commit(); cpa_wait<0>(); __syncthreads();

    const int ar  = tid >> 1;            // A-loader row 0..127
    const int ac4 = (tid & 1) * 8;       // A-loader u32 offset 0/8

#define LOADA(s, kc)                                                            \
    do {                                                                        \
        cpa16_u(su + ((uint32_t)(s) * 2560u + (uint32_t)ar * 20u + ac4) * 4u,   \
                Ag + (size_t)ar * 512 + (kc) * 32 + ac4 * 2);                   \
        cpa16_u(su + ((uint32_t)(s) * 2560u + (uint32_t)ar * 20u + ac4 + 4) * 4u, \
                Ag + (size_t)ar * 512 + (kc) * 32 + ac4 * 2 + 8);               \
        cpa_commit();                                                           \
    } while (0)

    for (int t = 0; t < Dd; t++) {
        const __nv_bfloat16* Abase = Hbf + (size_t)t * Bn * Hh + (size_t)mb * 256 * 512;
        const float* Hfp = Hf + (size_t)(t & 1) * Bn * Hh;
        float* Hfn       = Hf + (size_t)((t + 1) & 1) * Bn * Hh;
        __nv_bfloat16* Hbn = (__nv_bfloat16*)(Hbf + (size_t)(t + 1) * Bn * Hh);

        for (int mh = 0; mh < 2; mh++) {
            const __nv_bfloat16* Ag = Abase + (size_t)mh * 128 * 512;

            float acc[3][2][4][4];
#pragma unroll
            for (int g = 0; g < 3; g++)
#pragma unroll
                for (int mt = 0; mt < 2; mt++)
#pragma unroll
                    for (int nt = 0; nt < 4; nt++)
#pragma unroll
                        for (int r = 0; r < 4; r++) acc[g][mt][nt][r] = 0.f;

            LOADA(0, 0);
            LOADA(1, 1);

            for (int kc = 0; kc < 16; kc++) {
                const int s = kc & 1;
                if (kc < 15) cpa_wait<1>(); else cpa_wait<0>();
                __syncthreads();
#pragma unroll
                for (int kb = 0; kb < 16; kb += 8) {
                    uint32_t af[2][4];
#pragma unroll
                    for (int mt = 0; mt < 2; mt++) {
                        int r = wm * 32 + mt * 16 + gid;
                        uint32_t base = (uint32_t)s * 2560u + (uint32_t)r * 20u + kb + t4;
                        af[mt][0] = sm[base];
                        af[mt][1] = sm[base + 160];        // +8 rows * 20
                        af[mt][2] = sm[base + 4];
                        af[mt][3] = sm[base + 164];
                    }
#pragma unroll
                    for (int g = 0; g < 3; g++)
#pragma unroll
                        for (int nt = 0; nt < 4; nt++) {
                            int nrow = g * 64 + wn * 32 + nt * 8 + gid;
                            uint32_t bbase = BW + (uint32_t)nrow * 260u + (uint32_t)kc * 16u + kb + t4;
                            uint32_t bf[2];
                            bf[0] = sm[bbase];
                            bf[1] = sm[bbase + 4];
#pragma unroll
                            for (int mt = 0; mt < 2; mt++)
                                mma_bf16(acc[g][mt][nt], af[mt], bf);
                        }
                }
                __syncthreads();
                if (kc + 2 < 16) LOADA(s, kc + 2);
            }

            // ---- epilogue for this 128-row half --------------------------------
#pragma unroll
            for (int mt = 0; mt < 2; mt++) {
                int b_lo = mb * 256 + mh * 128 + wm * 32 + mt * 16 + gid;
                int b_hi = b_lo + 8;
                float zt_lo = (t == 0) ? -1.0f : z[(size_t)b_lo * Dd + (t - 1)];
                float zt_hi = (t == 0) ? -1.0f : z[(size_t)b_hi * Dd + (t - 1)];
                const float* gic_lo = gic + (size_t)b_lo * G3;
                const float* gic_hi = gic + (size_t)b_hi * G3;
                const float* hp_lo  = Hfp + (size_t)b_lo * Hh;
                const float* hp_hi  = Hfp + (size_t)b_hi * Hh;
#pragma unroll
                for (int nt = 0; nt < 4; nt++) {
                    int jc = jb * 64 + wn * 32 + nt * 8 + t4 * 2;
                    float hlo[2], hhi[2];
#pragma unroll
                    for (int cc = 0; cc < 2; cc++) {
                        int j = jc + cc;
                        float wzr = Wih[j], wzz = Wih[512 + j], wzn = Wih[1024 + j];
                        float br  = bhh[j], bz  = bhh[512 + j], bn_ = bhh[1024 + j];
                        {
                            float hr = acc[0][mt][nt][cc] + br;
                            float hz = acc[1][mt][nt][cc] + bz;
                            float hn = acc[2][mt][nt][cc] + bn_;
                            float r = fast_sig(fmaf(zt_lo, wzr, gic_lo[j]) + hr);
                            float u = fast_sig(fmaf(zt_lo, wzz, gic_lo[512 + j]) + hz);
                            float n = fast_tanh(fmaf(r, hn, fmaf(zt_lo, wzn, gic_lo[1024 + j])));
                            hlo[cc] = fmaf(u, hp_lo[j] - n, n);
                        }
                        {
                            float hr = acc[0][mt][nt][2 + cc] + br;
                            float hz = acc[1][mt][nt][2 + cc] + bz;
                            float hn = acc[2][mt][nt][2 + cc] + bn_;
                            float r = fast_sig(fmaf(zt_hi, wzr, gic_hi[j]) + hr);
                            float u = fast_sig(fmaf(zt_hi, wzz, gic_hi[512 + j]) + hz);
                            float n = fast_tanh(fmaf(r, hn, fmaf(zt_hi, wzn, gic_hi[1024 + j])));
                            hhi[cc] = fmaf(u, hp_hi[j] - n, n);
                        }
                    }
                    *(float2*)(Hfn + (size_t)b_lo * Hh + jc) = make_float2(hlo[0], hlo[1]);
                    *(float2*)(Hfn + (size_t)b_hi * Hh + jc) = make_float2(hhi[0], hhi[1]);
                    *(uint32_t*)(Hbn + (size_t)b_lo * Hh + jc) = pack_bf16x2(hlo[0], hlo[1]);
                    *(uint32_t*)(Hbn + (size_t)b_hi * Hh + jc) = pack_bf16x2(hhi[0], hhi[1]);
                }
            }
        }

        // ---- grid-wide barrier (publish h_{t+1}) -------------------------------
        __threadfence();
        __syncthreads();
        if (tid == 0) {
            unsigned v = atomicAdd(&g_bar_cnt, 1u);
            if (v == NCTA - 1) {
                g_bar_cnt = 0;
                __threadfence();
                atomicExch(&g_bar_flag, (unsigned)(t + 1));
            } else {
                while (atomicAdd(&g_bar_flag, 0u) < (unsigned)(t + 1)) { }
            }
        }
        __syncthreads();
    }
#undef LOADA
}

// ============ bf16 MLP GEMM (A bf16 [M][512], BT bf16 [512][512]) ============
// MODE 0: bf16 out = tanh(v + mlpc[row&4095][col]) ; MODE 1: f32 out = tanh(v + bias[col])
template<int MODE>
__global__ __launch_bounds__(256)
void bgemm_mlp(const __nv_bfloat16* __restrict__ A, const __nv_bfloat16* __restrict__ BT,
               const float* __restrict__ bias, void* __restrict__ Cout, int M)
{
    const int K = 512, N = 512;
    __shared__ uint32_t As[2][128][20];
    __shared__ uint32_t Bs[2][128][20];

    const int tid  = threadIdx.x;
    const int wid  = tid >> 5;
    const int lane = tid & 31;
    const int g    = lane >> 2;
    const int t    = lane & 3;
    const int wm   = wid >> 2;
    const int wn   = wid & 3;

    const int row0 = blockIdx.y * 128;
    const int col0 = blockIdx.x * 128;

    float acc[4][4][4];
#pragma unroll
    for (int mt = 0; mt < 4; mt++)
#pragma unroll
        for (int nt = 0; nt < 4; nt++)
#pragma unroll
            for (int r = 0; r < 4; r++) acc[mt][nt][r] = 0.f;

    const int lr = tid >> 1;
    const int lc = (tid & 1) * 2;

#define LOAD_STAGE(s, kt)                                                        \
    do {                                                                         \
        cpa16_u(smem_u32(&As[s][lr][lc * 4]),                                    \
                A  + (size_t)(row0 + lr) * K + (kt) * 32 + lc * 8);              \
        cpa16_u(smem_u32(&As[s][lr][(lc + 1) * 4]),                              \
                A  + (size_t)(row0 + lr) * K + (kt) * 32 + (lc + 1) * 8);        \
        cpa16_u(smem_u32(&Bs[s][lr][lc * 4]),                                    \
                BT + (size_t)(col0 + lr) * K + (kt) * 32 + lc * 8);              \
        cpa16_u(smem_u32(&Bs[s][lr][(lc + 1) * 4]),                              \
                BT + (size_t)(col0 + lr) * K + (kt) * 32 + (lc + 1) * 8);        \
        cpa_commit();                                                            \
    } while (0)

    LOAD_STAGE(0, 0);
    LOAD_STAGE(1, 1);

    const int nk = K / 32;
    for (int kt = 0; kt < nk; ++kt) {
        const int s = kt & 1;
        cpa_wait<1>();
        __syncthreads();
#pragma unroll
        for (int kb = 0; kb < 16; kb += 8) {
            uint32_t af[4][4];
#pragma unroll
            for (int mt = 0; mt < 4; mt++) {
                int r = wm * 64 + mt * 16 + g;
                af[mt][0] = As[s][r][kb + t];     af[mt][1] = As[s][r + 8][kb + t];
                af[mt][2] = As[s][r][kb + t + 4]; af[mt][3] = As[s][r + 8][kb + t + 4];
            }
#pragma unroll
            for (int nt = 0; nt < 4; nt++) {
                int n = wn * 32 + nt * 8 + g;
                uint32_t bf[2];
                bf[0] = Bs[s][n][kb + t];
                bf[1] = Bs[s][n][kb + t + 4];
#pragma unroll
                for (int mt = 0; mt < 4; mt++)
                    mma_bf16(acc[mt][nt], af[mt], bf);
            }
        }
        __syncthreads();
        if (kt + 2 < nk) LOAD_STAGE(s, kt + 2);
    }
#undef LOAD_STAGE

#pragma unroll
    for (int mt = 0; mt < 4; mt++) {
        int row_lo = row0 + wm * 64 + mt * 16 + g;
        int row_hi = row_lo + 8;
#pragma unroll
        for (int nt = 0; nt < 4; nt++) {
            int col = col0 + wn * 32 + nt * 8 + t * 2;
            float v0 = acc[mt][nt][0], v1 = acc[mt][nt][1];
            float v2 = acc[mt][nt][2], v3 = acc[mt][nt][3];
            if (MODE == 0) {
                const float* blo = bias + (size_t)(row_lo & (Bn - 1)) * HIDd + col;
                const float* bhi = bias + (size_t)(row_hi & (Bn - 1)) * HIDd + col;
                v0 = fast_tanh(v0 + blo[0]); v1 = fast_tanh(v1 + blo[1]);
                v2 = fast_tanh(v2 + bhi[0]); v3 = fast_tanh(v3 + bhi[1]);
                __nv_bfloat16* C = (__nv_bfloat16*)Cout;
                *(uint32_t*)(C + (size_t)row_lo * N + col) = pack_bf16x2(v0, v1);
                *(uint32_t*)(C + (size_t)row_hi * N + col) = pack_bf16x2(v2, v3);
            } else {
                float b0 = bias[col], b1 = bias[col + 1];
                v0 = fast_tanh(v0 + b0); v1 = fast_tanh(v1 + b1);
                v2 = fast_tanh(v2 + b0); v3 = fast_tanh(v3 + b1);
                float* C = (float*)Cout;
                *(float2*)(C + (size_t)row_lo * N + col) = make_float2(v0, v1);
                *(float2*)(C + (size_t)row_hi * N + col) = make_float2(v2, v3);
            }
        }
    }
}

// ---------------- head GEMM (N=30) fused with mixture log-likelihood --------
__global__ __launch_bounds__(128)
void head_kernel(const float* __restrict__ W2, const float* __restrict__ b2,
                 const float* __restrict__ z)
{
    __shared__ float a2s[4][512];
    __shared__ float ps[4][32];
    int w = threadIdx.x >> 5, lane = threadIdx.x & 31;
    size_t r = (size_t)blockIdx.x * 4 + w;

    const float4* src = (const float4*)(g_A2 + r * HIDd);
#pragma unroll
    for (int i = 0; i < 4; i++) {
        float4 v = src[lane + 32 * i];
        *(float4*)&a2s[w][(lane + 32 * i) * 4] = v;
    }
    __syncwarp();

    if (lane < 30) {
        float acc = b2[lane];
#pragma unroll 8
        for (int k = 0; k < 512; k++)
            acc = fmaf(a2s[w][k], W2[k * 30 + lane], acc);
        ps[w][lane] = acc;
    }
    __syncwarp();

    if (lane == 0) {
        int t = (int)(r >> 12);
        int b = (int)(r & 4095);
        float zv = z[(size_t)b * Dd + t];
        float* p = ps[w];
        float m1 = -1e30f, m2 = -1e30f;
        float term[10];
#pragma unroll
        for (int k = 0; k < 10; k++) {
            float l = p[k], mu = p[10 + k], ls = p[20 + k];
            float d = (zv - mu) * expf(-ls);
            float tv = l - ls - 0.91893853320467274f - 0.5f * d * d;
            term[k] = tv;
            m1 = fmaxf(m1, tv);
            m2 = fmaxf(m2, l);
        }
        float s1 = 0.f, s2 = 0.f;
#pragma unroll
        for (int k = 0; k < 10; k++) {
            s1 += expf(term[k] - m1);
            s2 += expf(p[k] - m2);
        }
        g_ll[(size_t)b * Dd + t] = (m1 + logf(s1)) - (m2 + logf(s2));
    }
}

// ---------------- final: sort query desc (bitonic) + masked dot -------------
__global__ __launch_bounds__(128)
void final_kernel(const float* __restrict__ bb, const float* __restrict__ m,
                  float* __restrict__ out)
{
    __shared__ float s[128];
    __shared__ float red[128];
    int b = blockIdx.x, t = threadIdx.x;

    float q = -1.0f;
    if (t < Dd) {
        float bv = bb[(size_t)b * Dd + t];
        q = m[(size_t)b * Dd + t] * (1.0f - bv);
    }
    s[t] = q;
    __syncthreads();

    for (int k = 2; k <= 128; k <<= 1) {
        for (int j = k >> 1; j > 0; j >>= 1) {
            int ixj = t ^ j;
            if (ixj > t) {
                float a = s[t], c = s[ixj];
                bool up = ((t & k) == 0);
                if (up ? (a > c) : (a < c)) { s[t] = c; s[ixj] = a; }
            }
            __syncthreads();
        }
    }

    float prod = 0.f;
    if (t < Dd) prod = g_ll[(size_t)b * Dd + t] * s[127 - t];
    red[t] = prod;
    __syncthreads();
    for (int st = 64; st > 0; st >>= 1) {
        if (t < st) red[t] += red[t + st];
        __syncthreads();
    }
    if (t == 0) out[b] = red[0];
}

// ---------------- launch ----------------------------------------------------
extern "C" void kernel_launch(void* const* d_in, const int* in_sizes, int n_in,
                              void* d_out, int out_size)
{
    const float* z   = (const float*)d_in[0];
    const float* c   = (const float*)d_in[1];
    const float* bb  = (const float*)d_in[2];
    const float* m   = (const float*)d_in[3];
    const float* Wih = (const float*)d_in[4];
    const float* Whh = (const float*)d_in[5];
    const float* bih = (const float*)d_in[6];
    const float* bhh = (const float*)d_in[7];
    const float* W0  = (const float*)d_in[8];
    const float* b0  = (const float*)d_in[9];
    const float* W1  = (const float*)d_in[10];
    const float* b1  = (const float*)d_in[11];
    const float* W2  = (const float*)d_in[12];
    const float* b2  = (const float*)d_in[13];
    float* out = (float*)d_out;

    float *pConst, *pGic, *pMlpc, *pHf, *pA2;
    __nv_bfloat16 *pHbf, *pWhhT, *pW0T, *pW1T, *pA1bf;
    cudaGetSymbolAddress((void**)&pConst, g_const);
    cudaGetSymbolAddress((void**)&pGic,   g_gic);
    cudaGetSymbolAddress((void**)&pMlpc,  g_mlpc);
    cudaGetSymbolAddress((void**)&pHf,    g_Hf);
    cudaGetSymbolAddress((void**)&pHbf,   g_Hbf);
    cudaGetSymbolAddress((void**)&pWhhT,  g_WhhT);
    cudaGetSymbolAddress((void**)&pW0T,   g_W0T);
    cudaGetSymbolAddress((void**)&pW1T,   g_W1T);
    cudaGetSymbolAddress((void**)&pA1bf,  g_A1bf);
    cudaGetSymbolAddress((void**)&pA2,    g_A2);

    static int attr_done = 0;
    if (!attr_done) {
        cudaFuncSetAttribute(gru_persist, cudaFuncAttributeMaxDynamicSharedMemorySize, 220160);
        attr_done = 1;
    }

    build_const_kernel<<<(Bn * CN + 255) / 256, 256>>>(c, bb, m);
    zero_h0_kernel<<<(Bn * Hh) / 256, 256>>>();

    dim3 cb(32, 8);
    convT_kernel<<<dim3(G3 / 32,  Hh / 32),  cb>>>(Whh, pWhhT, Hh, G3);
    convT_kernel<<<dim3(HIDd / 32, Hh / 32), cb>>>(W0,  pW0T,  Hh, HIDd);
    convT_kernel<<<dim3(HIDd / 32, HIDd / 32), cb>>>(W1, pW1T, HIDd, HIDd);

    // gi_const = const @ Wih[1:] + bih   (tf32 path, K=536)
    tgemm_kernel<<<dim3(G3 / 128, Bn / 128), 256>>>(pConst, Wih + G3, bih, pGic,
                                                    Bn, G3, CN);
    // mlp_const = const @ W0[H:] + b0
    tgemm_kernel<<<dim3(HIDd / 128, Bn / 128), 256>>>(pConst, W0 + (size_t)Hh * HIDd,
                                                      b0, pMlpc, Bn, HIDd, CN);
    // recurrence: ONE persistent launch for all 112 steps
    gru_persist<<<NCTA, 256, 220160>>>(pHbf, pHf, pWhhT, Wih, bhh, pGic, z);

    // batched MLP
    bgemm_mlp<0><<<dim3(HIDd / 128, TOTR / 128), 256>>>(pHbf + (size_t)Bn * Hh, pW0T,
                                                        pMlpc, pA1bf, TOTR);
    bgemm_mlp<1><<<dim3(HIDd / 128, TOTR / 128), 256>>>(pA1bf, pW1T, b1, pA2, TOTR);
    head_kernel<<<TOTR / 4, 128>>>(W2, b2, z);
    final_kernel<<<Bn, 128>>>(bb, m, out);
}

// round 8
// speedup vs baseline: 3.7614x; 1.3459x over previous
#include <cuda_runtime.h>
#include <cuda_bf16.h>
#include <math.h>
#include <stdint.h>

#define Bn   4096
#define Dd   112
#define NTd  200
#define Hh   512
#define HIDd 512
#define CN   536      /* 3*D + NT */
#define G3   1536     /* 3*H */
#define TOTR (Dd*Bn)  /* 458752 */
#define NCTA 128      /* persistent grid */

// ---------------- device scratch ---------------------------------------------
__device__ float g_const[(size_t)Bn * CN];
__device__ float g_gic  [(size_t)Bn * G3];
__device__ float4 g_gic4[(size_t)Bn * Hh];     // {gic_r+bhh_r, gic_z+bhh_z, gic_n, bhh_n}
__device__ float4 g_wz4 [Hh];                  // {wz_r, wz_z, wz_n, 0}
__device__ float g_mlpc [(size_t)Bn * HIDd];
__device__ float g_Hf   [2 * (size_t)Bn * Hh];
__device__ __nv_bfloat16 g_Hbf [(size_t)(Dd+1) * Bn * Hh];
__device__ __nv_bfloat16 g_WhhT[(size_t)G3 * Hh];
__device__ __nv_bfloat16 g_W0T [(size_t)HIDd * Hh];
__device__ __nv_bfloat16 g_W1T [(size_t)HIDd * HIDd];
__device__ __nv_bfloat16 g_A1bf[(size_t)TOTR * HIDd];
__device__ float g_A2   [(size_t)TOTR * HIDd];
__device__ float g_ll   [(size_t)Bn * Dd];
__device__ unsigned g_bar_cnt;
__device__ unsigned g_bar_flag;

// ---------------- helpers ----------------------------------------------------
__device__ __forceinline__ float fast_sig(float x)  { return 1.f / (1.f + __expf(-x)); }
__device__ __forceinline__ float fast_tanh(float x) { return fmaf(2.f, 1.f / (1.f + __expf(-2.f * x)), -1.f); }

__device__ __forceinline__ uint32_t pack_bf16x2(float lo, float hi)
{
    uint32_t r;
    asm("cvt.rn.bf16x2.f32 %0, %1, %2;" : "=r"(r) : "f"(hi), "f"(lo));
    return r;
}
__device__ __forceinline__ uint32_t smem_u32(const void* p)
{
    uint32_t a;
    asm("{ .reg .u64 t; cvta.to.shared.u64 t, %1; cvt.u32.u64 %0, t; }" : "=r"(a) : "l"(p));
    return a;
}
__device__ __forceinline__ void cpa16_u(uint32_t dst, const void* src)
{
    asm volatile("cp.async.cg.shared.global [%0], [%1], 16;\n" :: "r"(dst), "l"(src));
}
__device__ __forceinline__ void cpa_commit() { asm volatile("cp.async.commit_group;\n"); }
template<int N>
__device__ __forceinline__ void cpa_wait()   { asm volatile("cp.async.wait_group %0;\n" :: "n"(N)); }

__device__ __forceinline__ uint32_t f2tf32(float x)
{
    uint32_t u;
    asm("cvt.rna.tf32.f32 %0, %1;" : "=r"(u) : "f"(x));
    return u;
}
__device__ __forceinline__ void mma_tf32(float* d, const uint32_t* a, const uint32_t* b)
{
    asm volatile(
        "mma.sync.aligned.m16n8k8.row.col.f32.tf32.tf32.f32 "
        "{%0,%1,%2,%3}, {%4,%5,%6,%7}, {%8,%9}, {%0,%1,%2,%3};\n"
        : "+f"(d[0]), "+f"(d[1]), "+f"(d[2]), "+f"(d[3])
        : "r"(a[0]), "r"(a[1]), "r"(a[2]), "r"(a[3]), "r"(b[0]), "r"(b[1]));
}
__device__ __forceinline__ void mma_bf16(float* d, const uint32_t* a, const uint32_t* b)
{
    asm volatile(
        "mma.sync.aligned.m16n8k16.row.col.f32.bf16.bf16.f32 "
        "{%0,%1,%2,%3}, {%4,%5,%6,%7}, {%8,%9}, {%0,%1,%2,%3};\n"
        : "+f"(d[0]), "+f"(d[1]), "+f"(d[2]), "+f"(d[3])
        : "r"(a[0]), "r"(a[1]), "r"(a[2]), "r"(a[3]), "r"(b[0]), "r"(b[1]));
}

// ---------------- merged prep kernel -----------------------------------------
__global__ void prep_kernel(const float* __restrict__ c,
                            const float* __restrict__ bb,
                            const float* __restrict__ m,
                            const float* __restrict__ Wih)
{
    size_t idx = (size_t)blockIdx.x * blockDim.x + threadIdx.x;
    const size_t R1 = (size_t)Bn * CN;
    const size_t R2 = R1 + (size_t)Bn * Hh;
    if (idx < R1) {
        int b = (int)(idx / CN);
        int i = (int)(idx % CN);
        float v;
        if (i < Dd + NTd)            v = c [(size_t)b * (Dd + NTd) + i];
        else if (i < Dd + NTd + Dd)  v = bb[(size_t)b * Dd + (i - (Dd + NTd))];
        else                         v = m [(size_t)b * Dd + (i - (Dd + NTd + Dd))];
        g_const[idx] = v;
    } else if (idx < R2) {
        size_t i2 = idx - R1;
        g_Hf[i2] = 0.f;
        g_Hbf[i2] = __float2bfloat16(0.f);
    } else if (idx < R2 + Hh) {
        int j = (int)(idx - R2);
        g_wz4[j] = make_float4(Wih[j], Wih[512 + j], Wih[1024 + j], 0.f);
        if (j == 0) { g_bar_cnt = 0; g_bar_flag = 0; }
    }
}

// pack gic4 after tgemm produced g_gic
__global__ void gic4_pack_kernel(const float* __restrict__ bhh)
{
    size_t idx = (size_t)blockIdx.x * blockDim.x + threadIdx.x;
    if (idx >= (size_t)Bn * Hh) return;
    int b = (int)(idx >> 9);
    int j = (int)(idx & 511);
    const float* g = g_gic + (size_t)b * G3;
    g_gic4[idx] = make_float4(g[j] + bhh[j],
                              g[512 + j] + bhh[512 + j],
                              g[1024 + j],
                              bhh[1024 + j]);
}

// merged transpose+convert (z selects matrix)
__global__ void convT3_kernel(const float* __restrict__ Whh,
                              const float* __restrict__ W0,
                              const float* __restrict__ W1)
{
    __shared__ float tile[32][33];
    const float* in;
    __nv_bfloat16* out;
    int Krows = 512, Ncols;
    if (blockIdx.z == 0)      { in = Whh; out = g_WhhT; Ncols = G3; }
    else if (blockIdx.z == 1) { in = W0;  out = g_W0T;  Ncols = HIDd; }
    else                      { in = W1;  out = g_W1T;  Ncols = HIDd; }
    int n0 = blockIdx.x * 32;
    if (n0 >= Ncols) return;
    int k0 = blockIdx.y * 32;
    int tx = threadIdx.x, ty = threadIdx.y;
    for (int i = ty; i < 32; i += 8)
        tile[i][tx] = in[(size_t)(k0 + i) * Ncols + n0 + tx];
    __syncthreads();
    for (int i = ty; i < 32; i += 8)
        out[(size_t)(n0 + i) * Krows + k0 + tx] = __float2bfloat16(tile[tx][i]);
}

// ---------------- tf32 GEMM for K=536 precompute (fp32 in/out) ---------------
__global__ __launch_bounds__(256)
void tgemm_kernel(const float* __restrict__ A, const float* __restrict__ B,
                  const float* __restrict__ bias, float* __restrict__ C,
                  int M, int N, int K)
{
    __shared__ uint32_t As[128][12];
    __shared__ uint32_t Bs[8][136];

    const int tid  = threadIdx.x;
    const int wid  = tid >> 5;
    const int lane = tid & 31;
    const int gid  = lane >> 2;
    const int tig  = lane & 3;
    const int wm   = wid >> 2;
    const int wn   = wid & 3;
    const int row0 = blockIdx.y * 128;
    const int col0 = blockIdx.x * 128;

    float acc[4][4][4];
#pragma unroll
    for (int mt = 0; mt < 4; mt++)
#pragma unroll
        for (int nt = 0; nt < 4; nt++)
#pragma unroll
            for (int r = 0; r < 4; r++) acc[mt][nt][r] = 0.f;

    const int ar = tid >> 1;
    const int ak = (tid & 1) * 4;
    const int bk = tid >> 5;
    const int bn = (tid & 31) * 4;
    const int niter = K >> 3;

    const float* Ag = A + (size_t)(row0 + ar) * K + ak;
    const float* Bg = B + (size_t)bk * N + col0 + bn;

    float4 pa = *(const float4*)Ag;
    float4 pb = *(const float4*)Bg;

    for (int it = 0; it < niter; ++it) {
        As[ar][ak + 0] = f2tf32(pa.x); As[ar][ak + 1] = f2tf32(pa.y);
        As[ar][ak + 2] = f2tf32(pa.z); As[ar][ak + 3] = f2tf32(pa.w);
        Bs[bk][bn + 0] = f2tf32(pb.x); Bs[bk][bn + 1] = f2tf32(pb.y);
        Bs[bk][bn + 2] = f2tf32(pb.z); Bs[bk][bn + 3] = f2tf32(pb.w);
        __syncthreads();
        if (it + 1 < niter) {
            pa = *(const float4*)(Ag + (size_t)(it + 1) * 8);
            pb = *(const float4*)(Bg + (size_t)(it + 1) * 8 * N);
        }
        uint32_t af[4][4];
#pragma unroll
        for (int mt = 0; mt < 4; mt++) {
            int rb = wm * 64 + mt * 16 + gid;
            af[mt][0] = As[rb][tig];     af[mt][1] = As[rb + 8][tig];
            af[mt][2] = As[rb][tig + 4]; af[mt][3] = As[rb + 8][tig + 4];
        }
        uint32_t bf[4][2];
#pragma unroll
        for (int nt = 0; nt < 4; nt++) {
            int cb = wn * 32 + nt * 8 + gid;
            bf[nt][0] = Bs[tig][cb]; bf[nt][1] = Bs[tig + 4][cb];
        }
#pragma unroll
        for (int mt = 0; mt < 4; mt++)
#pragma unroll
            for (int nt = 0; nt < 4; nt++)
                mma_tf32(acc[mt][nt], af[mt], bf[nt]);
        __syncthreads();
    }
#pragma unroll
    for (int mt = 0; mt < 4; mt++) {
        int row_lo = row0 + wm * 64 + mt * 16 + gid;
        int row_hi = row_lo + 8;
#pragma unroll
        for (int nt = 0; nt < 4; nt++) {
            int col = col0 + wn * 32 + nt * 8 + tig * 2;
            float b0 = bias[col], b1 = bias[col + 1];
            *(float2*)(C + (size_t)row_lo * N + col) =
                make_float2(acc[mt][nt][0] + b0, acc[mt][nt][1] + b1);
            *(float2*)(C + (size_t)row_hi * N + col) =
                make_float2(acc[mt][nt][2] + b0, acc[mt][nt][3] + b1);
        }
    }
}

// ============ PERSISTENT weight-stationary GRU recurrence (512 thr) ==========
// 128 CTAs. CTA c: batch rows [(c>>3)*256, +256), j cols [(c&7)*64, +64).
// smem: A triple-buffer 3*2560 u32 (30720 B) + resident WhhT slice
// [192 rows][260 u32] (199680 B) = 230400 B.
__global__ __launch_bounds__(512, 1)
void gru_persist(const __nv_bfloat16* __restrict__ Hbf,
                 float* __restrict__ Hf,
                 const __nv_bfloat16* __restrict__ WhhT,
                 const float* __restrict__ z)
{
    extern __shared__ uint32_t sm[];
    const int tid  = threadIdx.x;
    const int wid  = tid >> 5;          // 0..15
    const int lane = tid & 31;
    const int gid  = lane >> 2;
    const int t4   = lane & 3;
    const int wm   = wid >> 1;          // 0..7 : 16-row slice
    const int wn   = wid & 1;           // 0..1 : 32-col slice
    const int jb   = blockIdx.x & 7;
    const int mb   = blockIdx.x >> 3;
    uint32_t su = smem_u32(sm);
    const uint32_t BW = 7680;           // B region start (u32 words)

    // resident Whh slice: [3 gates][64 n][512 k] bf16, row stride 260 u32
    for (int i = tid; i < 12288; i += 512) {
        int n_row = i >> 6;
        int c16   = i & 63;             // 16B chunk within row
        int g = n_row >> 6, n = n_row & 63;
        cpa16_u(su + (BW + (uint32_t)n_row * 260u + (uint32_t)c16 * 4u) * 4u,
                WhhT + ((size_t)(g * 512 + jb * 64 + n)) * 512 + c16 * 8);
    }
    cpa_commit(); cpa_wait<0>(); __syncthreads();

    const int ar  = tid >> 2;           // A row 0..127
    const int ac4 = (tid & 3) << 2;     // u32 offset 0,4,8,12

#define LOADA(s, kc)                                                            \
    do {                                                                        \
        cpa16_u(su + ((uint32_t)(s) * 2560u + (uint32_t)ar * 20u + ac4) * 4u,   \
                Ag + (size_t)ar * 512 + (kc) * 32 + ac4 * 2);                   \
        cpa_commit();                                                           \
    } while (0)

    for (int t = 0; t < Dd; t++) {
        const __nv_bfloat16* Abase = Hbf + (size_t)t * Bn * Hh + (size_t)mb * 256 * 512;
        const float* Hfp = Hf + (size_t)(t & 1) * Bn * Hh;
        float* Hfn       = Hf + (size_t)((t + 1) & 1) * Bn * Hh;
        __nv_bfloat16* Hbn = (__nv_bfloat16*)(Hbf + (size_t)(t + 1) * Bn * Hh);

        for (int mh = 0; mh < 2; mh++) {
            const __nv_bfloat16* Ag = Abase + (size_t)mh * 128 * 512;

            float acc[3][4][4];
#pragma unroll
            for (int g = 0; g < 3; g++)
#pragma unroll
                for (int nt = 0; nt < 4; nt++)
#pragma unroll
                    for (int r = 0; r < 4; r++) acc[g][nt][r] = 0.f;

            LOADA(0, 0);
            LOADA(1, 1);

            for (int kc = 0; kc < 16; kc++) {
                const int s = kc % 3;
                if (kc < 14) cpa_wait<1>(); else cpa_wait<0>();
                __syncthreads();
                if (kc + 2 < 16) LOADA((kc + 2) % 3, kc + 2);

#pragma unroll
                for (int kb = 0; kb < 16; kb += 8) {
                    uint32_t af[4];
                    {
                        uint32_t base = (uint32_t)s * 2560u + (uint32_t)(wm * 16 + gid) * 20u + kb + t4;
                        af[0] = sm[base];       af[1] = sm[base + 160];
                        af[2] = sm[base + 4];   af[3] = sm[base + 164];
                    }
#pragma unroll
                    for (int g = 0; g < 3; g++)
#pragma unroll
                        for (int nt = 0; nt < 4; nt++) {
                            int nrow = g * 64 + wn * 32 + nt * 8 + gid;
                            uint32_t bbase = BW + (uint32_t)nrow * 260u + (uint32_t)kc * 16u + kb + t4;
                            uint32_t bf[2];
                            bf[0] = sm[bbase];
                            bf[1] = sm[bbase + 4];
                            mma_bf16(acc[g][nt], af, bf);
                        }
                }
            }

            // ---- epilogue for this 128-row half ----------------------------
            {
                int b_lo = mb * 256 + mh * 128 + wm * 16 + gid;
                int b_hi = b_lo + 8;
                float zt_lo = (t == 0) ? -1.0f : z[(size_t)b_lo * Dd + (t - 1)];
                float zt_hi = (t == 0) ? -1.0f : z[(size_t)b_hi * Dd + (t - 1)];
                const float4* g4lo = g_gic4 + (size_t)b_lo * Hh;
                const float4* g4hi = g_gic4 + (size_t)b_hi * Hh;
                const float* hp_lo = Hfp + (size_t)b_lo * Hh;
                const float* hp_hi = Hfp + (size_t)b_hi * Hh;
                float* hf_lo = Hfn + (size_t)b_lo * Hh;
                float* hf_hi = Hfn + (size_t)b_hi * Hh;
                __nv_bfloat16* hb_lo = Hbn + (size_t)b_lo * Hh;
                __nv_bfloat16* hb_hi = Hbn + (size_t)b_hi * Hh;

#pragma unroll
                for (int nt = 0; nt < 4; nt++) {
                    int jc = jb * 64 + wn * 32 + nt * 8 + t4 * 2;
                    float hlo[2], hhi[2];
#pragma unroll
                    for (int cc = 0; cc < 2; cc++) {
                        int j = jc + cc;
                        float4 w4  = g_wz4[j];
                        float4 glo = g4lo[j];
                        float4 ghi = g4hi[j];
                        {
                            float r = fast_sig(fmaf(zt_lo, w4.x, glo.x) + acc[0][nt][cc]);
                            float u = fast_sig(fmaf(zt_lo, w4.y, glo.y) + acc[1][nt][cc]);
                            float n = fast_tanh(fmaf(r, acc[2][nt][cc] + glo.w,
                                                     fmaf(zt_lo, w4.z, glo.z)));
                            hlo[cc] = fmaf(u, hp_lo[j] - n, n);
                        }
                        {
                            float r = fast_sig(fmaf(zt_hi, w4.x, ghi.x) + acc[0][nt][2 + cc]);
                            float u = fast_sig(fmaf(zt_hi, w4.y, ghi.y) + acc[1][nt][2 + cc]);
                            float n = fast_tanh(fmaf(r, acc[2][nt][2 + cc] + ghi.w,
                                                     fmaf(zt_hi, w4.z, ghi.z)));
                            hhi[cc] = fmaf(u, hp_hi[j] - n, n);
                        }
                    }
                    *(float2*)(hf_lo + jc) = make_float2(hlo[0], hlo[1]);
                    *(float2*)(hf_hi + jc) = make_float2(hhi[0], hhi[1]);
                    *(uint32_t*)(hb_lo + jc) = pack_bf16x2(hlo[0], hlo[1]);
                    *(uint32_t*)(hb_hi + jc) = pack_bf16x2(hhi[0], hhi[1]);
                }
            }
            __syncthreads();   // epilogue done before next half reuses stage 0
        }

        // ---- grid-wide barrier (publish h_{t+1}) ---------------------------
        __threadfence();
        __syncthreads();
        if (tid == 0) {
            unsigned v = atomicAdd(&g_bar_cnt, 1u);
            if (v == NCTA - 1) {
                g_bar_cnt = 0;
                __threadfence();
                atomicExch(&g_bar_flag, (unsigned)(t + 1));
            } else {
                while (atomicAdd(&g_bar_flag, 0u) < (unsigned)(t + 1)) { }
            }
        }
        __syncthreads();
    }
#undef LOADA
}

// ============ bf16 MLP GEMM (A bf16 [M][512], BT bf16 [512][512]) ============
template<int MODE>
__global__ __launch_bounds__(256)
void bgemm_mlp(const __nv_bfloat16* __restrict__ A, const __nv_bfloat16* __restrict__ BT,
               const float* __restrict__ bias, void* __restrict__ Cout, int M)
{
    const int K = 512, N = 512;
    __shared__ uint32_t As[2][128][20];
    __shared__ uint32_t Bs[2][128][20];

    const int tid  = threadIdx.x;
    const int wid  = tid >> 5;
    const int lane = tid & 31;
    const int g    = lane >> 2;
    const int t    = lane & 3;
    const int wm   = wid >> 2;
    const int wn   = wid & 3;

    const int row0 = blockIdx.y * 128;
    const int col0 = blockIdx.x * 128;

    float acc[4][4][4];
#pragma unroll
    for (int mt = 0; mt < 4; mt++)
#pragma unroll
        for (int nt = 0; nt < 4; nt++)
#pragma unroll
            for (int r = 0; r < 4; r++) acc[mt][nt][r] = 0.f;

    const int lr = tid >> 1;
    const int lc = (tid & 1) * 2;

#define LOAD_STAGE(s, kt)                                                        \
    do {                                                                         \
        cpa16_u(smem_u32(&As[s][lr][lc * 4]),                                    \
                A  + (size_t)(row0 + lr) * K + (kt) * 32 + lc * 8);              \
        cpa16_u(smem_u32(&As[s][lr][(lc + 1) * 4]),                              \
                A  + (size_t)(row0 + lr) * K + (kt) * 32 + (lc + 1) * 8);        \
        cpa16_u(smem_u32(&Bs[s][lr][lc * 4]),                                    \
                BT + (size_t)(col0 + lr) * K + (kt) * 32 + lc * 8);              \
        cpa16_u(smem_u32(&Bs[s][lr][(lc + 1) * 4]),                              \
                BT + (size_t)(col0 + lr) * K + (kt) * 32 + (lc + 1) * 8);        \
        cpa_commit();                                                            \
    } while (0)

    LOAD_STAGE(0, 0);
    LOAD_STAGE(1, 1);

    const int nk = K / 32;
    for (int kt = 0; kt < nk; ++kt) {
        const int s = kt & 1;
        cpa_wait<1>();
        __syncthreads();
#pragma unroll
        for (int kb = 0; kb < 16; kb += 8) {
            uint32_t af[4][4];
#pragma unroll
            for (int mt = 0; mt < 4; mt++) {
                int r = wm * 64 + mt * 16 + g;
                af[mt][0] = As[s][r][kb + t];     af[mt][1] = As[s][r + 8][kb + t];
                af[mt][2] = As[s][r][kb + t + 4]; af[mt][3] = As[s][r + 8][kb + t + 4];
            }
#pragma unroll
            for (int nt = 0; nt < 4; nt++) {
                int n = wn * 32 + nt * 8 + g;
                uint32_t bf[2];
                bf[0] = Bs[s][n][kb + t];
                bf[1] = Bs[s][n][kb + t + 4];
#pragma unroll
                for (int mt = 0; mt < 4; mt++)
                    mma_bf16(acc[mt][nt], af[mt], bf);
            }
        }
        __syncthreads();
        if (kt + 2 < nk) LOAD_STAGE(s, kt + 2);
    }
#undef LOAD_STAGE

#pragma unroll
    for (int mt = 0; mt < 4; mt++) {
        int row_lo = row0 + wm * 64 + mt * 16 + g;
        int row_hi = row_lo + 8;
#pragma unroll
        for (int nt = 0; nt < 4; nt++) {
            int col = col0 + wn * 32 + nt * 8 + t * 2;
            float v0 = acc[mt][nt][0], v1 = acc[mt][nt][1];
            float v2 = acc[mt][nt][2], v3 = acc[mt][nt][3];
            if (MODE == 0) {
                const float* blo = bias + (size_t)(row_lo & (Bn - 1)) * HIDd + col;
                const float* bhi = bias + (size_t)(row_hi & (Bn - 1)) * HIDd + col;
                v0 = fast_tanh(v0 + blo[0]); v1 = fast_tanh(v1 + blo[1]);
                v2 = fast_tanh(v2 + bhi[0]); v3 = fast_tanh(v3 + bhi[1]);
                __nv_bfloat16* C = (__nv_bfloat16*)Cout;
                *(uint32_t*)(C + (size_t)row_lo * N + col) = pack_bf16x2(v0, v1);
                *(uint32_t*)(C + (size_t)row_hi * N + col) = pack_bf16x2(v2, v3);
            } else {
                float b0 = bias[col], b1 = bias[col + 1];
                v0 = fast_tanh(v0 + b0); v1 = fast_tanh(v1 + b1);
                v2 = fast_tanh(v2 + b0); v3 = fast_tanh(v3 + b1);
                float* C = (float*)Cout;
                *(float2*)(C + (size_t)row_lo * N + col) = make_float2(v0, v1);
                *(float2*)(C + (size_t)row_hi * N + col) = make_float2(v2, v3);
            }
        }
    }
}

// ---------------- head GEMM (N=30) fused with mixture log-likelihood --------
__global__ __launch_bounds__(128)
void head_kernel(const float* __restrict__ W2, const float* __restrict__ b2,
                 const float* __restrict__ z)
{
    __shared__ float a2s[4][512];
    __shared__ float ps[4][32];
    int w = threadIdx.x >> 5, lane = threadIdx.x & 31;
    size_t r = (size_t)blockIdx.x * 4 + w;

    const float4* src = (const float4*)(g_A2 + r * HIDd);
#pragma unroll
    for (int i = 0; i < 4; i++) {
        float4 v = src[lane + 32 * i];
        *(float4*)&a2s[w][(lane + 32 * i) * 4] = v;
    }
    __syncwarp();

    if (lane < 30) {
        float acc = b2[lane];
#pragma unroll 8
        for (int k = 0; k < 512; k++)
            acc = fmaf(a2s[w][k], W2[k * 30 + lane], acc);
        ps[w][lane] = acc;
    }
    __syncwarp();

    if (lane == 0) {
        int t = (int)(r >> 12);
        int b = (int)(r & 4095);
        float zv = z[(size_t)b * Dd + t];
        float* p = ps[w];
        float m1 = -1e30f, m2 = -1e30f;
        float term[10];
#pragma unroll
        for (int k = 0; k < 10; k++) {
            float l = p[k], mu = p[10 + k], ls = p[20 + k];
            float d = (zv - mu) * expf(-ls);
            float tv = l - ls - 0.91893853320467274f - 0.5f * d * d;
            term[k] = tv;
            m1 = fmaxf(m1, tv);
            m2 = fmaxf(m2, l);
        }
        float s1 = 0.f, s2 = 0.f;
#pragma unroll
        for (int k = 0; k < 10; k++) {
            s1 += expf(term[k] - m1);
            s2 += expf(p[k] - m2);
        }
        g_ll[(size_t)b * Dd + t] = (m1 + logf(s1)) - (m2 + logf(s2));
    }
}

// ---------------- final: sort query desc (bitonic) + masked dot -------------
__global__ __launch_bounds__(128)
void final_kernel(const float* __restrict__ bb, const float* __restrict__ m,
                  float* __restrict__ out)
{
    __shared__ float s[128];
    __shared__ float red[128];
    int b = blockIdx.x, t = threadIdx.x;

    float q = -1.0f;
    if (t < Dd) {
        float bv = bb[(size_t)b * Dd + t];
        q = m[(size_t)b * Dd + t] * (1.0f - bv);
    }
    s[t] = q;
    __syncthreads();

    for (int k = 2; k <= 128; k <<= 1) {
        for (int j = k >> 1; j > 0; j >>= 1) {
            int ixj = t ^ j;
            if (ixj > t) {
                float a = s[t], c = s[ixj];
                bool up = ((t & k) == 0);
                if (up ? (a > c) : (a < c)) { s[t] = c; s[ixj] = a; }
            }
            __syncthreads();
        }
    }

    float prod = 0.f;
    if (t < Dd) prod = g_ll[(size_t)b * Dd + t] * s[127 - t];
    red[t] = prod;
    __syncthreads();
    for (int st = 64; st > 0; st >>= 1) {
        if (t < st) red[t] += red[t + st];
        __syncthreads();
    }
    if (t == 0) out[b] = red[0];
}

// ---------------- launch ----------------------------------------------------
extern "C" void kernel_launch(void* const* d_in, const int* in_sizes, int n_in,
                              void* d_out, int out_size)
{
    const float* z   = (const float*)d_in[0];
    const float* c   = (const float*)d_in[1];
    const float* bb  = (const float*)d_in[2];
    const float* m   = (const float*)d_in[3];
    const float* Wih = (const float*)d_in[4];
    const float* Whh = (const float*)d_in[5];
    const float* bih = (const float*)d_in[6];
    const float* bhh = (const float*)d_in[7];
    const float* W0  = (const float*)d_in[8];
    const float* b0  = (const float*)d_in[9];
    const float* W1  = (const float*)d_in[10];
    const float* b1  = (const float*)d_in[11];
    const float* W2  = (const float*)d_in[12];
    const float* b2  = (const float*)d_in[13];
    float* out = (float*)d_out;

    float *pConst, *pGic, *pMlpc, *pHf, *pA2;
    __nv_bfloat16 *pHbf, *pWhhT, *pW0T, *pW1T, *pA1bf;
    cudaGetSymbolAddress((void**)&pConst, g_const);
    cudaGetSymbolAddress((void**)&pGic,   g_gic);
    cudaGetSymbolAddress((void**)&pMlpc,  g_mlpc);
    cudaGetSymbolAddress((void**)&pHf,    g_Hf);
    cudaGetSymbolAddress((void**)&pHbf,   g_Hbf);
    cudaGetSymbolAddress((void**)&pWhhT,  g_WhhT);
    cudaGetSymbolAddress((void**)&pW0T,   g_W0T);
    cudaGetSymbolAddress((void**)&pW1T,   g_W1T);
    cudaGetSymbolAddress((void**)&pA1bf,  g_A1bf);
    cudaGetSymbolAddress((void**)&pA2,    g_A2);

    static int attr_done = 0;
    if (!attr_done) {
        cudaFuncSetAttribute(gru_persist, cudaFuncAttributeMaxDynamicSharedMemorySize, 230400);
        attr_done = 1;
    }

    // 0: merged prep (const build + h0 zero + wz4 + barrier reset)
    {
        size_t tot = (size_t)Bn * CN + (size_t)Bn * Hh + Hh;
        prep_kernel<<<(unsigned)((tot + 255) / 256), 256>>>(c, bb, m, Wih);
    }
    // 1: merged transpose+convert of Whh / W0[:H] / W1
    convT3_kernel<<<dim3(48, 16, 3), dim3(32, 8)>>>(Whh, W0, W1);
    // 2: gi_const = const @ Wih[1:] + bih
    tgemm_kernel<<<dim3(G3 / 128, Bn / 128), 256>>>(pConst, Wih + G3, bih, pGic,
                                                    Bn, G3, CN);
    // 3: mlp_const = const @ W0[H:] + b0
    tgemm_kernel<<<dim3(HIDd / 128, Bn / 128), 256>>>(pConst, W0 + (size_t)Hh * HIDd,
                                                      b0, pMlpc, Bn, HIDd, CN);
    // 4: pack gic4 (gic + bhh folding)
    gic4_pack_kernel<<<(Bn * Hh) / 256, 256>>>(bhh);
    // 5: recurrence — ONE persistent launch for all 112 steps
    gru_persist<<<NCTA, 512, 230400>>>(pHbf, pHf, pWhhT, z);
    // 6-7: batched MLP
    bgemm_mlp<0><<<dim3(HIDd / 128, TOTR / 128), 256>>>(pHbf + (size_t)Bn * Hh, pW0T,
                                                        pMlpc, pA1bf, TOTR);
    bgemm_mlp<1><<<dim3(HIDd / 128, TOTR / 128), 256>>>(pA1bf, pW1T, b1, pA2, TOTR);
    // 8-9: head + final
    head_kernel<<<TOTR / 4, 128>>>(W2, b2, z);
    final_kernel<<<Bn, 128>>>(bb, m, out);
}

// round 9
// speedup vs baseline: 3.8531x; 1.0244x over previous
#include <cuda_runtime.h>
#include <cuda_bf16.h>
#include <math.h>
#include <stdint.h>

#define Bn   4096
#define Dd   112
#define NTd  200
#define Hh   512
#define HIDd 512
#define CN   536      /* 3*D + NT */
#define G3   1536     /* 3*H */
#define TOTR (Dd*Bn)  /* 458752 */
#define NCTA 128      /* persistent grid */

// ---------------- device scratch ---------------------------------------------
__device__ float g_const[(size_t)Bn * CN];
__device__ float g_gic  [(size_t)Bn * G3];
__device__ float4 g_gic4[(size_t)Bn * Hh];     // {gic_r+bhh_r, gic_z+bhh_z, gic_n, bhh_n}
__device__ float4 g_wz4 [Hh];                  // {wz_r, wz_z, wz_n, 0}
__device__ float g_mlpc [(size_t)Bn * HIDd];
__device__ float g_Hf   [2 * (size_t)Bn * Hh];
__device__ __nv_bfloat16 g_Hbf [(size_t)(Dd+1) * Bn * Hh];
__device__ __nv_bfloat16 g_WhhT[(size_t)G3 * Hh];
__device__ __nv_bfloat16 g_W0T [(size_t)HIDd * Hh];
__device__ __nv_bfloat16 g_W1T [(size_t)HIDd * HIDd];
__device__ __nv_bfloat16 g_A1bf[(size_t)TOTR * HIDd];
__device__ float g_A2   [(size_t)TOTR * HIDd];
__device__ float g_ll   [(size_t)Bn * Dd];
__device__ unsigned g_bar_cnt;
__device__ unsigned g_bar_flag;

// ---------------- helpers ----------------------------------------------------
__device__ __forceinline__ float fast_sig(float x)  { return 1.f / (1.f + __expf(-x)); }
__device__ __forceinline__ float fast_tanh(float x) { return fmaf(2.f, 1.f / (1.f + __expf(-2.f * x)), -1.f); }

__device__ __forceinline__ uint32_t pack_bf16x2(float lo, float hi)
{
    uint32_t r;
    asm("cvt.rn.bf16x2.f32 %0, %1, %2;" : "=r"(r) : "f"(hi), "f"(lo));
    return r;
}
__device__ __forceinline__ uint32_t smem_u32(const void* p)
{
    uint32_t a;
    asm("{ .reg .u64 t; cvta.to.shared.u64 t, %1; cvt.u32.u64 %0, t; }" : "=r"(a) : "l"(p));
    return a;
}
__device__ __forceinline__ void cpa16_u(uint32_t dst, const void* src)
{
    asm volatile("cp.async.cg.shared.global [%0], [%1], 16;\n" :: "r"(dst), "l"(src));
}
__device__ __forceinline__ void cpa_commit() { asm volatile("cp.async.commit_group;\n"); }
template<int N>
__device__ __forceinline__ void cpa_wait()   { asm volatile("cp.async.wait_group %0;\n" :: "n"(N)); }

__device__ __forceinline__ uint32_t f2tf32(float x)
{
    uint32_t u;
    asm("cvt.rna.tf32.f32 %0, %1;" : "=r"(u) : "f"(x));
    return u;
}
__device__ __forceinline__ void mma_tf32(float* d, const uint32_t* a, const uint32_t* b)
{
    asm volatile(
        "mma.sync.aligned.m16n8k8.row.col.f32.tf32.tf32.f32 "
        "{%0,%1,%2,%3}, {%4,%5,%6,%7}, {%8,%9}, {%0,%1,%2,%3};\n"
        : "+f"(d[0]), "+f"(d[1]), "+f"(d[2]), "+f"(d[3])
        : "r"(a[0]), "r"(a[1]), "r"(a[2]), "r"(a[3]), "r"(b[0]), "r"(b[1]));
}
__device__ __forceinline__ void mma_bf16(float* d, const uint32_t* a, const uint32_t* b)
{
    asm volatile(
        "mma.sync.aligned.m16n8k16.row.col.f32.bf16.bf16.f32 "
        "{%0,%1,%2,%3}, {%4,%5,%6,%7}, {%8,%9}, {%0,%1,%2,%3};\n"
        : "+f"(d[0]), "+f"(d[1]), "+f"(d[2]), "+f"(d[3])
        : "r"(a[0]), "r"(a[1]), "r"(a[2]), "r"(a[3]), "r"(b[0]), "r"(b[1]));
}

// ---------------- merged prep kernel -----------------------------------------
__global__ void prep_kernel(const float* __restrict__ c,
                            const float* __restrict__ bb,
                            const float* __restrict__ m,
                            const float* __restrict__ Wih)
{
    size_t idx = (size_t)blockIdx.x * blockDim.x + threadIdx.x;
    const size_t R1 = (size_t)Bn * CN;
    const size_t R2 = R1 + (size_t)Bn * Hh;
    if (idx < R1) {
        int b = (int)(idx / CN);
        int i = (int)(idx % CN);
        float v;
        if (i < Dd + NTd)            v = c [(size_t)b * (Dd + NTd) + i];
        else if (i < Dd + NTd + Dd)  v = bb[(size_t)b * Dd + (i - (Dd + NTd))];
        else                         v = m [(size_t)b * Dd + (i - (Dd + NTd + Dd))];
        g_const[idx] = v;
    } else if (idx < R2) {
        size_t i2 = idx - R1;
        g_Hf[i2] = 0.f;
        g_Hbf[i2] = __float2bfloat16(0.f);
    } else if (idx < R2 + Hh) {
        int j = (int)(idx - R2);
        g_wz4[j] = make_float4(Wih[j], Wih[512 + j], Wih[1024 + j], 0.f);
        if (j == 0) { g_bar_cnt = 0; g_bar_flag = 0; }
    }
}

// pack gic4 after tgemm produced g_gic
__global__ void gic4_pack_kernel(const float* __restrict__ bhh)
{
    size_t idx = (size_t)blockIdx.x * blockDim.x + threadIdx.x;
    if (idx >= (size_t)Bn * Hh) return;
    int b = (int)(idx >> 9);
    int j = (int)(idx & 511);
    const float* g = g_gic + (size_t)b * G3;
    g_gic4[idx] = make_float4(g[j] + bhh[j],
                              g[512 + j] + bhh[512 + j],
                              g[1024 + j],
                              bhh[1024 + j]);
}

// merged transpose+convert (z selects matrix)
__global__ void convT3_kernel(const float* __restrict__ Whh,
                              const float* __restrict__ W0,
                              const float* __restrict__ W1)
{
    __shared__ float tile[32][33];
    const float* in;
    __nv_bfloat16* out;
    int Krows = 512, Ncols;
    if (blockIdx.z == 0)      { in = Whh; out = g_WhhT; Ncols = G3; }
    else if (blockIdx.z == 1) { in = W0;  out = g_W0T;  Ncols = HIDd; }
    else                      { in = W1;  out = g_W1T;  Ncols = HIDd; }
    int n0 = blockIdx.x * 32;
    if (n0 >= Ncols) return;
    int k0 = blockIdx.y * 32;
    int tx = threadIdx.x, ty = threadIdx.y;
    for (int i = ty; i < 32; i += 8)
        tile[i][tx] = in[(size_t)(k0 + i) * Ncols + n0 + tx];
    __syncthreads();
    for (int i = ty; i < 32; i += 8)
        out[(size_t)(n0 + i) * Krows + k0 + tx] = __float2bfloat16(tile[tx][i]);
}

// ---------------- tf32 GEMM for K=536 precompute (fp32 in/out) ---------------
__global__ __launch_bounds__(256)
void tgemm_kernel(const float* __restrict__ A, const float* __restrict__ B,
                  const float* __restrict__ bias, float* __restrict__ C,
                  int M, int N, int K)
{
    __shared__ uint32_t As[128][12];
    __shared__ uint32_t Bs[8][136];

    const int tid  = threadIdx.x;
    const int wid  = tid >> 5;
    const int lane = tid & 31;
    const int gid  = lane >> 2;
    const int tig  = lane & 3;
    const int wm   = wid >> 2;
    const int wn   = wid & 3;
    const int row0 = blockIdx.y * 128;
    const int col0 = blockIdx.x * 128;

    float acc[4][4][4];
#pragma unroll
    for (int mt = 0; mt < 4; mt++)
#pragma unroll
        for (int nt = 0; nt < 4; nt++)
#pragma unroll
            for (int r = 0; r < 4; r++) acc[mt][nt][r] = 0.f;

    const int ar = tid >> 1;
    const int ak = (tid & 1) * 4;
    const int bk = tid >> 5;
    const int bn = (tid & 31) * 4;
    const int niter = K >> 3;

    const float* Ag = A + (size_t)(row0 + ar) * K + ak;
    const float* Bg = B + (size_t)bk * N + col0 + bn;

    float4 pa = *(const float4*)Ag;
    float4 pb = *(const float4*)Bg;

    for (int it = 0; it < niter; ++it) {
        As[ar][ak + 0] = f2tf32(pa.x); As[ar][ak + 1] = f2tf32(pa.y);
        As[ar][ak + 2] = f2tf32(pa.z); As[ar][ak + 3] = f2tf32(pa.w);
        Bs[bk][bn + 0] = f2tf32(pb.x); Bs[bk][bn + 1] = f2tf32(pb.y);
        Bs[bk][bn + 2] = f2tf32(pb.z); Bs[bk][bn + 3] = f2tf32(pb.w);
        __syncthreads();
        if (it + 1 < niter) {
            pa = *(const float4*)(Ag + (size_t)(it + 1) * 8);
            pb = *(const float4*)(Bg + (size_t)(it + 1) * 8 * N);
        }
        uint32_t af[4][4];
#pragma unroll
        for (int mt = 0; mt < 4; mt++) {
            int rb = wm * 64 + mt * 16 + gid;
            af[mt][0] = As[rb][tig];     af[mt][1] = As[rb + 8][tig];
            af[mt][2] = As[rb][tig + 4]; af[mt][3] = As[rb + 8][tig + 4];
        }
        uint32_t bf[4][2];
#pragma unroll
        for (int nt = 0; nt < 4; nt++) {
            int cb = wn * 32 + nt * 8 + gid;
            bf[nt][0] = Bs[tig][cb]; bf[nt][1] = Bs[tig + 4][cb];
        }
#pragma unroll
        for (int mt = 0; mt < 4; mt++)
#pragma unroll
            for (int nt = 0; nt < 4; nt++)
                mma_tf32(acc[mt][nt], af[mt], bf[nt]);
        __syncthreads();
    }
#pragma unroll
    for (int mt = 0; mt < 4; mt++) {
        int row_lo = row0 + wm * 64 + mt * 16 + gid;
        int row_hi = row_lo + 8;
#pragma unroll
        for (int nt = 0; nt < 4; nt++) {
            int col = col0 + wn * 32 + nt * 8 + tig * 2;
            float b0 = bias[col], b1 = bias[col + 1];
            *(float2*)(C + (size_t)row_lo * N + col) =
                make_float2(acc[mt][nt][0] + b0, acc[mt][nt][1] + b1);
            *(float2*)(C + (size_t)row_hi * N + col) =
                make_float2(acc[mt][nt][2] + b0, acc[mt][nt][3] + b1);
        }
    }
}

// ============ PERSISTENT weight-stationary GRU recurrence (1024 thr) =========
// 128 CTAs. CTA c: batch rows [(c>>3)*256, +256), j cols [(c&7)*64, +64).
// 32 warps: wm = wid>>2 (16-row slice of 128), wn = wid&3 (16-col slice of 64).
// smem: A triple-buffer 3*2560 u32 (30720 B) + resident WhhT slice
// [192 rows][260 u32] (199680 B) = 230400 B.
__global__ __launch_bounds__(1024, 1)
void gru_persist(const __nv_bfloat16* __restrict__ Hbf,
                 float* __restrict__ Hf,
                 const __nv_bfloat16* __restrict__ WhhT,
                 const float* __restrict__ z)
{
    extern __shared__ uint32_t sm[];
    const int tid  = threadIdx.x;
    const int wid  = tid >> 5;          // 0..31
    const int lane = tid & 31;
    const int gid  = lane >> 2;
    const int t4   = lane & 3;
    const int wm   = wid >> 2;          // 0..7 : 16-row slice
    const int wn   = wid & 3;           // 0..3 : 16-col slice
    const int jb   = blockIdx.x & 7;
    const int mb   = blockIdx.x >> 3;
    uint32_t su = smem_u32(sm);
    const uint32_t BW = 7680;           // B region start (u32 words)

    // resident Whh slice: [3 gates][64 n][512 k] bf16, row stride 260 u32
    for (int i = tid; i < 12288; i += 1024) {
        int n_row = i >> 6;
        int c16   = i & 63;             // 16B chunk within row
        int g = n_row >> 6, n = n_row & 63;
        cpa16_u(su + (BW + (uint32_t)n_row * 260u + (uint32_t)c16 * 4u) * 4u,
                WhhT + ((size_t)(g * 512 + jb * 64 + n)) * 512 + c16 * 8);
    }
    cpa_commit(); cpa_wait<0>(); __syncthreads();

    const int ar  = tid >> 3;           // A row 0..127  (tid<1024: rows repeat x?)
    const int ac4 = (tid & 7) << 1;     // u32 offset 0,2,...,14  (8B chunks)

    // A stage = 128 rows x 16 u32 (+4 pad) ; 1024 threads x 8B = 8KB exactly
#define LOADA(s, kc)                                                            \
    do {                                                                        \
        asm volatile("cp.async.ca.shared.global [%0], [%1], 8;\n"               \
            :: "r"(su + ((uint32_t)(s) * 2560u + (uint32_t)ar * 20u + ac4) * 4u), \
               "l"(Ag + (size_t)ar * 512 + (kc) * 32 + ac4 * 2));               \
        cpa_commit();                                                           \
    } while (0)

    for (int t = 0; t < Dd; t++) {
        const __nv_bfloat16* Abase = Hbf + (size_t)t * Bn * Hh + (size_t)mb * 256 * 512;
        const float* Hfp = Hf + (size_t)(t & 1) * Bn * Hh;
        float* Hfn       = Hf + (size_t)((t + 1) & 1) * Bn * Hh;
        __nv_bfloat16* Hbn = (__nv_bfloat16*)(Hbf + (size_t)(t + 1) * Bn * Hh);

        for (int mh = 0; mh < 2; mh++) {
            const __nv_bfloat16* Ag = Abase + (size_t)mh * 128 * 512;

            float acc[3][2][4];
#pragma unroll
            for (int g = 0; g < 3; g++)
#pragma unroll
                for (int nt = 0; nt < 2; nt++)
#pragma unroll
                    for (int r = 0; r < 4; r++) acc[g][nt][r] = 0.f;

            LOADA(0, 0);
            LOADA(1, 1);

            for (int kc = 0; kc < 16; kc++) {
                const int s = kc % 3;
                if (kc < 14) cpa_wait<1>(); else cpa_wait<0>();
                __syncthreads();
                if (kc + 2 < 16) LOADA((kc + 2) % 3, kc + 2);

#pragma unroll
                for (int kb = 0; kb < 16; kb += 8) {
                    uint32_t af[4];
                    {
                        uint32_t base = (uint32_t)s * 2560u + (uint32_t)(wm * 16 + gid) * 20u + kb + t4;
                        af[0] = sm[base];       af[1] = sm[base + 160];
                        af[2] = sm[base + 4];   af[3] = sm[base + 164];
                    }
#pragma unroll
                    for (int g = 0; g < 3; g++)
#pragma unroll
                        for (int nt = 0; nt < 2; nt++) {
                            int nrow = g * 64 + wn * 16 + nt * 8 + gid;
                            uint32_t bbase = BW + (uint32_t)nrow * 260u + (uint32_t)kc * 16u + kb + t4;
                            uint32_t bf[2];
                            bf[0] = sm[bbase];
                            bf[1] = sm[bbase + 4];
                            mma_bf16(acc[g][nt], af, bf);
                        }
                }
            }

            // ---- epilogue for this 128-row half ----------------------------
            {
                int b_lo = mb * 256 + mh * 128 + wm * 16 + gid;
                int b_hi = b_lo + 8;
                float zt_lo = (t == 0) ? -1.0f : z[(size_t)b_lo * Dd + (t - 1)];
                float zt_hi = (t == 0) ? -1.0f : z[(size_t)b_hi * Dd + (t - 1)];
                const float4* g4lo = g_gic4 + (size_t)b_lo * Hh;
                const float4* g4hi = g_gic4 + (size_t)b_hi * Hh;
                const float* hp_lo = Hfp + (size_t)b_lo * Hh;
                const float* hp_hi = Hfp + (size_t)b_hi * Hh;
                float* hf_lo = Hfn + (size_t)b_lo * Hh;
                float* hf_hi = Hfn + (size_t)b_hi * Hh;
                __nv_bfloat16* hb_lo = Hbn + (size_t)b_lo * Hh;
                __nv_bfloat16* hb_hi = Hbn + (size_t)b_hi * Hh;

#pragma unroll
                for (int nt = 0; nt < 2; nt++) {
                    int jc = jb * 64 + wn * 16 + nt * 8 + t4 * 2;
                    float hlo[2], hhi[2];
#pragma unroll
                    for (int cc = 0; cc < 2; cc++) {
                        int j = jc + cc;
                        float4 w4  = g_wz4[j];
                        float4 glo = g4lo[j];
                        float4 ghi = g4hi[j];
                        {
                            float r = fast_sig(fmaf(zt_lo, w4.x, glo.x) + acc[0][nt][cc]);
                            float u = fast_sig(fmaf(zt_lo, w4.y, glo.y) + acc[1][nt][cc]);
                            float n = fast_tanh(fmaf(r, acc[2][nt][cc] + glo.w,
                                                     fmaf(zt_lo, w4.z, glo.z)));
                            hlo[cc] = fmaf(u, hp_lo[j] - n, n);
                        }
                        {
                            float r = fast_sig(fmaf(zt_hi, w4.x, ghi.x) + acc[0][nt][2 + cc]);
                            float u = fast_sig(fmaf(zt_hi, w4.y, ghi.y) + acc[1][nt][2 + cc]);
                            float n = fast_tanh(fmaf(r, acc[2][nt][2 + cc] + ghi.w,
                                                     fmaf(zt_hi, w4.z, ghi.z)));
                            hhi[cc] = fmaf(u, hp_hi[j] - n, n);
                        }
                    }
                    *(float2*)(hf_lo + jc) = make_float2(hlo[0], hlo[1]);
                    *(float2*)(hf_hi + jc) = make_float2(hhi[0], hhi[1]);
                    *(uint32_t*)(hb_lo + jc) = pack_bf16x2(hlo[0], hlo[1]);
                    *(uint32_t*)(hb_hi + jc) = pack_bf16x2(hhi[0], hhi[1]);
                }
            }
            __syncthreads();   // epilogue done before next half reuses stage 0
        }

        // ---- grid-wide barrier (publish h_{t+1}) ---------------------------
        __threadfence();
        __syncthreads();
        if (tid == 0) {
            unsigned v = atomicAdd(&g_bar_cnt, 1u);
            if (v == NCTA - 1) {
                g_bar_cnt = 0;
                __threadfence();
                atomicExch(&g_bar_flag, (unsigned)(t + 1));
            } else {
                while (atomicAdd(&g_bar_flag, 0u) < (unsigned)(t + 1)) { }
            }
        }
        __syncthreads();
    }
#undef LOADA
}

// ============ bf16 MLP GEMM (A bf16 [M][512], BT bf16 [512][512]) ============
template<int MODE>
__global__ __launch_bounds__(256)
void bgemm_mlp(const __nv_bfloat16* __restrict__ A, const __nv_bfloat16* __restrict__ BT,
               const float* __restrict__ bias, void* __restrict__ Cout, int M)
{
    const int K = 512, N = 512;
    __shared__ uint32_t As[2][128][20];
    __shared__ uint32_t Bs[2][128][20];

    const int tid  = threadIdx.x;
    const int wid  = tid >> 5;
    const int lane = tid & 31;
    const int g    = lane >> 2;
    const int t    = lane & 3;
    const int wm   = wid >> 2;
    const int wn   = wid & 3;

    const int row0 = blockIdx.y * 128;
    const int col0 = blockIdx.x * 128;

    float acc[4][4][4];
#pragma unroll
    for (int mt = 0; mt < 4; mt++)
#pragma unroll
        for (int nt = 0; nt < 4; nt++)
#pragma unroll
            for (int r = 0; r < 4; r++) acc[mt][nt][r] = 0.f;

    const int lr = tid >> 1;
    const int lc = (tid & 1) * 2;

#define LOAD_STAGE(s, kt)                                                        \
    do {                                                                         \
        cpa16_u(smem_u32(&As[s][lr][lc * 4]),                                    \
                A  + (size_t)(row0 + lr) * K + (kt) * 32 + lc * 8);              \
        cpa16_u(smem_u32(&As[s][lr][(lc + 1) * 4]),                              \
                A  + (size_t)(row0 + lr) * K + (kt) * 32 + (lc + 1) * 8);        \
        cpa16_u(smem_u32(&Bs[s][lr][lc * 4]),                                    \
                BT + (size_t)(col0 + lr) * K + (kt) * 32 + lc * 8);              \
        cpa16_u(smem_u32(&Bs[s][lr][(lc + 1) * 4]),                              \
                BT + (size_t)(col0 + lr) * K + (kt) * 32 + (lc + 1) * 8);        \
        cpa_commit();                                                            \
    } while (0)

    LOAD_STAGE(0, 0);
    LOAD_STAGE(1, 1);

    const int nk = K / 32;
    for (int kt = 0; kt < nk; ++kt) {
        const int s = kt & 1;
        cpa_wait<1>();
        __syncthreads();
#pragma unroll
        for (int kb = 0; kb < 16; kb += 8) {
            uint32_t af[4][4];
#pragma unroll
            for (int mt = 0; mt < 4; mt++) {
                int r = wm * 64 + mt * 16 + g;
                af[mt][0] = As[s][r][kb + t];     af[mt][1] = As[s][r + 8][kb + t];
                af[mt][2] = As[s][r][kb + t + 4]; af[mt][3] = As[s][r + 8][kb + t + 4];
            }
#pragma unroll
            for (int nt = 0; nt < 4; nt++) {
                int n = wn * 32 + nt * 8 + g;
                uint32_t bf[2];
                bf[0] = Bs[s][n][kb + t];
                bf[1] = Bs[s][n][kb + t + 4];
#pragma unroll
                for (int mt = 0; mt < 4; mt++)
                    mma_bf16(acc[mt][nt], af[mt], bf);
            }
        }
        __syncthreads();
        if (kt + 2 < nk) LOAD_STAGE(s, kt + 2);
    }
#undef LOAD_STAGE

#pragma unroll
    for (int mt = 0; mt < 4; mt++) {
        int row_lo = row0 + wm * 64 + mt * 16 + g;
        int row_hi = row_lo + 8;
#pragma unroll
        for (int nt = 0; nt < 4; nt++) {
            int col = col0 + wn * 32 + nt * 8 + t * 2;
            float v0 = acc[mt][nt][0], v1 = acc[mt][nt][1];
            float v2 = acc[mt][nt][2], v3 = acc[mt][nt][3];
            if (MODE == 0) {
                const float* blo = bias + (size_t)(row_lo & (Bn - 1)) * HIDd + col;
                const float* bhi = bias + (size_t)(row_hi & (Bn - 1)) * HIDd + col;
                v0 = fast_tanh(v0 + blo[0]); v1 = fast_tanh(v1 + blo[1]);
                v2 = fast_tanh(v2 + bhi[0]); v3 = fast_tanh(v3 + bhi[1]);
                __nv_bfloat16* C = (__nv_bfloat16*)Cout;
                *(uint32_t*)(C + (size_t)row_lo * N + col) = pack_bf16x2(v0, v1);
                *(uint32_t*)(C + (size_t)row_hi * N + col) = pack_bf16x2(v2, v3);
            } else {
                float b0 = bias[col], b1 = bias[col + 1];
                v0 = fast_tanh(v0 + b0); v1 = fast_tanh(v1 + b1);
                v2 = fast_tanh(v2 + b0); v3 = fast_tanh(v3 + b1);
                float* C = (float*)Cout;
                *(float2*)(C + (size_t)row_lo * N + col) = make_float2(v0, v1);
                *(float2*)(C + (size_t)row_hi * N + col) = make_float2(v2, v3);
            }
        }
    }
}

// ---------------- head GEMM (N=30) fused with mixture log-likelihood --------
__global__ __launch_bounds__(128)
void head_kernel(const float* __restrict__ W2, const float* __restrict__ b2,
                 const float* __restrict__ z)
{
    __shared__ float a2s[4][512];
    __shared__ float ps[4][32];
    int w = threadIdx.x >> 5, lane = threadIdx.x & 31;
    size_t r = (size_t)blockIdx.x * 4 + w;

    const float4* src = (const float4*)(g_A2 + r * HIDd);
#pragma unroll
    for (int i = 0; i < 4; i++) {
        float4 v = src[lane + 32 * i];
        *(float4*)&a2s[w][(lane + 32 * i) * 4] = v;
    }
    __syncwarp();

    if (lane < 30) {
        float acc = b2[lane];
#pragma unroll 8
        for (int k = 0; k < 512; k++)
            acc = fmaf(a2s[w][k], W2[k * 30 + lane], acc);
        ps[w][lane] = acc;
    }
    __syncwarp();

    if (lane == 0) {
        int t = (int)(r >> 12);
        int b = (int)(r & 4095);
        float zv = z[(size_t)b * Dd + t];
        float* p = ps[w];
        float m1 = -1e30f, m2 = -1e30f;
        float term[10];
#pragma unroll
        for (int k = 0; k < 10; k++) {
            float l = p[k], mu = p[10 + k], ls = p[20 + k];
            float d = (zv - mu) * expf(-ls);
            float tv = l - ls - 0.91893853320467274f - 0.5f * d * d;
            term[k] = tv;
            m1 = fmaxf(m1, tv);
            m2 = fmaxf(m2, l);
        }
        float s1 = 0.f, s2 = 0.f;
#pragma unroll
        for (int k = 0; k < 10; k++) {
            s1 += expf(term[k] - m1);
            s2 += expf(p[k] - m2);
        }
        g_ll[(size_t)b * Dd + t] = (m1 + logf(s1)) - (m2 + logf(s2));
    }
}

// ---------------- final: sort query desc (bitonic) + masked dot -------------
__global__ __launch_bounds__(128)
void final_kernel(const float* __restrict__ bb, const float* __restrict__ m,
                  float* __restrict__ out)
{
    __shared__ float s[128];
    __shared__ float red[128];
    int b = blockIdx.x, t = threadIdx.x;

    float q = -1.0f;
    if (t < Dd) {
        float bv = bb[(size_t)b * Dd + t];
        q = m[(size_t)b * Dd + t] * (1.0f - bv);
    }
    s[t] = q;
    __syncthreads();

    for (int k = 2; k <= 128; k <<= 1) {
        for (int j = k >> 1; j > 0; j >>= 1) {
            int ixj = t ^ j;
            if (ixj > t) {
                float a = s[t], c = s[ixj];
                bool up = ((t & k) == 0);
                if (up ? (a > c) : (a < c)) { s[t] = c; s[ixj] = a; }
            }
            __syncthreads();
        }
    }

    float prod = 0.f;
    if (t < Dd) prod = g_ll[(size_t)b * Dd + t] * s[127 - t];
    red[t] = prod;
    __syncthreads();
    for (int st = 64; st > 0; st >>= 1) {
        if (t < st) red[t] += red[t + st];
        __syncthreads();
    }
    if (t == 0) out[b] = red[0];
}

// ---------------- launch ----------------------------------------------------
extern "C" void kernel_launch(void* const* d_in, const int* in_sizes, int n_in,
                              void* d_out, int out_size)
{
    const float* z   = (const float*)d_in[0];
    const float* c   = (const float*)d_in[1];
    const float* bb  = (const float*)d_in[2];
    const float* m   = (const float*)d_in[3];
    const float* Wih = (const float*)d_in[4];
    const float* Whh = (const float*)d_in[5];
    const float* bih = (const float*)d_in[6];
    const float* bhh = (const float*)d_in[7];
    const float* W0  = (const float*)d_in[8];
    const float* b0  = (const float*)d_in[9];
    const float* W1  = (const float*)d_in[10];
    const float* b1  = (const float*)d_in[11];
    const float* W2  = (const float*)d_in[12];
    const float* b2  = (const float*)d_in[13];
    float* out = (float*)d_out;

    float *pConst, *pGic, *pMlpc, *pHf, *pA2;
    __nv_bfloat16 *pHbf, *pWhhT, *pW0T, *pW1T, *pA1bf;
    cudaGetSymbolAddress((void**)&pConst, g_const);
    cudaGetSymbolAddress((void**)&pGic,   g_gic);
    cudaGetSymbolAddress((void**)&pMlpc,  g_mlpc);
    cudaGetSymbolAddress((void**)&pHf,    g_Hf);
    cudaGetSymbolAddress((void**)&pHbf,   g_Hbf);
    cudaGetSymbolAddress((void**)&pWhhT,  g_WhhT);
    cudaGetSymbolAddress((void**)&pW0T,   g_W0T);
    cudaGetSymbolAddress((void**)&pW1T,   g_W1T);
    cudaGetSymbolAddress((void**)&pA1bf,  g_A1bf);
    cudaGetSymbolAddress((void**)&pA2,    g_A2);

    static int attr_done = 0;
    if (!attr_done) {
        cudaFuncSetAttribute(gru_persist, cudaFuncAttributeMaxDynamicSharedMemorySize, 230400);
        attr_done = 1;
    }

    // 0: merged prep (const build + h0 zero + wz4 + barrier reset)
    {
        size_t tot = (size_t)Bn * CN + (size_t)Bn * Hh + Hh;
        prep_kernel<<<(unsigned)((tot + 255) / 256), 256>>>(c, bb, m, Wih);
    }
    // 1: merged transpose+convert of Whh / W0[:H] / W1
    convT3_kernel<<<dim3(48, 16, 3), dim3(32, 8)>>>(Whh, W0, W1);
    // 2: gi_const = const @ Wih[1:] + bih
    tgemm_kernel<<<dim3(G3 / 128, Bn / 128), 256>>>(pConst, Wih + G3, bih, pGic,
                                                    Bn, G3, CN);
    // 3: mlp_const = const @ W0[H:] + b0
    tgemm_kernel<<<dim3(HIDd / 128, Bn / 128), 256>>>(pConst, W0 + (size_t)Hh * HIDd,
                                                      b0, pMlpc, Bn, HIDd, CN);
    // 4: pack gic4 (gic + bhh folding)
    gic4_pack_kernel<<<(Bn * Hh) / 256, 256>>>(bhh);
    // 5: recurrence — ONE persistent launch, 1024 threads
    gru_persist<<<NCTA, 1024, 230400>>>(pHbf, pHf, pWhhT, z);
    // 6-7: batched MLP
    bgemm_mlp<0><<<dim3(HIDd / 128, TOTR / 128), 256>>>(pHbf + (size_t)Bn * Hh, pW0T,
                                                        pMlpc, pA1bf, TOTR);
    bgemm_mlp<1><<<dim3(HIDd / 128, TOTR / 128), 256>>>(pA1bf, pW1T, b1, pA2, TOTR);
    // 8-9: head + final
    head_kernel<<<TOTR / 4, 128>>>(W2, b2, z);
    final_kernel<<<Bn, 128>>>(bb, m, out);
}

// round 10
// speedup vs baseline: 3.8660x; 1.0034x over previous
#include <cuda_runtime.h>
#include <cuda_bf16.h>
#include <math.h>
#include <stdint.h>

#define Bn   4096
#define Dd   112
#define NTd  200
#define Hh   512
#define HIDd 512
#define CN   536      /* 3*D + NT */
#define G3   1536     /* 3*H */
#define TOTR (Dd*Bn)  /* 458752 */
#define NCTA 128      /* persistent grid */

// ---------------- device scratch ---------------------------------------------
__device__ float g_const[(size_t)Bn * CN];
__device__ float g_gic  [(size_t)Bn * G3];
__device__ float4 g_gic4[(size_t)Bn * Hh];     // {gic_r+bhh_r, gic_z+bhh_z, gic_n, bhh_n}
__device__ float4 g_wz4 [Hh];                  // {wz_r, wz_z, wz_n, 0}
__device__ float g_mlpc [(size_t)Bn * HIDd];
__device__ float g_Hf   [2 * (size_t)Bn * Hh];
__device__ __nv_bfloat16 g_Hbf [(size_t)(Dd+1) * Bn * Hh];
__device__ __nv_bfloat16 g_WhhT[(size_t)G3 * Hh];
__device__ __nv_bfloat16 g_W0T [(size_t)HIDd * Hh];
__device__ __nv_bfloat16 g_W1T [(size_t)HIDd * HIDd];
__device__ __nv_bfloat16 g_A1bf[(size_t)TOTR * HIDd];
__device__ __nv_bfloat16 g_A2bf[(size_t)TOTR * HIDd];
__device__ float g_ll   [(size_t)Bn * Dd];
__device__ unsigned g_bar_cnt;
__device__ unsigned g_bar_flag;

// ---------------- helpers ----------------------------------------------------
__device__ __forceinline__ float fast_sig(float x)  { return 1.f / (1.f + __expf(-x)); }
__device__ __forceinline__ float fast_tanh(float x) { return fmaf(2.f, 1.f / (1.f + __expf(-2.f * x)), -1.f); }

__device__ __forceinline__ uint32_t pack_bf16x2(float lo, float hi)
{
    uint32_t r;
    asm("cvt.rn.bf16x2.f32 %0, %1, %2;" : "=r"(r) : "f"(hi), "f"(lo));
    return r;
}
__device__ __forceinline__ uint32_t smem_u32(const void* p)
{
    uint32_t a;
    asm("{ .reg .u64 t; cvta.to.shared.u64 t, %1; cvt.u32.u64 %0, t; }" : "=r"(a) : "l"(p));
    return a;
}
__device__ __forceinline__ void cpa16_u(uint32_t dst, const void* src)
{
    asm volatile("cp.async.cg.shared.global [%0], [%1], 16;\n" :: "r"(dst), "l"(src));
}
__device__ __forceinline__ void cpa_commit() { asm volatile("cp.async.commit_group;\n"); }
template<int N>
__device__ __forceinline__ void cpa_wait()   { asm volatile("cp.async.wait_group %0;\n" :: "n"(N)); }

__device__ __forceinline__ uint32_t f2tf32(float x)
{
    uint32_t u;
    asm("cvt.rna.tf32.f32 %0, %1;" : "=r"(u) : "f"(x));
    return u;
}
__device__ __forceinline__ void mma_tf32(float* d, const uint32_t* a, const uint32_t* b)
{
    asm volatile(
        "mma.sync.aligned.m16n8k8.row.col.f32.tf32.tf32.f32 "
        "{%0,%1,%2,%3}, {%4,%5,%6,%7}, {%8,%9}, {%0,%1,%2,%3};\n"
        : "+f"(d[0]), "+f"(d[1]), "+f"(d[2]), "+f"(d[3])
        : "r"(a[0]), "r"(a[1]), "r"(a[2]), "r"(a[3]), "r"(b[0]), "r"(b[1]));
}
__device__ __forceinline__ void mma_bf16(float* d, const uint32_t* a, const uint32_t* b)
{
    asm volatile(
        "mma.sync.aligned.m16n8k16.row.col.f32.bf16.bf16.f32 "
        "{%0,%1,%2,%3}, {%4,%5,%6,%7}, {%8,%9}, {%0,%1,%2,%3};\n"
        : "+f"(d[0]), "+f"(d[1]), "+f"(d[2]), "+f"(d[3])
        : "r"(a[0]), "r"(a[1]), "r"(a[2]), "r"(a[3]), "r"(b[0]), "r"(b[1]));
}

// ---------------- merged prep kernel -----------------------------------------
__global__ void prep_kernel(const float* __restrict__ c,
                            const float* __restrict__ bb,
                            const float* __restrict__ m,
                            const float* __restrict__ Wih)
{
    size_t idx = (size_t)blockIdx.x * blockDim.x + threadIdx.x;
    const size_t R1 = (size_t)Bn * CN;
    const size_t R2 = R1 + (size_t)Bn * Hh;
    if (idx < R1) {
        int b = (int)(idx / CN);
        int i = (int)(idx % CN);
        float v;
        if (i < Dd + NTd)            v = c [(size_t)b * (Dd + NTd) + i];
        else if (i < Dd + NTd + Dd)  v = bb[(size_t)b * Dd + (i - (Dd + NTd))];
        else                         v = m [(size_t)b * Dd + (i - (Dd + NTd + Dd))];
        g_const[idx] = v;
    } else if (idx < R2) {
        size_t i2 = idx - R1;
        g_Hf[i2] = 0.f;
        g_Hbf[i2] = __float2bfloat16(0.f);
    } else if (idx < R2 + Hh) {
        int j = (int)(idx - R2);
        g_wz4[j] = make_float4(Wih[j], Wih[512 + j], Wih[1024 + j], 0.f);
        if (j == 0) { g_bar_cnt = 0; g_bar_flag = 0; }
    }
}

// pack gic4 after tgemm produced g_gic
__global__ void gic4_pack_kernel(const float* __restrict__ bhh)
{
    size_t idx = (size_t)blockIdx.x * blockDim.x + threadIdx.x;
    if (idx >= (size_t)Bn * Hh) return;
    int b = (int)(idx >> 9);
    int j = (int)(idx & 511);
    const float* g = g_gic + (size_t)b * G3;
    g_gic4[idx] = make_float4(g[j] + bhh[j],
                              g[512 + j] + bhh[512 + j],
                              g[1024 + j],
                              bhh[1024 + j]);
}

// merged transpose+convert (z selects matrix)
__global__ void convT3_kernel(const float* __restrict__ Whh,
                              const float* __restrict__ W0,
                              const float* __restrict__ W1)
{
    __shared__ float tile[32][33];
    const float* in;
    __nv_bfloat16* out;
    int Krows = 512, Ncols;
    if (blockIdx.z == 0)      { in = Whh; out = g_WhhT; Ncols = G3; }
    else if (blockIdx.z == 1) { in = W0;  out = g_W0T;  Ncols = HIDd; }
    else                      { in = W1;  out = g_W1T;  Ncols = HIDd; }
    int n0 = blockIdx.x * 32;
    if (n0 >= Ncols) return;
    int k0 = blockIdx.y * 32;
    int tx = threadIdx.x, ty = threadIdx.y;
    for (int i = ty; i < 32; i += 8)
        tile[i][tx] = in[(size_t)(k0 + i) * Ncols + n0 + tx];
    __syncthreads();
    for (int i = ty; i < 32; i += 8)
        out[(size_t)(n0 + i) * Krows + k0 + tx] = __float2bfloat16(tile[tx][i]);
}

// ---------------- tf32 GEMM for K=536 precompute (fp32 in/out) ---------------
__global__ __launch_bounds__(256)
void tgemm_kernel(const float* __restrict__ A, const float* __restrict__ B,
                  const float* __restrict__ bias, float* __restrict__ C,
                  int M, int N, int K)
{
    __shared__ uint32_t As[128][12];
    __shared__ uint32_t Bs[8][136];

    const int tid  = threadIdx.x;
    const int wid  = tid >> 5;
    const int lane = tid & 31;
    const int gid  = lane >> 2;
    const int tig  = lane & 3;
    const int wm   = wid >> 2;
    const int wn   = wid & 3;
    const int row0 = blockIdx.y * 128;
    const int col0 = blockIdx.x * 128;

    float acc[4][4][4];
#pragma unroll
    for (int mt = 0; mt < 4; mt++)
#pragma unroll
        for (int nt = 0; nt < 4; nt++)
#pragma unroll
            for (int r = 0; r < 4; r++) acc[mt][nt][r] = 0.f;

    const int ar = tid >> 1;
    const int ak = (tid & 1) * 4;
    const int bk = tid >> 5;
    const int bn = (tid & 31) * 4;
    const int niter = K >> 3;

    const float* Ag = A + (size_t)(row0 + ar) * K + ak;
    const float* Bg = B + (size_t)bk * N + col0 + bn;

    float4 pa = *(const float4*)Ag;
    float4 pb = *(const float4*)Bg;

    for (int it = 0; it < niter; ++it) {
        As[ar][ak + 0] = f2tf32(pa.x); As[ar][ak + 1] = f2tf32(pa.y);
        As[ar][ak + 2] = f2tf32(pa.z); As[ar][ak + 3] = f2tf32(pa.w);
        Bs[bk][bn + 0] = f2tf32(pb.x); Bs[bk][bn + 1] = f2tf32(pb.y);
        Bs[bk][bn + 2] = f2tf32(pb.z); Bs[bk][bn + 3] = f2tf32(pb.w);
        __syncthreads();
        if (it + 1 < niter) {
            pa = *(const float4*)(Ag + (size_t)(it + 1) * 8);
            pb = *(const float4*)(Bg + (size_t)(it + 1) * 8 * N);
        }
        uint32_t af[4][4];
#pragma unroll
        for (int mt = 0; mt < 4; mt++) {
            int rb = wm * 64 + mt * 16 + gid;
            af[mt][0] = As[rb][tig];     af[mt][1] = As[rb + 8][tig];
            af[mt][2] = As[rb][tig + 4]; af[mt][3] = As[rb + 8][tig + 4];
        }
        uint32_t bf[4][2];
#pragma unroll
        for (int nt = 0; nt < 4; nt++) {
            int cb = wn * 32 + nt * 8 + gid;
            bf[nt][0] = Bs[tig][cb]; bf[nt][1] = Bs[tig + 4][cb];
        }
#pragma unroll
        for (int mt = 0; mt < 4; mt++)
#pragma unroll
            for (int nt = 0; nt < 4; nt++)
                mma_tf32(acc[mt][nt], af[mt], bf[nt]);
        __syncthreads();
    }
#pragma unroll
    for (int mt = 0; mt < 4; mt++) {
        int row_lo = row0 + wm * 64 + mt * 16 + gid;
        int row_hi = row_lo + 8;
#pragma unroll
        for (int nt = 0; nt < 4; nt++) {
            int col = col0 + wn * 32 + nt * 8 + tig * 2;
            float b0 = bias[col], b1 = bias[col + 1];
            *(float2*)(C + (size_t)row_lo * N + col) =
                make_float2(acc[mt][nt][0] + b0, acc[mt][nt][1] + b1);
            *(float2*)(C + (size_t)row_hi * N + col) =
                make_float2(acc[mt][nt][2] + b0, acc[mt][nt][3] + b1);
        }
    }
}

// ============ PERSISTENT weight-stationary GRU recurrence (1024 thr) =========
__global__ __launch_bounds__(1024, 1)
void gru_persist(const __nv_bfloat16* __restrict__ Hbf,
                 float* __restrict__ Hf,
                 const __nv_bfloat16* __restrict__ WhhT,
                 const float* __restrict__ z)
{
    extern __shared__ uint32_t sm[];
    const int tid  = threadIdx.x;
    const int wid  = tid >> 5;          // 0..31
    const int lane = tid & 31;
    const int gid  = lane >> 2;
    const int t4   = lane & 3;
    const int wm   = wid >> 2;          // 0..7 : 16-row slice
    const int wn   = wid & 3;           // 0..3 : 16-col slice
    const int jb   = blockIdx.x & 7;
    const int mb   = blockIdx.x >> 3;
    uint32_t su = smem_u32(sm);
    const uint32_t BW = 7680;           // B region start (u32 words)

    // resident Whh slice: [3 gates][64 n][512 k] bf16, row stride 260 u32
    for (int i = tid; i < 12288; i += 1024) {
        int n_row = i >> 6;
        int c16   = i & 63;
        int g = n_row >> 6, n = n_row & 63;
        cpa16_u(su + (BW + (uint32_t)n_row * 260u + (uint32_t)c16 * 4u) * 4u,
                WhhT + ((size_t)(g * 512 + jb * 64 + n)) * 512 + c16 * 8);
    }
    cpa_commit(); cpa_wait<0>(); __syncthreads();

    const int ar  = tid >> 3;           // A row 0..127
    const int ac4 = (tid & 7) << 1;     // u32 offset 0,2,...,14

#define LOADA(s, kc)                                                            \
    do {                                                                        \
        asm volatile("cp.async.ca.shared.global [%0], [%1], 8;\n"               \
            :: "r"(su + ((uint32_t)(s) * 2560u + (uint32_t)ar * 20u + ac4) * 4u), \
               "l"(Ag + (size_t)ar * 512 + (kc) * 32 + ac4 * 2));               \
        cpa_commit();                                                           \
    } while (0)

    for (int t = 0; t < Dd; t++) {
        const __nv_bfloat16* Abase = Hbf + (size_t)t * Bn * Hh + (size_t)mb * 256 * 512;
        const float* Hfp = Hf + (size_t)(t & 1) * Bn * Hh;
        float* Hfn       = Hf + (size_t)((t + 1) & 1) * Bn * Hh;
        __nv_bfloat16* Hbn = (__nv_bfloat16*)(Hbf + (size_t)(t + 1) * Bn * Hh);

        for (int mh = 0; mh < 2; mh++) {
            const __nv_bfloat16* Ag = Abase + (size_t)mh * 128 * 512;

            float acc[3][2][4];
#pragma unroll
            for (int g = 0; g < 3; g++)
#pragma unroll
                for (int nt = 0; nt < 2; nt++)
#pragma unroll
                    for (int r = 0; r < 4; r++) acc[g][nt][r] = 0.f;

            LOADA(0, 0);
            LOADA(1, 1);

            for (int kc = 0; kc < 16; kc++) {
                const int s = kc % 3;
                if (kc < 14) cpa_wait<1>(); else cpa_wait<0>();
                __syncthreads();
                if (kc + 2 < 16) LOADA((kc + 2) % 3, kc + 2);

#pragma unroll
                for (int kb = 0; kb < 16; kb += 8) {
                    uint32_t af[4];
                    {
                        uint32_t base = (uint32_t)s * 2560u + (uint32_t)(wm * 16 + gid) * 20u + kb + t4;
                        af[0] = sm[base];       af[1] = sm[base + 160];
                        af[2] = sm[base + 4];   af[3] = sm[base + 164];
                    }
#pragma unroll
                    for (int g = 0; g < 3; g++)
#pragma unroll
                        for (int nt = 0; nt < 2; nt++) {
                            int nrow = g * 64 + wn * 16 + nt * 8 + gid;
                            uint32_t bbase = BW + (uint32_t)nrow * 260u + (uint32_t)kc * 16u + kb + t4;
                            uint32_t bf[2];
                            bf[0] = sm[bbase];
                            bf[1] = sm[bbase + 4];
                            mma_bf16(acc[g][nt], af, bf);
                        }
                }
            }

            // ---- epilogue for this 128-row half ----------------------------
            {
                int b_lo = mb * 256 + mh * 128 + wm * 16 + gid;
                int b_hi = b_lo + 8;
                float zt_lo = (t == 0) ? -1.0f : z[(size_t)b_lo * Dd + (t - 1)];
                float zt_hi = (t == 0) ? -1.0f : z[(size_t)b_hi * Dd + (t - 1)];
                const float4* g4lo = g_gic4 + (size_t)b_lo * Hh;
                const float4* g4hi = g_gic4 + (size_t)b_hi * Hh;
                const float* hp_lo = Hfp + (size_t)b_lo * Hh;
                const float* hp_hi = Hfp + (size_t)b_hi * Hh;
                float* hf_lo = Hfn + (size_t)b_lo * Hh;
                float* hf_hi = Hfn + (size_t)b_hi * Hh;
                __nv_bfloat16* hb_lo = Hbn + (size_t)b_lo * Hh;
                __nv_bfloat16* hb_hi = Hbn + (size_t)b_hi * Hh;

#pragma unroll
                for (int nt = 0; nt < 2; nt++) {
                    int jc = jb * 64 + wn * 16 + nt * 8 + t4 * 2;
                    float hlo[2], hhi[2];
#pragma unroll
                    for (int cc = 0; cc < 2; cc++) {
                        int j = jc + cc;
                        float4 w4  = g_wz4[j];
                        float4 glo = g4lo[j];
                        float4 ghi = g4hi[j];
                        {
                            float r = fast_sig(fmaf(zt_lo, w4.x, glo.x) + acc[0][nt][cc]);
                            float u = fast_sig(fmaf(zt_lo, w4.y, glo.y) + acc[1][nt][cc]);
                            float n = fast_tanh(fmaf(r, acc[2][nt][cc] + glo.w,
                                                     fmaf(zt_lo, w4.z, glo.z)));
                            hlo[cc] = fmaf(u, hp_lo[j] - n, n);
                        }
                        {
                            float r = fast_sig(fmaf(zt_hi, w4.x, ghi.x) + acc[0][nt][2 + cc]);
                            float u = fast_sig(fmaf(zt_hi, w4.y, ghi.y) + acc[1][nt][2 + cc]);
                            float n = fast_tanh(fmaf(r, acc[2][nt][2 + cc] + ghi.w,
                                                     fmaf(zt_hi, w4.z, ghi.z)));
                            hhi[cc] = fmaf(u, hp_hi[j] - n, n);
                        }
                    }
                    *(float2*)(hf_lo + jc) = make_float2(hlo[0], hlo[1]);
                    *(float2*)(hf_hi + jc) = make_float2(hhi[0], hhi[1]);
                    *(uint32_t*)(hb_lo + jc) = pack_bf16x2(hlo[0], hlo[1]);
                    *(uint32_t*)(hb_hi + jc) = pack_bf16x2(hhi[0], hhi[1]);
                }
            }
            __syncthreads();
        }

        // ---- grid-wide barrier (publish h_{t+1}) ---------------------------
        __threadfence();
        __syncthreads();
        if (tid == 0) {
            unsigned v = atomicAdd(&g_bar_cnt, 1u);
            if (v == NCTA - 1) {
                g_bar_cnt = 0;
                __threadfence();
                atomicExch(&g_bar_flag, (unsigned)(t + 1));
            } else {
                while (atomicAdd(&g_bar_flag, 0u) < (unsigned)(t + 1)) { }
            }
        }
        __syncthreads();
    }
#undef LOADA
}

// ============ bf16 MLP GEMM (A bf16 [M][512], BT bf16 [512][512]) ============
// MODE 0: bf16 out = tanh(v + mlpc[row&4095][col]) ; MODE 1: bf16 out = tanh(v + bias[col])
template<int MODE>
__global__ __launch_bounds__(256)
void bgemm_mlp(const __nv_bfloat16* __restrict__ A, const __nv_bfloat16* __restrict__ BT,
               const float* __restrict__ bias, __nv_bfloat16* __restrict__ Cout, int M)
{
    const int K = 512, N = 512;
    __shared__ uint32_t As[2][128][20];
    __shared__ uint32_t Bs[2][128][20];

    const int tid  = threadIdx.x;
    const int wid  = tid >> 5;
    const int lane = tid & 31;
    const int g    = lane >> 2;
    const int t    = lane & 3;
    const int wm   = wid >> 2;
    const int wn   = wid & 3;

    const int row0 = blockIdx.y * 128;
    const int col0 = blockIdx.x * 128;

    float acc[4][4][4];
#pragma unroll
    for (int mt = 0; mt < 4; mt++)
#pragma unroll
        for (int nt = 0; nt < 4; nt++)
#pragma unroll
            for (int r = 0; r < 4; r++) acc[mt][nt][r] = 0.f;

    const int lr = tid >> 1;
    const int lc = (tid & 1) * 2;

#define LOAD_STAGE(s, kt)                                                        \
    do {                                                                         \
        cpa16_u(smem_u32(&As[s][lr][lc * 4]),                                    \
                A  + (size_t)(row0 + lr) * K + (kt) * 32 + lc * 8);              \
        cpa16_u(smem_u32(&As[s][lr][(lc + 1) * 4]),                              \
                A  + (size_t)(row0 + lr) * K + (kt) * 32 + (lc + 1) * 8);        \
        cpa16_u(smem_u32(&Bs[s][lr][lc * 4]),                                    \
                BT + (size_t)(col0 + lr) * K + (kt) * 32 + lc * 8);              \
        cpa16_u(smem_u32(&Bs[s][lr][(lc + 1) * 4]),                              \
                BT + (size_t)(col0 + lr) * K + (kt) * 32 + (lc + 1) * 8);        \
        cpa_commit();                                                            \
    } while (0)

    LOAD_STAGE(0, 0);
    LOAD_STAGE(1, 1);

    const int nk = K / 32;
    for (int kt = 0; kt < nk; ++kt) {
        const int s = kt & 1;
        cpa_wait<1>();
        __syncthreads();
#pragma unroll
        for (int kb = 0; kb < 16; kb += 8) {
            uint32_t af[4][4];
#pragma unroll
            for (int mt = 0; mt < 4; mt++) {
                int r = wm * 64 + mt * 16 + g;
                af[mt][0] = As[s][r][kb + t];     af[mt][1] = As[s][r + 8][kb + t];
                af[mt][2] = As[s][r][kb + t + 4]; af[mt][3] = As[s][r + 8][kb + t + 4];
            }
#pragma unroll
            for (int nt = 0; nt < 4; nt++) {
                int n = wn * 32 + nt * 8 + g;
                uint32_t bf[2];
                bf[0] = Bs[s][n][kb + t];
                bf[1] = Bs[s][n][kb + t + 4];
#pragma unroll
                for (int mt = 0; mt < 4; mt++)
                    mma_bf16(acc[mt][nt], af[mt], bf);
            }
        }
        __syncthreads();
        if (kt + 2 < nk) LOAD_STAGE(s, kt + 2);
    }
#undef LOAD_STAGE

#pragma unroll
    for (int mt = 0; mt < 4; mt++) {
        int row_lo = row0 + wm * 64 + mt * 16 + g;
        int row_hi = row_lo + 8;
#pragma unroll
        for (int nt = 0; nt < 4; nt++) {
            int col = col0 + wn * 32 + nt * 8 + t * 2;
            float v0 = acc[mt][nt][0], v1 = acc[mt][nt][1];
            float v2 = acc[mt][nt][2], v3 = acc[mt][nt][3];
            if (MODE == 0) {
                const float* blo = bias + (size_t)(row_lo & (Bn - 1)) * HIDd + col;
                const float* bhi = bias + (size_t)(row_hi & (Bn - 1)) * HIDd + col;
                v0 = fast_tanh(v0 + blo[0]); v1 = fast_tanh(v1 + blo[1]);
                v2 = fast_tanh(v2 + bhi[0]); v3 = fast_tanh(v3 + bhi[1]);
            } else {
                float b0 = bias[col], b1 = bias[col + 1];
                v0 = fast_tanh(v0 + b0); v1 = fast_tanh(v1 + b1);
                v2 = fast_tanh(v2 + b0); v3 = fast_tanh(v3 + b1);
            }
            *(uint32_t*)(Cout + (size_t)row_lo * N + col) = pack_bf16x2(v0, v1);
            *(uint32_t*)(Cout + (size_t)row_hi * N + col) = pack_bf16x2(v2, v3);
        }
    }
}

// ---------------- head GEMM (N=30) fused with mixture log-likelihood --------
__global__ __launch_bounds__(128)
void head_kernel(const float* __restrict__ W2, const float* __restrict__ b2,
                 const float* __restrict__ z)
{
    __shared__ float a2s[4][512];
    __shared__ float ps[4][32];
    int w = threadIdx.x >> 5, lane = threadIdx.x & 31;
    size_t r = (size_t)blockIdx.x * 4 + w;

    const __nv_bfloat162* src = (const __nv_bfloat162*)(g_A2bf + r * HIDd);
#pragma unroll
    for (int i = 0; i < 8; i++) {
        __nv_bfloat162 v = src[lane + 32 * i];
        a2s[w][(lane + 32 * i) * 2 + 0] = __bfloat162float(v.x);
        a2s[w][(lane + 32 * i) * 2 + 1] = __bfloat162float(v.y);
    }
    __syncwarp();

    if (lane < 30) {
        float acc = b2[lane];
#pragma unroll 8
        for (int k = 0; k < 512; k++)
            acc = fmaf(a2s[w][k], W2[k * 30 + lane], acc);
        ps[w][lane] = acc;
    }
    __syncwarp();

    if (lane == 0) {
        int t = (int)(r >> 12);
        int b = (int)(r & 4095);
        float zv = z[(size_t)b * Dd + t];
        float* p = ps[w];
        float m1 = -1e30f, m2 = -1e30f;
        float term[10];
#pragma unroll
        for (int k = 0; k < 10; k++) {
            float l = p[k], mu = p[10 + k], ls = p[20 + k];
            float d = (zv - mu) * expf(-ls);
            float tv = l - ls - 0.91893853320467274f - 0.5f * d * d;
            term[k] = tv;
            m1 = fmaxf(m1, tv);
            m2 = fmaxf(m2, l);
        }
        float s1 = 0.f, s2 = 0.f;
#pragma unroll
        for (int k = 0; k < 10; k++) {
            s1 += expf(term[k] - m1);
            s2 += expf(p[k] - m2);
        }
        g_ll[(size_t)b * Dd + t] = (m1 + logf(s1)) - (m2 + logf(s2));
    }
}

// ---------------- final: sort query desc (bitonic) + masked dot -------------
__global__ __launch_bounds__(128)
void final_kernel(const float* __restrict__ bb, const float* __restrict__ m,
                  float* __restrict__ out)
{
    __shared__ float s[128];
    __shared__ float red[128];
    int b = blockIdx.x, t = threadIdx.x;

    float q = -1.0f;
    if (t < Dd) {
        float bv = bb[(size_t)b * Dd + t];
        q = m[(size_t)b * Dd + t] * (1.0f - bv);
    }
    s[t] = q;
    __syncthreads();

    for (int k = 2; k <= 128; k <<= 1) {
        for (int j = k >> 1; j > 0; j >>= 1) {
            int ixj = t ^ j;
            if (ixj > t) {
                float a = s[t], c = s[ixj];
                bool up = ((t & k) == 0);
                if (up ? (a > c) : (a < c)) { s[t] = c; s[ixj] = a; }
            }
            __syncthreads();
        }
    }

    float prod = 0.f;
    if (t < Dd) prod = g_ll[(size_t)b * Dd + t] * s[127 - t];
    red[t] = prod;
    __syncthreads();
    for (int st = 64; st > 0; st >>= 1) {
        if (t < st) red[t] += red[t + st];
        __syncthreads();
    }
    if (t == 0) out[b] = red[0];
}

// ---------------- launch ----------------------------------------------------
extern "C" void kernel_launch(void* const* d_in, const int* in_sizes, int n_in,
                              void* d_out, int out_size)
{
    const float* z   = (const float*)d_in[0];
    const float* c   = (const float*)d_in[1];
    const float* bb  = (const float*)d_in[2];
    const float* m   = (const float*)d_in[3];
    const float* Wih = (const float*)d_in[4];
    const float* Whh = (const float*)d_in[5];
    const float* bih = (const float*)d_in[6];
    const float* bhh = (const float*)d_in[7];
    const float* W0  = (const float*)d_in[8];
    const float* b0  = (const float*)d_in[9];
    const float* W1  = (const float*)d_in[10];
    const float* b1  = (const float*)d_in[11];
    const float* W2  = (const float*)d_in[12];
    const float* b2  = (const float*)d_in[13];
    float* out = (float*)d_out;

    float *pConst, *pGic, *pMlpc, *pHf;
    __nv_bfloat16 *pHbf, *pWhhT, *pW0T, *pW1T, *pA1bf, *pA2bf;
    cudaGetSymbolAddress((void**)&pConst, g_const);
    cudaGetSymbolAddress((void**)&pGic,   g_gic);
    cudaGetSymbolAddress((void**)&pMlpc,  g_mlpc);
    cudaGetSymbolAddress((void**)&pHf,    g_Hf);
    cudaGetSymbolAddress((void**)&pHbf,   g_Hbf);
    cudaGetSymbolAddress((void**)&pWhhT,  g_WhhT);
    cudaGetSymbolAddress((void**)&pW0T,   g_W0T);
    cudaGetSymbolAddress((void**)&pW1T,   g_W1T);
    cudaGetSymbolAddress((void**)&pA1bf,  g_A1bf);
    cudaGetSymbolAddress((void**)&pA2bf,  g_A2bf);

    static int attr_done = 0;
    if (!attr_done) {
        cudaFuncSetAttribute(gru_persist, cudaFuncAttributeMaxDynamicSharedMemorySize, 230400);
        attr_done = 1;
    }

    // 0: merged prep
    {
        size_t tot = (size_t)Bn * CN + (size_t)Bn * Hh + Hh;
        prep_kernel<<<(unsigned)((tot + 255) / 256), 256>>>(c, bb, m, Wih);
    }
    // 1: merged transpose+convert of Whh / W0[:H] / W1
    convT3_kernel<<<dim3(48, 16, 3), dim3(32, 8)>>>(Whh, W0, W1);
    // 2: gi_const = const @ Wih[1:] + bih
    tgemm_kernel<<<dim3(G3 / 128, Bn / 128), 256>>>(pConst, Wih + G3, bih, pGic,
                                                    Bn, G3, CN);
    // 3: mlp_const = const @ W0[H:] + b0
    tgemm_kernel<<<dim3(HIDd / 128, Bn / 128), 256>>>(pConst, W0 + (size_t)Hh * HIDd,
                                                      b0, pMlpc, Bn, HIDd, CN);
    // 4: pack gic4
    gic4_pack_kernel<<<(Bn * Hh) / 256, 256>>>(bhh);
    // 5: recurrence — ONE persistent launch, 1024 threads
    gru_persist<<<NCTA, 1024, 230400>>>(pHbf, pHf, pWhhT, z);
    // 6-7: batched MLP (both outputs bf16 now)
    bgemm_mlp<0><<<dim3(HIDd / 128, TOTR / 128), 256>>>(pHbf + (size_t)Bn * Hh, pW0T,
                                                        pMlpc, pA1bf, TOTR);
    bgemm_mlp<1><<<dim3(HIDd / 128, TOTR / 128), 256>>>(pA1bf, pW1T, b1, pA2bf, TOTR);
    // 8-9: head + final
    head_kernel<<<TOTR / 4, 128>>>(W2, b2, z);
    final_kernel<<<Bn, 128>>>(bb, m, out);
}